// round 2
// baseline (speedup 1.0000x reference)
#include <cuda_runtime.h>
#include <cstdint>
#include <cstdio>

#define B_    16
#define N_    1024
#define C_    768
#define H_    12
#define HD_   64
#define M_TOT (B_ * N_)        // 16384
#define QKV_N (3 * C_)         // 2304

// Scratch (allowed: __device__ globals, no runtime allocation)
__device__ float g_qkv[(size_t)M_TOT * QKV_N];   // [16384, 2304]
__device__ float g_attn[(size_t)M_TOT * C_];     // [16384, 768]

// ---------------------------------------------------------------------------
// SGEMM with bias: C[M,N] = A[M,K] @ B[K,N] + bias[N]
// BM=BN=128, BK=8, 256 threads, 8x8 per thread (2x2 quadrants of 4x4).
// Requires M%128==0, N%128==0, K%8==0 (true for all uses here).
// ---------------------------------------------------------------------------
__global__ __launch_bounds__(256) void sgemm_bias_kernel(
    const float* __restrict__ A, const float* __restrict__ B,
    const float* __restrict__ bias, float* __restrict__ C,
    int M, int N, int K)
{
    __shared__ float As[8][128];   // transposed A tile
    __shared__ float Bs[8][128];

    const int tid = threadIdx.x;
    const int bm  = blockIdx.y * 128;
    const int bn  = blockIdx.x * 128;
    const int tr  = tid >> 4;          // 0..15
    const int tc  = tid & 15;          // 0..15

    const int arow = tid >> 1;         // 0..127
    const int acol = (tid & 1) * 4;    // 0 or 4
    const int brow = tid >> 5;         // 0..7
    const int bcol = (tid & 31) * 4;   // 0..124

    float acc[8][8];
#pragma unroll
    for (int i = 0; i < 8; i++)
#pragma unroll
        for (int j = 0; j < 8; j++) acc[i][j] = 0.f;

    for (int kt = 0; kt < K; kt += 8) {
        const float4 av = *(const float4*)(A + (size_t)(bm + arow) * K + kt + acol);
        const float4 bv = *(const float4*)(B + (size_t)(kt + brow) * N + bn + bcol);
        __syncthreads();   // previous compute done before overwriting tiles
        As[acol + 0][arow] = av.x;
        As[acol + 1][arow] = av.y;
        As[acol + 2][arow] = av.z;
        As[acol + 3][arow] = av.w;
        *(float4*)&Bs[brow][bcol] = bv;
        __syncthreads();
#pragma unroll
        for (int k = 0; k < 8; k++) {
            float a[8], b[8];
            *(float4*)&a[0] = *(const float4*)&As[k][tr * 4];
            *(float4*)&a[4] = *(const float4*)&As[k][64 + tr * 4];
            *(float4*)&b[0] = *(const float4*)&Bs[k][tc * 4];
            *(float4*)&b[4] = *(const float4*)&Bs[k][64 + tc * 4];
#pragma unroll
            for (int i = 0; i < 8; i++)
#pragma unroll
                for (int j = 0; j < 8; j++)
                    acc[i][j] += a[i] * b[j];
        }
    }

#pragma unroll
    for (int ih = 0; ih < 2; ih++) {
#pragma unroll
        for (int ii = 0; ii < 4; ii++) {
            const int row = bm + ih * 64 + tr * 4 + ii;
#pragma unroll
            for (int jh = 0; jh < 2; jh++) {
                const int col = bn + jh * 64 + tc * 4;
                float4 o;
                o.x = acc[ih * 4 + ii][jh * 4 + 0] + bias[col + 0];
                o.y = acc[ih * 4 + ii][jh * 4 + 1] + bias[col + 1];
                o.z = acc[ih * 4 + ii][jh * 4 + 2] + bias[col + 2];
                o.w = acc[ih * 4 + ii][jh * 4 + 3] + bias[col + 3];
                *(float4*)(C + (size_t)row * N + col) = o;
            }
        }
    }
}

// ---------------------------------------------------------------------------
// RoPE (in place on q and k portions of g_qkv).
// out[j]    = t[j]  * cos(pos*inv[j/2])   - t[j+16] * sin(pos*inv[j/2])
// out[j+16] = t[j+16]*cos(pos*inv[8+j/2]) + t[j]    * sin(pos*inv[8+j/2])
// inv[k] = 10000^(-k/16). One thread per (row, head, {q,k}, {h,w}, pair j).
// ---------------------------------------------------------------------------
__global__ void rope_kernel(float* __restrict__ qkv,
                            const int* __restrict__ ph,
                            const int* __restrict__ pw)
{
    const int idx = blockIdx.x * blockDim.x + threadIdx.x;
    const int j    = idx & 15;
    const int half = (idx >> 4) & 1;
    const int s    = (idx >> 5) & 1;
    const int head = (idx >> 6) % 12;
    const int row  = idx / 768;
    if (row >= M_TOT) return;

    const float pos = (float)(half ? pw[row] : ph[row]);
    const size_t base = (size_t)row * QKV_N + s * 768 + head * 64 + half * 32;

    const float t0 = qkv[base + j];
    const float t1 = qkv[base + j + 16];

    const float L = 9.210340371976184f / 16.0f;   // ln(10000)/16
    const int k0 = j >> 1;
    const float f0 = pos * expf(-L * (float)k0);
    const float f1 = pos * expf(-L * (float)(k0 + 8));
    float c0, s0, c1, s1;
    sincosf(f0, &s0, &c0);
    sincosf(f1, &s1, &c1);

    qkv[base + j]      = t0 * c0 - t1 * s0;
    qkv[base + j + 16] = t1 * c1 + t0 * s1;
}

// ---------------------------------------------------------------------------
// Flash attention: one CTA per (q-tile of 64 rows, head, batch).
// 256 threads as 16x16; thread owns rows ty*4..+3, cols tx+16*{0..3}.
// 16 key iterations of 64; online softmax; output in [B,N,C] layout.
// ---------------------------------------------------------------------------
#define ST 68   // smem row stride (floats)

__global__ __launch_bounds__(256) void attn_kernel(const float* __restrict__ qkv,
                                                   float* __restrict__ out)
{
    extern __shared__ float sm[];
    float* Qs = sm;
    float* Ks = sm + 64 * ST;
    float* Vs = sm + 2 * 64 * ST;
    float* Ps = sm + 3 * 64 * ST;

    const int tid = threadIdx.x;
    const int qb  = blockIdx.x;   // 0..15
    const int h   = blockIdx.y;   // 0..11
    const int b   = blockIdx.z;   // 0..15
    const int ty  = tid >> 4;
    const int tx  = tid & 15;

    const size_t qrow0 = (size_t)b * N_ + (size_t)qb * 64;

    // Load Q tile, pre-scaled by 1/sqrt(64)
    for (int idx = tid; idx < 1024; idx += 256) {
        const int r  = idx >> 4;
        const int c4 = (idx & 15) * 4;
        float4 v = *(const float4*)(qkv + (qrow0 + r) * QKV_N + h * 64 + c4);
        v.x *= 0.125f; v.y *= 0.125f; v.z *= 0.125f; v.w *= 0.125f;
        *(float4*)&Qs[r * ST + c4] = v;
    }

    float acc[4][4];
    float mrun[4], lrun[4];
#pragma unroll
    for (int i = 0; i < 4; i++) {
        mrun[i] = -1e30f;
        lrun[i] = 0.f;
#pragma unroll
        for (int j = 0; j < 4; j++) acc[i][j] = 0.f;
    }

    for (int kb = 0; kb < 16; kb++) {
        __syncthreads();   // prev P@V done (and Q loaded, first iter)
        const size_t krow0 = (size_t)b * N_ + (size_t)kb * 64;
        for (int idx = tid; idx < 1024; idx += 256) {
            const int r  = idx >> 4;
            const int c4 = (idx & 15) * 4;
            *(float4*)&Ks[r * ST + c4] =
                *(const float4*)(qkv + (krow0 + r) * QKV_N + 768 + h * 64 + c4);
            *(float4*)&Vs[r * ST + c4] =
                *(const float4*)(qkv + (krow0 + r) * QKV_N + 1536 + h * 64 + c4);
        }
        __syncthreads();

        // S = Qs @ Ks^T  (64x64, 4x4 per thread)
        float sv[4][4];
#pragma unroll
        for (int i = 0; i < 4; i++)
#pragma unroll
            for (int j = 0; j < 4; j++) sv[i][j] = 0.f;

#pragma unroll 4
        for (int d4 = 0; d4 < 64; d4 += 4) {
            float4 aa[4], bb[4];
#pragma unroll
            for (int i = 0; i < 4; i++)
                aa[i] = *(const float4*)&Qs[(ty * 4 + i) * ST + d4];
#pragma unroll
            for (int j = 0; j < 4; j++)
                bb[j] = *(const float4*)&Ks[(tx + 16 * j) * ST + d4];
#pragma unroll
            for (int i = 0; i < 4; i++)
#pragma unroll
                for (int j = 0; j < 4; j++)
                    sv[i][j] += aa[i].x * bb[j].x + aa[i].y * bb[j].y +
                                aa[i].z * bb[j].z + aa[i].w * bb[j].w;
        }

        // Online softmax update + write P tile
#pragma unroll
        for (int i = 0; i < 4; i++) {
            float mx = sv[i][0];
            mx = fmaxf(mx, sv[i][1]);
            mx = fmaxf(mx, sv[i][2]);
            mx = fmaxf(mx, sv[i][3]);
#pragma unroll
            for (int o = 8; o >= 1; o >>= 1)
                mx = fmaxf(mx, __shfl_xor_sync(0xffffffffu, mx, o));
            const float mnew = fmaxf(mrun[i], mx);
            const float corr = __expf(mrun[i] - mnew);
            float rs = 0.f;
#pragma unroll
            for (int j = 0; j < 4; j++) {
                const float p = __expf(sv[i][j] - mnew);
                Ps[(ty * 4 + i) * ST + tx + 16 * j] = p;
                rs += p;
            }
#pragma unroll
            for (int o = 8; o >= 1; o >>= 1)
                rs += __shfl_xor_sync(0xffffffffu, rs, o);
            lrun[i] = lrun[i] * corr + rs;
#pragma unroll
            for (int j = 0; j < 4; j++) acc[i][j] *= corr;
            mrun[i] = mnew;
        }
        __syncthreads();

        // acc += P (64x64) @ V (64x64)
#pragma unroll 4
        for (int kk4 = 0; kk4 < 64; kk4 += 4) {
            float4 pp[4];
#pragma unroll
            for (int i = 0; i < 4; i++)
                pp[i] = *(const float4*)&Ps[(ty * 4 + i) * ST + kk4];
#pragma unroll
            for (int t = 0; t < 4; t++) {
                float vv[4];
#pragma unroll
                for (int j = 0; j < 4; j++)
                    vv[j] = Vs[(kk4 + t) * ST + tx + 16 * j];
#pragma unroll
                for (int i = 0; i < 4; i++) {
                    const float pt = ((const float*)&pp[i])[t];
#pragma unroll
                    for (int j = 0; j < 4; j++)
                        acc[i][j] += pt * vv[j];
                }
            }
        }
    }

    // Write output: [B, N, C] with col = h*64 + c
#pragma unroll
    for (int i = 0; i < 4; i++) {
        const float il = 1.f / lrun[i];
        const size_t row = qrow0 + ty * 4 + i;
#pragma unroll
        for (int j = 0; j < 4; j++)
            out[row * C_ + h * 64 + tx + 16 * j] = acc[i][j] * il;
    }
}

// ---------------------------------------------------------------------------
extern "C" void kernel_launch(void* const* d_in, const int* in_sizes, int n_in,
                              void* d_out, int out_size)
{
    const float* x     = (const float*)d_in[0];
    const float* Wqkv  = (const float*)d_in[1];
    const float* bqkv  = (const float*)d_in[2];
    const float* Wproj = (const float*)d_in[3];
    const float* bproj = (const float*)d_in[4];
    const int*   ph    = (const int*)d_in[5];
    const int*   pw    = (const int*)d_in[6];
    float*       out   = (float*)d_out;

    float *qkv = nullptr, *attn = nullptr;
    cudaGetSymbolAddress((void**)&qkv, g_qkv);
    cudaGetSymbolAddress((void**)&attn, g_attn);

    // 1) QKV projection: [16384,768] @ [768,2304] + b
    sgemm_bias_kernel<<<dim3(QKV_N / 128, M_TOT / 128), 256>>>(
        x, Wqkv, bqkv, qkv, M_TOT, QKV_N, C_);

    // 2) RoPE in place on q,k
    {
        const int total = M_TOT * 12 * 2 * 2 * 16;   // 12,582,912
        rope_kernel<<<(total + 255) / 256, 256>>>(qkv, ph, pw);
    }

    // 3) Attention
    {
        const size_t smem = (size_t)4 * 64 * ST * sizeof(float);   // 69632 B
        cudaFuncSetAttribute(attn_kernel,
                             cudaFuncAttributeMaxDynamicSharedMemorySize,
                             (int)smem);
        attn_kernel<<<dim3(16, H_, B_), 256, smem>>>(qkv, attn);
    }

    // 4) Output projection: [16384,768] @ [768,768] + b
    sgemm_bias_kernel<<<dim3(C_ / 128, M_TOT / 128), 256>>>(
        attn, Wproj, bproj, out, M_TOT, C_, C_);
}

// round 4
// speedup vs baseline: 1.2020x; 1.2020x over previous
#include <cuda_runtime.h>
#include <cuda_bf16.h>
#include <cstdint>

#define B_    16
#define N_    1024
#define C_    768
#define H_    12
#define M_TOT (B_ * N_)        // 16384
#define QKV_N (3 * C_)         // 2304
#define K_DIM 768

// ---------------------------------------------------------------------------
// Scratch (__device__ globals only)
// ---------------------------------------------------------------------------
__device__ __align__(16) float g_qkv[(size_t)M_TOT * QKV_N];
__device__ __align__(16) float g_attn[(size_t)M_TOT * C_];
__device__ __align__(16) __nv_bfloat16 g_wqkv_hi[(size_t)QKV_N * K_DIM];  // [N,K]
__device__ __align__(16) __nv_bfloat16 g_wqkv_lo[(size_t)QKV_N * K_DIM];
__device__ __align__(16) __nv_bfloat16 g_wproj_hi[(size_t)C_ * K_DIM];
__device__ __align__(16) __nv_bfloat16 g_wproj_lo[(size_t)C_ * K_DIM];

// ---------------------------------------------------------------------------
// mma.sync / ldmatrix helpers (compute_80-level ISA: safe at .target sm_103)
// ---------------------------------------------------------------------------
__device__ __forceinline__ uint32_t smem_u32(const void* p) {
    uint32_t a;
    asm("{ .reg .u64 t; cvta.to.shared.u64 t, %1; cvt.u32.u64 %0, t; }"
        : "=r"(a) : "l"(p));
    return a;
}
__device__ __forceinline__ void ldm4(uint32_t* r, uint32_t addr) {
    asm volatile("ldmatrix.sync.aligned.m8n8.x4.shared.b16 {%0,%1,%2,%3}, [%4];"
                 : "=r"(r[0]), "=r"(r[1]), "=r"(r[2]), "=r"(r[3]) : "r"(addr));
}
__device__ __forceinline__ void mma_bf16(float* c, const uint32_t* a, const uint32_t* b) {
    asm volatile("mma.sync.aligned.m16n8k16.row.col.f32.bf16.bf16.f32 "
                 "{%0,%1,%2,%3}, {%4,%5,%6,%7}, {%8,%9}, {%0,%1,%2,%3};"
                 : "+f"(c[0]), "+f"(c[1]), "+f"(c[2]), "+f"(c[3])
                 : "r"(a[0]), "r"(a[1]), "r"(a[2]), "r"(a[3]),
                   "r"(b[0]), "r"(b[1]));
}
__device__ __forceinline__ uint32_t pack2_bf16(float a, float b) {
    return ((uint32_t)__bfloat16_as_ushort(__float2bfloat16(b)) << 16) |
           (uint32_t)__bfloat16_as_ushort(__float2bfloat16(a));
}

// ---------------------------------------------------------------------------
// Weight prep: W [K,N] fp32 -> hi/lo [N,K] bf16, tiled transpose (coalesced)
// ---------------------------------------------------------------------------
__global__ void split_w_kernel(const float* __restrict__ W,
                               __nv_bfloat16* __restrict__ hi,
                               __nv_bfloat16* __restrict__ lo,
                               int K, int N) {
    __shared__ float t[32][33];
    const int tx = threadIdx.x, ty = threadIdx.y;
    const int n0 = blockIdx.x * 32, k0 = blockIdx.y * 32;
#pragma unroll
    for (int j = 0; j < 4; j++) {
        const int k = k0 + ty + j * 8;
        t[ty + j * 8][tx] = W[(size_t)k * N + n0 + tx];
    }
    __syncthreads();
#pragma unroll
    for (int j = 0; j < 4; j++) {
        const int n = n0 + ty + j * 8;
        const int k = k0 + tx;
        const float w = t[tx][ty + j * 8];
        const __nv_bfloat16 h = __float2bfloat16(w);
        hi[(size_t)n * K + k] = h;
        lo[(size_t)n * K + k] = __float2bfloat16(w - __bfloat162float(h));
    }
}

// ---------------------------------------------------------------------------
// bf16x3 HMMA GEMM: C[M,N] = A[M,K] @ Bt[N,K]^T + bias
// BM=BN=128, BK=32, 256 thr (8 warps, 2x4), warp tile 64x32.
// ---------------------------------------------------------------------------
#define SAB 40   // smem row stride in halfs (80 B -> conflict-free ldmatrix)

__global__ __launch_bounds__(256) void gemm_mma_kernel(
    const float* __restrict__ A, const __nv_bfloat16* __restrict__ Bhg,
    const __nv_bfloat16* __restrict__ Blg, const float* __restrict__ bias,
    float* __restrict__ Cout, int M, int N, int K)
{
    __shared__ __align__(16) __nv_bfloat16 sm_[4 * 128 * SAB];
    __nv_bfloat16* sAh = sm_;
    __nv_bfloat16* sAl = sm_ + 128 * SAB;
    __nv_bfloat16* sBh = sm_ + 2 * 128 * SAB;
    __nv_bfloat16* sBl = sm_ + 3 * 128 * SAB;
    const uint32_t uAh = smem_u32(sAh), uAl = smem_u32(sAl);
    const uint32_t uBh = smem_u32(sBh), uBl = smem_u32(sBl);

    const int tid = threadIdx.x;
    const int wid = tid >> 5;
    const int l   = tid & 31;
    const int wm  = wid >> 2;          // 0..1
    const int wn  = wid & 3;           // 0..3
    const int bm  = blockIdx.y * 128;
    const int bn  = blockIdx.x * 128;

    // ldmatrix lane-address components (in halfs)
    const int a_row = l & 15;
    const int a_col = (l >> 4) * 8;
    const int b_row = (l & 7) + ((l >> 4) & 1) * 8;
    const int b_col = ((l >> 3) & 1) * 8;

    float acc[4][4][4];
#pragma unroll
    for (int i = 0; i < 4; i++)
#pragma unroll
        for (int j = 0; j < 4; j++)
#pragma unroll
            for (int t = 0; t < 4; t++) acc[i][j][t] = 0.f;

    for (int kt = 0; kt < K; kt += 32) {
        // ---- A tile: 128x32 fp32 -> hi/lo bf16
#pragma unroll
        for (int i = 0; i < 4; i++) {
            const int li = i * 256 + tid;
            const int r  = li >> 3;
            const int c4 = (li & 7) * 4;
            const float4 v = *(const float4*)(A + (size_t)(bm + r) * K + kt + c4);
            const __nv_bfloat16 h0 = __float2bfloat16(v.x);
            const __nv_bfloat16 h1 = __float2bfloat16(v.y);
            const __nv_bfloat16 h2 = __float2bfloat16(v.z);
            const __nv_bfloat16 h3 = __float2bfloat16(v.w);
            uint2 hp, lp;
            hp.x = ((uint32_t)__bfloat16_as_ushort(h1) << 16) | __bfloat16_as_ushort(h0);
            hp.y = ((uint32_t)__bfloat16_as_ushort(h3) << 16) | __bfloat16_as_ushort(h2);
            lp.x = pack2_bf16(v.x - __bfloat162float(h0), v.y - __bfloat162float(h1));
            lp.y = pack2_bf16(v.z - __bfloat162float(h2), v.w - __bfloat162float(h3));
            *(uint2*)&sAh[r * SAB + c4] = hp;
            *(uint2*)&sAl[r * SAB + c4] = lp;
        }
        // ---- B tiles: 128x32 bf16 (hi, lo)
#pragma unroll
        for (int i = 0; i < 2; i++) {
            const int li = i * 256 + tid;
            const int r  = li >> 2;
            const int c8 = (li & 3) * 8;
            const size_t gi = (size_t)(bn + r) * K + kt + c8;
            *(uint4*)&sBh[r * SAB + c8] = *(const uint4*)(Bhg + gi);
            *(uint4*)&sBl[r * SAB + c8] = *(const uint4*)(Blg + gi);
        }
        __syncthreads();

#pragma unroll
        for (int kh = 0; kh < 2; kh++) {
            const int kc = kh * 16;
            uint32_t af[4][4], bf[4][2];

            // Ah fragments
#pragma unroll
            for (int ti = 0; ti < 4; ti++)
                ldm4(af[ti], uAh + 2 * ((wm * 64 + ti * 16 + a_row) * SAB + kc + a_col));
            // Bh fragments (two x4 loads cover 4 n-tiles)
#pragma unroll
            for (int bp = 0; bp < 2; bp++) {
                uint32_t r4[4];
                ldm4(r4, uBh + 2 * ((wn * 32 + bp * 16 + b_row) * SAB + kc + b_col));
                bf[bp * 2 + 0][0] = r4[0]; bf[bp * 2 + 0][1] = r4[1];
                bf[bp * 2 + 1][0] = r4[2]; bf[bp * 2 + 1][1] = r4[3];
            }
#pragma unroll
            for (int ti = 0; ti < 4; ti++)
#pragma unroll
                for (int nj = 0; nj < 4; nj++)
                    mma_bf16(acc[ti][nj], af[ti], bf[nj]);

            // Bl fragments (overwrite bf), Ah still live
#pragma unroll
            for (int bp = 0; bp < 2; bp++) {
                uint32_t r4[4];
                ldm4(r4, uBl + 2 * ((wn * 32 + bp * 16 + b_row) * SAB + kc + b_col));
                bf[bp * 2 + 0][0] = r4[0]; bf[bp * 2 + 0][1] = r4[1];
                bf[bp * 2 + 1][0] = r4[2]; bf[bp * 2 + 1][1] = r4[3];
            }
#pragma unroll
            for (int ti = 0; ti < 4; ti++)
#pragma unroll
                for (int nj = 0; nj < 4; nj++)
                    mma_bf16(acc[ti][nj], af[ti], bf[nj]);

            // Al fragments (overwrite af), need Bh again
#pragma unroll
            for (int bp = 0; bp < 2; bp++) {
                uint32_t r4[4];
                ldm4(r4, uBh + 2 * ((wn * 32 + bp * 16 + b_row) * SAB + kc + b_col));
                bf[bp * 2 + 0][0] = r4[0]; bf[bp * 2 + 0][1] = r4[1];
                bf[bp * 2 + 1][0] = r4[2]; bf[bp * 2 + 1][1] = r4[3];
            }
#pragma unroll
            for (int ti = 0; ti < 4; ti++)
                ldm4(af[ti], uAl + 2 * ((wm * 64 + ti * 16 + a_row) * SAB + kc + a_col));
#pragma unroll
            for (int ti = 0; ti < 4; ti++)
#pragma unroll
                for (int nj = 0; nj < 4; nj++)
                    mma_bf16(acc[ti][nj], af[ti], bf[nj]);
        }
        __syncthreads();
    }

    // Epilogue: direct stores with bias (float2 per c-pair)
    const int row_in = l >> 2;
    const int col_in = (l & 3) * 2;
#pragma unroll
    for (int ti = 0; ti < 4; ti++) {
#pragma unroll
        for (int nj = 0; nj < 4; nj++) {
            const int col = bn + wn * 32 + nj * 8 + col_in;
            const float b0 = bias[col], b1 = bias[col + 1];
            const int r0 = bm + wm * 64 + ti * 16 + row_in;
            float2 v0 = { acc[ti][nj][0] + b0, acc[ti][nj][1] + b1 };
            float2 v1 = { acc[ti][nj][2] + b0, acc[ti][nj][3] + b1 };
            *(float2*)(Cout + (size_t)r0 * N + col) = v0;
            *(float2*)(Cout + (size_t)(r0 + 8) * N + col) = v1;
        }
    }
}

// ---------------------------------------------------------------------------
// RoPE (unchanged)
// ---------------------------------------------------------------------------
__global__ void rope_kernel(float* __restrict__ qkv,
                            const int* __restrict__ ph,
                            const int* __restrict__ pw)
{
    const int idx = blockIdx.x * blockDim.x + threadIdx.x;
    const int j    = idx & 15;
    const int half = (idx >> 4) & 1;
    const int s    = (idx >> 5) & 1;
    const int head = (idx >> 6) % 12;
    const int row  = idx / 768;
    if (row >= M_TOT) return;

    const float pos = (float)(half ? pw[row] : ph[row]);
    const size_t base = (size_t)row * QKV_N + s * 768 + head * 64 + half * 32;

    const float t0 = qkv[base + j];
    const float t1 = qkv[base + j + 16];

    const float L = 9.210340371976184f / 16.0f;
    const int k0 = j >> 1;
    const float f0 = pos * expf(-L * (float)k0);
    const float f1 = pos * expf(-L * (float)(k0 + 8));
    float c0, s0, c1, s1;
    sincosf(f0, &s0, &c0);
    sincosf(f1, &s1, &c1);

    qkv[base + j]      = t0 * c0 - t1 * s0;
    qkv[base + j + 16] = t1 * c1 + t0 * s1;
}

// ---------------------------------------------------------------------------
// Flash attention (unchanged, fp32)
// ---------------------------------------------------------------------------
#define ST 68

__global__ __launch_bounds__(256) void attn_kernel(const float* __restrict__ qkv,
                                                   float* __restrict__ out)
{
    extern __shared__ float sm[];
    float* Qs = sm;
    float* Ks = sm + 64 * ST;
    float* Vs = sm + 2 * 64 * ST;
    float* Ps = sm + 3 * 64 * ST;

    const int tid = threadIdx.x;
    const int qb  = blockIdx.x;
    const int h   = blockIdx.y;
    const int b   = blockIdx.z;
    const int ty  = tid >> 4;
    const int tx  = tid & 15;

    const size_t qrow0 = (size_t)b * N_ + (size_t)qb * 64;

    for (int idx = tid; idx < 1024; idx += 256) {
        const int r  = idx >> 4;
        const int c4 = (idx & 15) * 4;
        float4 v = *(const float4*)(qkv + (qrow0 + r) * QKV_N + h * 64 + c4);
        v.x *= 0.125f; v.y *= 0.125f; v.z *= 0.125f; v.w *= 0.125f;
        *(float4*)&Qs[r * ST + c4] = v;
    }

    float acc[4][4];
    float mrun[4], lrun[4];
#pragma unroll
    for (int i = 0; i < 4; i++) {
        mrun[i] = -1e30f;
        lrun[i] = 0.f;
#pragma unroll
        for (int j = 0; j < 4; j++) acc[i][j] = 0.f;
    }

    for (int kb = 0; kb < 16; kb++) {
        __syncthreads();
        const size_t krow0 = (size_t)b * N_ + (size_t)kb * 64;
        for (int idx = tid; idx < 1024; idx += 256) {
            const int r  = idx >> 4;
            const int c4 = (idx & 15) * 4;
            *(float4*)&Ks[r * ST + c4] =
                *(const float4*)(qkv + (krow0 + r) * QKV_N + 768 + h * 64 + c4);
            *(float4*)&Vs[r * ST + c4] =
                *(const float4*)(qkv + (krow0 + r) * QKV_N + 1536 + h * 64 + c4);
        }
        __syncthreads();

        float sv[4][4];
#pragma unroll
        for (int i = 0; i < 4; i++)
#pragma unroll
            for (int j = 0; j < 4; j++) sv[i][j] = 0.f;

#pragma unroll 4
        for (int d4 = 0; d4 < 64; d4 += 4) {
            float4 aa[4], bb[4];
#pragma unroll
            for (int i = 0; i < 4; i++)
                aa[i] = *(const float4*)&Qs[(ty * 4 + i) * ST + d4];
#pragma unroll
            for (int j = 0; j < 4; j++)
                bb[j] = *(const float4*)&Ks[(tx + 16 * j) * ST + d4];
#pragma unroll
            for (int i = 0; i < 4; i++)
#pragma unroll
                for (int j = 0; j < 4; j++)
                    sv[i][j] += aa[i].x * bb[j].x + aa[i].y * bb[j].y +
                                aa[i].z * bb[j].z + aa[i].w * bb[j].w;
        }

#pragma unroll
        for (int i = 0; i < 4; i++) {
            float mx = sv[i][0];
            mx = fmaxf(mx, sv[i][1]);
            mx = fmaxf(mx, sv[i][2]);
            mx = fmaxf(mx, sv[i][3]);
#pragma unroll
            for (int o = 8; o >= 1; o >>= 1)
                mx = fmaxf(mx, __shfl_xor_sync(0xffffffffu, mx, o));
            const float mnew = fmaxf(mrun[i], mx);
            const float corr = __expf(mrun[i] - mnew);
            float rs = 0.f;
#pragma unroll
            for (int j = 0; j < 4; j++) {
                const float p = __expf(sv[i][j] - mnew);
                Ps[(ty * 4 + i) * ST + tx + 16 * j] = p;
                rs += p;
            }
#pragma unroll
            for (int o = 8; o >= 1; o >>= 1)
                rs += __shfl_xor_sync(0xffffffffu, rs, o);
            lrun[i] = lrun[i] * corr + rs;
#pragma unroll
            for (int j = 0; j < 4; j++) acc[i][j] *= corr;
            mrun[i] = mnew;
        }
        __syncthreads();

#pragma unroll 4
        for (int kk4 = 0; kk4 < 64; kk4 += 4) {
            float4 pp[4];
#pragma unroll
            for (int i = 0; i < 4; i++)
                pp[i] = *(const float4*)&Ps[(ty * 4 + i) * ST + kk4];
#pragma unroll
            for (int t = 0; t < 4; t++) {
                float vv[4];
#pragma unroll
                for (int j = 0; j < 4; j++)
                    vv[j] = Vs[(kk4 + t) * ST + tx + 16 * j];
#pragma unroll
                for (int i = 0; i < 4; i++) {
                    const float pt = ((const float*)&pp[i])[t];
#pragma unroll
                    for (int j = 0; j < 4; j++)
                        acc[i][j] += pt * vv[j];
                }
            }
        }
    }

#pragma unroll
    for (int i = 0; i < 4; i++) {
        const float il = 1.f / lrun[i];
        const size_t row = qrow0 + ty * 4 + i;
#pragma unroll
        for (int j = 0; j < 4; j++)
            out[row * C_ + h * 64 + tx + 16 * j] = acc[i][j] * il;
    }
}

// ---------------------------------------------------------------------------
extern "C" void kernel_launch(void* const* d_in, const int* in_sizes, int n_in,
                              void* d_out, int out_size)
{
    const float* x     = (const float*)d_in[0];
    const float* Wqkv  = (const float*)d_in[1];
    const float* bqkv  = (const float*)d_in[2];
    const float* Wproj = (const float*)d_in[3];
    const float* bproj = (const float*)d_in[4];
    const int*   ph    = (const int*)d_in[5];
    const int*   pw    = (const int*)d_in[6];
    float*       out   = (float*)d_out;

    float *qkv = nullptr, *attn = nullptr;
    __nv_bfloat16 *wqh = nullptr, *wql = nullptr, *wph = nullptr, *wpl = nullptr;
    cudaGetSymbolAddress((void**)&qkv,  g_qkv);
    cudaGetSymbolAddress((void**)&attn, g_attn);
    cudaGetSymbolAddress((void**)&wqh,  g_wqkv_hi);
    cudaGetSymbolAddress((void**)&wql,  g_wqkv_lo);
    cudaGetSymbolAddress((void**)&wph,  g_wproj_hi);
    cudaGetSymbolAddress((void**)&wpl,  g_wproj_lo);

    static bool attr_set = false;
    if (!attr_set) {
        cudaFuncSetAttribute(attn_kernel,
                             cudaFuncAttributeMaxDynamicSharedMemorySize,
                             (int)(4 * 64 * ST * sizeof(float)));
        attr_set = true;
    }

    // 0) Weight transpose + bf16 split (tiled, coalesced both sides)
    split_w_kernel<<<dim3(QKV_N / 32, K_DIM / 32), dim3(32, 8)>>>(Wqkv, wqh, wql, K_DIM, QKV_N);
    split_w_kernel<<<dim3(C_ / 32, K_DIM / 32), dim3(32, 8)>>>(Wproj, wph, wpl, K_DIM, C_);

    // 1) QKV projection (HMMA bf16x3)
    gemm_mma_kernel<<<dim3(QKV_N / 128, M_TOT / 128), 256>>>(
        x, wqh, wql, bqkv, qkv, M_TOT, QKV_N, K_DIM);

    // 2) RoPE in place on q,k
    {
        const int total = M_TOT * 12 * 2 * 2 * 16;
        rope_kernel<<<(total + 255) / 256, 256>>>(qkv, ph, pw);
    }

    // 3) Attention (fp32)
    attn_kernel<<<dim3(16, H_, B_), 256, 4 * 64 * ST * sizeof(float)>>>(qkv, attn);

    // 4) Output projection (HMMA bf16x3)
    gemm_mma_kernel<<<dim3(C_ / 128, M_TOT / 128), 256>>>(
        attn, wph, wpl, bproj, out, M_TOT, C_, K_DIM);
}

// round 5
// speedup vs baseline: 1.8803x; 1.5643x over previous
#include <cuda_runtime.h>
#include <cuda_bf16.h>
#include <cstdint>

#define B_    16
#define N_    1024
#define C_    768
#define H_    12
#define M_TOT (B_ * N_)        // 16384
#define QKV_N (3 * C_)         // 2304
#define K_DIM 768
#define BH_   (B_ * H_)        // 192

// ---------------------------------------------------------------------------
// Scratch (__device__ globals only)
// ---------------------------------------------------------------------------
__device__ __align__(16) float g_qkv[(size_t)M_TOT * QKV_N];
__device__ __align__(16) float g_attn[(size_t)M_TOT * C_];
__device__ __align__(16) __nv_bfloat16 g_wqkv_hi[(size_t)QKV_N * K_DIM];
__device__ __align__(16) __nv_bfloat16 g_wqkv_lo[(size_t)QKV_N * K_DIM];
__device__ __align__(16) __nv_bfloat16 g_wproj_hi[(size_t)C_ * K_DIM];
__device__ __align__(16) __nv_bfloat16 g_wproj_lo[(size_t)C_ * K_DIM];
// Attention operands: Q,K as [b,h,n,64]; V transposed as [b,h,64,n]
__device__ __align__(16) __nv_bfloat16 g_Qh[(size_t)BH_ * N_ * 64];
__device__ __align__(16) __nv_bfloat16 g_Ql[(size_t)BH_ * N_ * 64];
__device__ __align__(16) __nv_bfloat16 g_Kh[(size_t)BH_ * N_ * 64];
__device__ __align__(16) __nv_bfloat16 g_Kl[(size_t)BH_ * N_ * 64];
__device__ __align__(16) __nv_bfloat16 g_Vh[(size_t)BH_ * 64 * N_];
__device__ __align__(16) __nv_bfloat16 g_Vl[(size_t)BH_ * 64 * N_];

// ---------------------------------------------------------------------------
// mma.sync / ldmatrix / cp.async helpers (compute_80 ISA, valid at sm_103)
// ---------------------------------------------------------------------------
__device__ __forceinline__ uint32_t smem_u32(const void* p) {
    uint32_t a;
    asm("{ .reg .u64 t; cvta.to.shared.u64 t, %1; cvt.u32.u64 %0, t; }"
        : "=r"(a) : "l"(p));
    return a;
}
__device__ __forceinline__ void ldm4(uint32_t* r, uint32_t addr) {
    asm volatile("ldmatrix.sync.aligned.m8n8.x4.shared.b16 {%0,%1,%2,%3}, [%4];"
                 : "=r"(r[0]), "=r"(r[1]), "=r"(r[2]), "=r"(r[3]) : "r"(addr));
}
__device__ __forceinline__ void mma_bf16(float* c, const uint32_t* a, const uint32_t* b) {
    asm volatile("mma.sync.aligned.m16n8k16.row.col.f32.bf16.bf16.f32 "
                 "{%0,%1,%2,%3}, {%4,%5,%6,%7}, {%8,%9}, {%0,%1,%2,%3};"
                 : "+f"(c[0]), "+f"(c[1]), "+f"(c[2]), "+f"(c[3])
                 : "r"(a[0]), "r"(a[1]), "r"(a[2]), "r"(a[3]),
                   "r"(b[0]), "r"(b[1]));
}
__device__ __forceinline__ void cp16(uint32_t sa, const void* g) {
    asm volatile("cp.async.cg.shared.global [%0], [%1], 16;" :: "r"(sa), "l"(g));
}
__device__ __forceinline__ void cp_commit() {
    asm volatile("cp.async.commit_group;" ::: "memory");
}
__device__ __forceinline__ void cp_wait1() {
    asm volatile("cp.async.wait_group 1;" ::: "memory");
}
__device__ __forceinline__ void cp_wait0() {
    asm volatile("cp.async.wait_group 0;" ::: "memory");
}
__device__ __forceinline__ uint32_t pack2_bf16(float a, float b) {
    return ((uint32_t)__bfloat16_as_ushort(__float2bfloat16(b)) << 16) |
           (uint32_t)__bfloat16_as_ushort(__float2bfloat16(a));
}

// ---------------------------------------------------------------------------
// Weight prep (unchanged from R4)
// ---------------------------------------------------------------------------
__global__ void split_w_kernel(const float* __restrict__ W,
                               __nv_bfloat16* __restrict__ hi,
                               __nv_bfloat16* __restrict__ lo,
                               int K, int N) {
    __shared__ float t[32][33];
    const int tx = threadIdx.x, ty = threadIdx.y;
    const int n0 = blockIdx.x * 32, k0 = blockIdx.y * 32;
#pragma unroll
    for (int j = 0; j < 4; j++) {
        const int k = k0 + ty + j * 8;
        t[ty + j * 8][tx] = W[(size_t)k * N + n0 + tx];
    }
    __syncthreads();
#pragma unroll
    for (int j = 0; j < 4; j++) {
        const int n = n0 + ty + j * 8;
        const int k = k0 + tx;
        const float w = t[tx][ty + j * 8];
        const __nv_bfloat16 h = __float2bfloat16(w);
        hi[(size_t)n * K + k] = h;
        lo[(size_t)n * K + k] = __float2bfloat16(w - __bfloat162float(h));
    }
}

// ---------------------------------------------------------------------------
// bf16x3 HMMA GEMM (unchanged from R4)
// ---------------------------------------------------------------------------
#define SAB 40

__global__ __launch_bounds__(256) void gemm_mma_kernel(
    const float* __restrict__ A, const __nv_bfloat16* __restrict__ Bhg,
    const __nv_bfloat16* __restrict__ Blg, const float* __restrict__ bias,
    float* __restrict__ Cout, int M, int N, int K)
{
    __shared__ __align__(16) __nv_bfloat16 sm_[4 * 128 * SAB];
    __nv_bfloat16* sAh = sm_;
    __nv_bfloat16* sAl = sm_ + 128 * SAB;
    __nv_bfloat16* sBh = sm_ + 2 * 128 * SAB;
    __nv_bfloat16* sBl = sm_ + 3 * 128 * SAB;
    const uint32_t uAh = smem_u32(sAh), uAl = smem_u32(sAl);
    const uint32_t uBh = smem_u32(sBh), uBl = smem_u32(sBl);

    const int tid = threadIdx.x;
    const int wid = tid >> 5;
    const int l   = tid & 31;
    const int wm  = wid >> 2;
    const int wn  = wid & 3;
    const int bm  = blockIdx.y * 128;
    const int bn  = blockIdx.x * 128;

    const int a_row = l & 15;
    const int a_col = (l >> 4) * 8;
    const int b_row = (l & 7) + ((l >> 4) & 1) * 8;
    const int b_col = ((l >> 3) & 1) * 8;

    float acc[4][4][4];
#pragma unroll
    for (int i = 0; i < 4; i++)
#pragma unroll
        for (int j = 0; j < 4; j++)
#pragma unroll
            for (int t = 0; t < 4; t++) acc[i][j][t] = 0.f;

    for (int kt = 0; kt < K; kt += 32) {
#pragma unroll
        for (int i = 0; i < 4; i++) {
            const int li = i * 256 + tid;
            const int r  = li >> 3;
            const int c4 = (li & 7) * 4;
            const float4 v = *(const float4*)(A + (size_t)(bm + r) * K + kt + c4);
            const __nv_bfloat16 h0 = __float2bfloat16(v.x);
            const __nv_bfloat16 h1 = __float2bfloat16(v.y);
            const __nv_bfloat16 h2 = __float2bfloat16(v.z);
            const __nv_bfloat16 h3 = __float2bfloat16(v.w);
            uint2 hp, lp;
            hp.x = ((uint32_t)__bfloat16_as_ushort(h1) << 16) | __bfloat16_as_ushort(h0);
            hp.y = ((uint32_t)__bfloat16_as_ushort(h3) << 16) | __bfloat16_as_ushort(h2);
            lp.x = pack2_bf16(v.x - __bfloat162float(h0), v.y - __bfloat162float(h1));
            lp.y = pack2_bf16(v.z - __bfloat162float(h2), v.w - __bfloat162float(h3));
            *(uint2*)&sAh[r * SAB + c4] = hp;
            *(uint2*)&sAl[r * SAB + c4] = lp;
        }
#pragma unroll
        for (int i = 0; i < 2; i++) {
            const int li = i * 256 + tid;
            const int r  = li >> 2;
            const int c8 = (li & 3) * 8;
            const size_t gi = (size_t)(bn + r) * K + kt + c8;
            *(uint4*)&sBh[r * SAB + c8] = *(const uint4*)(Bhg + gi);
            *(uint4*)&sBl[r * SAB + c8] = *(const uint4*)(Blg + gi);
        }
        __syncthreads();

#pragma unroll
        for (int kh = 0; kh < 2; kh++) {
            const int kc = kh * 16;
            uint32_t af[4][4], bf[4][2];
#pragma unroll
            for (int ti = 0; ti < 4; ti++)
                ldm4(af[ti], uAh + 2 * ((wm * 64 + ti * 16 + a_row) * SAB + kc + a_col));
#pragma unroll
            for (int bp = 0; bp < 2; bp++) {
                uint32_t r4[4];
                ldm4(r4, uBh + 2 * ((wn * 32 + bp * 16 + b_row) * SAB + kc + b_col));
                bf[bp * 2 + 0][0] = r4[0]; bf[bp * 2 + 0][1] = r4[1];
                bf[bp * 2 + 1][0] = r4[2]; bf[bp * 2 + 1][1] = r4[3];
            }
#pragma unroll
            for (int ti = 0; ti < 4; ti++)
#pragma unroll
                for (int nj = 0; nj < 4; nj++)
                    mma_bf16(acc[ti][nj], af[ti], bf[nj]);
#pragma unroll
            for (int bp = 0; bp < 2; bp++) {
                uint32_t r4[4];
                ldm4(r4, uBl + 2 * ((wn * 32 + bp * 16 + b_row) * SAB + kc + b_col));
                bf[bp * 2 + 0][0] = r4[0]; bf[bp * 2 + 0][1] = r4[1];
                bf[bp * 2 + 1][0] = r4[2]; bf[bp * 2 + 1][1] = r4[3];
            }
#pragma unroll
            for (int ti = 0; ti < 4; ti++)
#pragma unroll
                for (int nj = 0; nj < 4; nj++)
                    mma_bf16(acc[ti][nj], af[ti], bf[nj]);
#pragma unroll
            for (int bp = 0; bp < 2; bp++) {
                uint32_t r4[4];
                ldm4(r4, uBh + 2 * ((wn * 32 + bp * 16 + b_row) * SAB + kc + b_col));
                bf[bp * 2 + 0][0] = r4[0]; bf[bp * 2 + 0][1] = r4[1];
                bf[bp * 2 + 1][0] = r4[2]; bf[bp * 2 + 1][1] = r4[3];
            }
#pragma unroll
            for (int ti = 0; ti < 4; ti++)
                ldm4(af[ti], uAl + 2 * ((wm * 64 + ti * 16 + a_row) * SAB + kc + a_col));
#pragma unroll
            for (int ti = 0; ti < 4; ti++)
#pragma unroll
                for (int nj = 0; nj < 4; nj++)
                    mma_bf16(acc[ti][nj], af[ti], bf[nj]);
        }
        __syncthreads();
    }

    const int row_in = l >> 2;
    const int col_in = (l & 3) * 2;
#pragma unroll
    for (int ti = 0; ti < 4; ti++) {
#pragma unroll
        for (int nj = 0; nj < 4; nj++) {
            const int col = bn + wn * 32 + nj * 8 + col_in;
            const float b0 = bias[col], b1 = bias[col + 1];
            const int r0 = bm + wm * 64 + ti * 16 + row_in;
            float2 v0 = { acc[ti][nj][0] + b0, acc[ti][nj][1] + b1 };
            float2 v1 = { acc[ti][nj][2] + b0, acc[ti][nj][3] + b1 };
            *(float2*)(Cout + (size_t)r0 * N + col) = v0;
            *(float2*)(Cout + (size_t)(r0 + 8) * N + col) = v1;
        }
    }
}

// ---------------------------------------------------------------------------
// RoPE + scale(Q) + hi/lo split of Q,K into [b,h,n,64] bf16
// ---------------------------------------------------------------------------
__global__ void rope_split_kernel(const float* __restrict__ qkv,
                                  const int* __restrict__ ph,
                                  const int* __restrict__ pw,
                                  __nv_bfloat16* __restrict__ Qh,
                                  __nv_bfloat16* __restrict__ Ql,
                                  __nv_bfloat16* __restrict__ Kh,
                                  __nv_bfloat16* __restrict__ Kl)
{
    const int idx = blockIdx.x * blockDim.x + threadIdx.x;
    const int j    = idx & 15;
    const int half = (idx >> 4) & 1;
    const int s    = (idx >> 5) & 1;
    const int head = (idx >> 6) % 12;
    const int row  = idx / 768;
    if (row >= M_TOT) return;

    const float pos = (float)(half ? pw[row] : ph[row]);
    const size_t base = (size_t)row * QKV_N + s * 768 + head * 64 + half * 32;
    const float t0 = qkv[base + j];
    const float t1 = qkv[base + j + 16];

    const float L = 9.210340371976184f / 16.0f;
    const int k0 = j >> 1;
    const float f0 = pos * expf(-L * (float)k0);
    const float f1 = pos * expf(-L * (float)(k0 + 8));
    float c0, s0, c1, s1;
    sincosf(f0, &s0, &c0);
    sincosf(f1, &s1, &c1);

    float o0 = t0 * c0 - t1 * s0;
    float o1 = t1 * c1 + t0 * s1;
    if (s == 0) { o0 *= 0.125f; o1 *= 0.125f; }   // fold 1/sqrt(64) into Q

    const int b = row >> 10, n = row & 1023;
    const size_t ob = ((size_t)(b * 12 + head) * N_ + n) * 64 + half * 32 + j;
    __nv_bfloat16* hi = s ? Kh : Qh;
    __nv_bfloat16* lo = s ? Kl : Ql;
    const __nv_bfloat16 h0 = __float2bfloat16(o0);
    const __nv_bfloat16 h1 = __float2bfloat16(o1);
    hi[ob]      = h0;
    hi[ob + 16] = h1;
    lo[ob]      = __float2bfloat16(o0 - __bfloat162float(h0));
    lo[ob + 16] = __float2bfloat16(o1 - __bfloat162float(h1));
}

// ---------------------------------------------------------------------------
// V: [row][1536+h*64+d] fp32 -> transposed [b,h,d,n] bf16 hi/lo (tiled)
// ---------------------------------------------------------------------------
__global__ void v_split_kernel(const float* __restrict__ qkv,
                               __nv_bfloat16* __restrict__ Vh,
                               __nv_bfloat16* __restrict__ Vl)
{
    __shared__ float ts[64][65];
    const int tid = threadIdx.x;
    const int n0 = blockIdx.x * 64;
    const int h  = blockIdx.y;
    const int b  = blockIdx.z;
    const int bh = b * 12 + h;

#pragma unroll
    for (int i = 0; i < 16; i++) {
        const int li = i * 256 + tid;
        const int r = li >> 6, c = li & 63;
        ts[r][c] = qkv[(size_t)(b * N_ + n0 + r) * QKV_N + 1536 + h * 64 + c];
    }
    __syncthreads();
#pragma unroll
    for (int i = 0; i < 8; i++) {
        const int li = i * 256 + tid;
        const int d = li >> 5, c2 = (li & 31) * 2;
        const float v0 = ts[c2][d], v1 = ts[c2 + 1][d];
        const __nv_bfloat16 h0 = __float2bfloat16(v0);
        const __nv_bfloat16 h1 = __float2bfloat16(v1);
        const size_t ob = ((size_t)bh * 64 + d) * N_ + n0 + c2;
        *(uint32_t*)&Vh[ob] =
            ((uint32_t)__bfloat16_as_ushort(h1) << 16) | __bfloat16_as_ushort(h0);
        *(uint32_t*)&Vl[ob] =
            pack2_bf16(v0 - __bfloat162float(h0), v1 - __bfloat162float(h1));
    }
}

// ---------------------------------------------------------------------------
// Tensor-core flash attention.
// CTA: 128 q-rows x (b,h). 8 warps x 16 rows. 16 key blocks of 64.
// K/V smem double-buffered via cp.async; Q frags direct from gmem.
// ---------------------------------------------------------------------------
#define ATS 72                    // smem row stride (halfs): 144B, ldmatrix conflict-free
#define AAS (64 * ATS)            // halfs per array
#define ATT_SMEM (2 * 4 * AAS * 2) // bytes = 73728

__global__ __launch_bounds__(256, 1) void attn_mma_kernel(
    const __nv_bfloat16* __restrict__ Qh, const __nv_bfloat16* __restrict__ Ql,
    const __nv_bfloat16* __restrict__ Kh, const __nv_bfloat16* __restrict__ Kl,
    const __nv_bfloat16* __restrict__ Vh, const __nv_bfloat16* __restrict__ Vl,
    float* __restrict__ out)
{
    extern __shared__ __nv_bfloat16 smh[];
    const uint32_t sb = smem_u32(smh);

    const int tid = threadIdx.x;
    const int wid = tid >> 5;
    const int l   = tid & 31;
    const int qb  = blockIdx.x;
    const int h   = blockIdx.y;
    const int b   = blockIdx.z;
    const int bh  = b * H_ + h;
    const int q0  = qb * 128;
    const int wrow = wid * 16;

    const int b_row = (l & 7) + ((l >> 4) & 1) * 8;
    const int b_col = ((l >> 3) & 1) * 8;

    // ---- Q fragments (hi/lo), direct gmem loads, once per CTA
    const uint32_t* q32h = (const uint32_t*)(Qh + ((size_t)bh * N_ + q0) * 64);
    const uint32_t* q32l = (const uint32_t*)(Ql + ((size_t)bh * N_ + q0) * 64);
    uint32_t qfh[4][4], qfl[4][4];
    {
        const int r0 = wrow + (l >> 2);
        const int cb = (l & 3) * 2;
#pragma unroll
        for (int t = 0; t < 4; t++) {
            const int c0 = t * 16 + cb;
            qfh[t][0] = q32h[(r0 * 64 + c0) >> 1];
            qfh[t][1] = q32h[((r0 + 8) * 64 + c0) >> 1];
            qfh[t][2] = q32h[(r0 * 64 + c0 + 8) >> 1];
            qfh[t][3] = q32h[((r0 + 8) * 64 + c0 + 8) >> 1];
            qfl[t][0] = q32l[(r0 * 64 + c0) >> 1];
            qfl[t][1] = q32l[((r0 + 8) * 64 + c0) >> 1];
            qfl[t][2] = q32l[(r0 * 64 + c0 + 8) >> 1];
            qfl[t][3] = q32l[((r0 + 8) * 64 + c0 + 8) >> 1];
        }
    }

    // ---- async K/V stage loader: 2048 x 16B chunks, 8 per thread
    const __nv_bfloat16* gKh = Kh + (size_t)bh * N_ * 64;
    const __nv_bfloat16* gKl = Kl + (size_t)bh * N_ * 64;
    const __nv_bfloat16* gVh = Vh + (size_t)bh * 64 * N_;
    const __nv_bfloat16* gVl = Vl + (size_t)bh * 64 * N_;

    auto prefetch = [&](int kb, int st) {
#pragma unroll
        for (int i = 0; i < 8; i++) {
            const int c   = i * 256 + tid;
            const int arr = c >> 9;          // 0:Kh 1:Kl 2:Vh 3:Vl (const per i-pair)
            const int r   = (c >> 3) & 63;
            const int c16 = c & 7;
            const uint32_t sa = sb + 2 * ((st * 4 + arr) * AAS + r * ATS + c16 * 8);
            const __nv_bfloat16* g;
            if (arr == 0)      g = gKh + (size_t)(kb * 64 + r) * 64 + c16 * 8;
            else if (arr == 1) g = gKl + (size_t)(kb * 64 + r) * 64 + c16 * 8;
            else if (arr == 2) g = gVh + (size_t)r * N_ + kb * 64 + c16 * 8;
            else               g = gVl + (size_t)r * N_ + kb * 64 + c16 * 8;
            cp16(sa, g);
        }
        cp_commit();
    };

    float acc[8][4];
    float mrun[2] = { -1e30f, -1e30f }, lrun[2] = { 0.f, 0.f };
#pragma unroll
    for (int j = 0; j < 8; j++)
#pragma unroll
        for (int t = 0; t < 4; t++) acc[j][t] = 0.f;

    prefetch(0, 0);

    for (int kb = 0; kb < 16; kb++) {
        const int st = kb & 1;
        if (kb + 1 < 16) { prefetch(kb + 1, st ^ 1); cp_wait1(); }
        else             { cp_wait0(); }
        __syncthreads();

        const uint32_t uKh = sb + 2 * ((st * 4 + 0) * AAS);
        const uint32_t uKl = sb + 2 * ((st * 4 + 1) * AAS);
        const uint32_t uVh = sb + 2 * ((st * 4 + 2) * AAS);
        const uint32_t uVl = sb + 2 * ((st * 4 + 3) * AAS);

        // ---- S = Q @ K^T  (16 x 64 per warp), 3-term split
        float sv[8][4];
#pragma unroll
        for (int j = 0; j < 8; j++)
#pragma unroll
            for (int t = 0; t < 4; t++) sv[j][t] = 0.f;

#pragma unroll
        for (int t = 0; t < 4; t++) {
#pragma unroll
            for (int bp = 0; bp < 4; bp++) {
                uint32_t rh[4], rl[4];
                ldm4(rh, uKh + 2 * ((bp * 16 + b_row) * ATS + t * 16 + b_col));
                ldm4(rl, uKl + 2 * ((bp * 16 + b_row) * ATS + t * 16 + b_col));
                mma_bf16(sv[2 * bp],     qfh[t], rh);
                mma_bf16(sv[2 * bp + 1], qfh[t], rh + 2);
                mma_bf16(sv[2 * bp],     qfl[t], rh);
                mma_bf16(sv[2 * bp + 1], qfl[t], rh + 2);
                mma_bf16(sv[2 * bp],     qfh[t], rl);
                mma_bf16(sv[2 * bp + 1], qfh[t], rl + 2);
            }
        }

        // ---- online softmax (rows l/4 and l/4+8; cols spread over quad)
#pragma unroll
        for (int i = 0; i < 2; i++) {
            float mx = -1e30f;
#pragma unroll
            for (int j = 0; j < 8; j++)
                mx = fmaxf(mx, fmaxf(sv[j][2 * i], sv[j][2 * i + 1]));
            mx = fmaxf(mx, __shfl_xor_sync(0xffffffffu, mx, 1));
            mx = fmaxf(mx, __shfl_xor_sync(0xffffffffu, mx, 2));
            const float mnew = fmaxf(mrun[i], mx);
            const float corr = __expf(mrun[i] - mnew);
            float rs = 0.f;
#pragma unroll
            for (int j = 0; j < 8; j++) {
                const float p0 = __expf(sv[j][2 * i] - mnew);
                const float p1 = __expf(sv[j][2 * i + 1] - mnew);
                sv[j][2 * i] = p0; sv[j][2 * i + 1] = p1;
                rs += p0 + p1;
            }
            rs += __shfl_xor_sync(0xffffffffu, rs, 1);
            rs += __shfl_xor_sync(0xffffffffu, rs, 2);
            lrun[i] = lrun[i] * corr + rs;
#pragma unroll
            for (int j = 0; j < 8; j++) {
                acc[j][2 * i] *= corr;
                acc[j][2 * i + 1] *= corr;
            }
            mrun[i] = mnew;
        }

        // ---- P fragments (C-frag -> A-frag identity), hi/lo split
        uint32_t pfh[4][4], pfl[4][4];
#pragma unroll
        for (int t = 0; t < 4; t++) {
#pragma unroll
            for (int q = 0; q < 4; q++) {
                const int j = 2 * t + (q >> 1);
                const float p0 = sv[j][(q & 1) * 2];
                const float p1 = sv[j][(q & 1) * 2 + 1];
                const __nv_bfloat16 h0 = __float2bfloat16(p0);
                const __nv_bfloat16 h1 = __float2bfloat16(p1);
                pfh[t][q] = ((uint32_t)__bfloat16_as_ushort(h1) << 16) |
                            __bfloat16_as_ushort(h0);
                pfl[t][q] = pack2_bf16(p0 - __bfloat162float(h0),
                                       p1 - __bfloat162float(h1));
            }
        }

        // ---- O += P @ V  (V^T in smem: [hd][keys]), 3-term split
#pragma unroll
        for (int t = 0; t < 4; t++) {
#pragma unroll
            for (int bp = 0; bp < 4; bp++) {
                uint32_t rh[4], rl[4];
                ldm4(rh, uVh + 2 * ((bp * 16 + b_row) * ATS + t * 16 + b_col));
                ldm4(rl, uVl + 2 * ((bp * 16 + b_row) * ATS + t * 16 + b_col));
                mma_bf16(acc[2 * bp],     pfh[t], rh);
                mma_bf16(acc[2 * bp + 1], pfh[t], rh + 2);
                mma_bf16(acc[2 * bp],     pfl[t], rh);
                mma_bf16(acc[2 * bp + 1], pfl[t], rh + 2);
                mma_bf16(acc[2 * bp],     pfh[t], rl);
                mma_bf16(acc[2 * bp + 1], pfh[t], rl + 2);
            }
        }
        __syncthreads();
    }

    // ---- normalize + store to [B,N,C]
    const float il0 = 1.f / lrun[0];
    const float il1 = 1.f / lrun[1];
    const int r0 = q0 + wrow + (l >> 2);
    const int cb = h * 64 + (l & 3) * 2;
#pragma unroll
    for (int j = 0; j < 8; j++) {
        float2 v0 = { acc[j][0] * il0, acc[j][1] * il0 };
        float2 v1 = { acc[j][2] * il1, acc[j][3] * il1 };
        *(float2*)(out + (size_t)(b * N_ + r0) * C_ + cb + j * 8) = v0;
        *(float2*)(out + (size_t)(b * N_ + r0 + 8) * C_ + cb + j * 8) = v1;
    }
}

// ---------------------------------------------------------------------------
extern "C" void kernel_launch(void* const* d_in, const int* in_sizes, int n_in,
                              void* d_out, int out_size)
{
    const float* x     = (const float*)d_in[0];
    const float* Wqkv  = (const float*)d_in[1];
    const float* bqkv  = (const float*)d_in[2];
    const float* Wproj = (const float*)d_in[3];
    const float* bproj = (const float*)d_in[4];
    const int*   ph    = (const int*)d_in[5];
    const int*   pw    = (const int*)d_in[6];
    float*       out   = (float*)d_out;

    float *qkv = nullptr, *attn = nullptr;
    __nv_bfloat16 *wqh, *wql, *wph, *wpl, *aQh, *aQl, *aKh, *aKl, *aVh, *aVl;
    cudaGetSymbolAddress((void**)&qkv,  g_qkv);
    cudaGetSymbolAddress((void**)&attn, g_attn);
    cudaGetSymbolAddress((void**)&wqh,  g_wqkv_hi);
    cudaGetSymbolAddress((void**)&wql,  g_wqkv_lo);
    cudaGetSymbolAddress((void**)&wph,  g_wproj_hi);
    cudaGetSymbolAddress((void**)&wpl,  g_wproj_lo);
    cudaGetSymbolAddress((void**)&aQh,  g_Qh);
    cudaGetSymbolAddress((void**)&aQl,  g_Ql);
    cudaGetSymbolAddress((void**)&aKh,  g_Kh);
    cudaGetSymbolAddress((void**)&aKl,  g_Kl);
    cudaGetSymbolAddress((void**)&aVh,  g_Vh);
    cudaGetSymbolAddress((void**)&aVl,  g_Vl);

    static bool attr_set = false;
    if (!attr_set) {
        cudaFuncSetAttribute(attn_mma_kernel,
                             cudaFuncAttributeMaxDynamicSharedMemorySize, ATT_SMEM);
        attr_set = true;
    }

    // 0) Weight transpose + bf16 split
    split_w_kernel<<<dim3(QKV_N / 32, K_DIM / 32), dim3(32, 8)>>>(Wqkv, wqh, wql, K_DIM, QKV_N);
    split_w_kernel<<<dim3(C_ / 32, K_DIM / 32), dim3(32, 8)>>>(Wproj, wph, wpl, K_DIM, C_);

    // 1) QKV projection (HMMA bf16x3)
    gemm_mma_kernel<<<dim3(QKV_N / 128, M_TOT / 128), 256>>>(
        x, wqh, wql, bqkv, qkv, M_TOT, QKV_N, K_DIM);

    // 2) RoPE + scale + split Q,K ; transpose + split V
    {
        const int total = M_TOT * 12 * 2 * 2 * 16;
        rope_split_kernel<<<(total + 255) / 256, 256>>>(qkv, ph, pw, aQh, aQl, aKh, aKl);
        v_split_kernel<<<dim3(N_ / 64, H_, B_), 256>>>(qkv, aVh, aVl);
    }

    // 3) Tensor-core flash attention
    attn_mma_kernel<<<dim3(N_ / 128, H_, B_), 256, ATT_SMEM>>>(
        aQh, aQl, aKh, aKl, aVh, aVl, attn);

    // 4) Output projection (HMMA bf16x3)
    gemm_mma_kernel<<<dim3(C_ / 128, M_TOT / 128), 256>>>(
        attn, wph, wpl, bproj, out, M_TOT, C_, K_DIM);
}

// round 6
// speedup vs baseline: 2.2388x; 1.1907x over previous
#include <cuda_runtime.h>
#include <cuda_bf16.h>
#include <cstdint>

#define B_    16
#define N_    1024
#define C_    768
#define H_    12
#define M_TOT (B_ * N_)        // 16384
#define QKV_N (3 * C_)         // 2304
#define K_DIM 768
#define BH_   (B_ * H_)        // 192

// ---------------------------------------------------------------------------
// Scratch (__device__ globals only)
// ---------------------------------------------------------------------------
__device__ __align__(16) float g_qkv[(size_t)M_TOT * QKV_N];
__device__ __align__(16) float g_attn[(size_t)M_TOT * C_];
__device__ __align__(16) __nv_bfloat16 g_wqkv_hi[(size_t)QKV_N * K_DIM];
__device__ __align__(16) __nv_bfloat16 g_wqkv_lo[(size_t)QKV_N * K_DIM];
__device__ __align__(16) __nv_bfloat16 g_wproj_hi[(size_t)C_ * K_DIM];
__device__ __align__(16) __nv_bfloat16 g_wproj_lo[(size_t)C_ * K_DIM];
// Activation hi/lo split (reused for x and attn-out; same shape)
__device__ __align__(16) __nv_bfloat16 g_ah[(size_t)M_TOT * K_DIM];
__device__ __align__(16) __nv_bfloat16 g_al[(size_t)M_TOT * K_DIM];
// Attention operands: Q,K as [b,h,n,64]; V transposed as [b,h,64,n]
__device__ __align__(16) __nv_bfloat16 g_Qh[(size_t)BH_ * N_ * 64];
__device__ __align__(16) __nv_bfloat16 g_Ql[(size_t)BH_ * N_ * 64];
__device__ __align__(16) __nv_bfloat16 g_Kh[(size_t)BH_ * N_ * 64];
__device__ __align__(16) __nv_bfloat16 g_Kl[(size_t)BH_ * N_ * 64];
__device__ __align__(16) __nv_bfloat16 g_Vh[(size_t)BH_ * 64 * N_];
__device__ __align__(16) __nv_bfloat16 g_Vl[(size_t)BH_ * 64 * N_];

// ---------------------------------------------------------------------------
// mma.sync / ldmatrix / cp.async helpers (compute_80 ISA, valid at sm_103)
// ---------------------------------------------------------------------------
__device__ __forceinline__ uint32_t smem_u32(const void* p) {
    uint32_t a;
    asm("{ .reg .u64 t; cvta.to.shared.u64 t, %1; cvt.u32.u64 %0, t; }"
        : "=r"(a) : "l"(p));
    return a;
}
__device__ __forceinline__ void ldm4(uint32_t* r, uint32_t addr) {
    asm volatile("ldmatrix.sync.aligned.m8n8.x4.shared.b16 {%0,%1,%2,%3}, [%4];"
                 : "=r"(r[0]), "=r"(r[1]), "=r"(r[2]), "=r"(r[3]) : "r"(addr));
}
__device__ __forceinline__ void mma_bf16(float* c, const uint32_t* a, const uint32_t* b) {
    asm volatile("mma.sync.aligned.m16n8k16.row.col.f32.bf16.bf16.f32 "
                 "{%0,%1,%2,%3}, {%4,%5,%6,%7}, {%8,%9}, {%0,%1,%2,%3};"
                 : "+f"(c[0]), "+f"(c[1]), "+f"(c[2]), "+f"(c[3])
                 : "r"(a[0]), "r"(a[1]), "r"(a[2]), "r"(a[3]),
                   "r"(b[0]), "r"(b[1]));
}
__device__ __forceinline__ void cp16(uint32_t sa, const void* g) {
    asm volatile("cp.async.cg.shared.global [%0], [%1], 16;" :: "r"(sa), "l"(g));
}
__device__ __forceinline__ void cp_commit() {
    asm volatile("cp.async.commit_group;" ::: "memory");
}
__device__ __forceinline__ void cp_wait1() {
    asm volatile("cp.async.wait_group 1;" ::: "memory");
}
__device__ __forceinline__ void cp_wait0() {
    asm volatile("cp.async.wait_group 0;" ::: "memory");
}
__device__ __forceinline__ uint32_t pack2_bf16(float a, float b) {
    return ((uint32_t)__bfloat16_as_ushort(__float2bfloat16(b)) << 16) |
           (uint32_t)__bfloat16_as_ushort(__float2bfloat16(a));
}

// ---------------------------------------------------------------------------
// Weight prep (unchanged)
// ---------------------------------------------------------------------------
__global__ void split_w_kernel(const float* __restrict__ W,
                               __nv_bfloat16* __restrict__ hi,
                               __nv_bfloat16* __restrict__ lo,
                               int K, int N) {
    __shared__ float t[32][33];
    const int tx = threadIdx.x, ty = threadIdx.y;
    const int n0 = blockIdx.x * 32, k0 = blockIdx.y * 32;
#pragma unroll
    for (int j = 0; j < 4; j++) {
        const int k = k0 + ty + j * 8;
        t[ty + j * 8][tx] = W[(size_t)k * N + n0 + tx];
    }
    __syncthreads();
#pragma unroll
    for (int j = 0; j < 4; j++) {
        const int n = n0 + ty + j * 8;
        const int k = k0 + tx;
        const float w = t[tx][ty + j * 8];
        const __nv_bfloat16 h = __float2bfloat16(w);
        hi[(size_t)n * K + k] = h;
        lo[(size_t)n * K + k] = __float2bfloat16(w - __bfloat162float(h));
    }
}

// ---------------------------------------------------------------------------
// Activation split: A [M,K] fp32 -> hi/lo bf16 [M,K] (elementwise, vectorized)
// ---------------------------------------------------------------------------
__global__ void split_a_kernel(const float* __restrict__ A,
                               __nv_bfloat16* __restrict__ hi,
                               __nv_bfloat16* __restrict__ lo,
                               int total4)
{
    const int i = blockIdx.x * blockDim.x + threadIdx.x;
    if (i >= total4) return;
    const float4 v = ((const float4*)A)[i];
    const __nv_bfloat16 h0 = __float2bfloat16(v.x);
    const __nv_bfloat16 h1 = __float2bfloat16(v.y);
    const __nv_bfloat16 h2 = __float2bfloat16(v.z);
    const __nv_bfloat16 h3 = __float2bfloat16(v.w);
    uint2 hp, lp;
    hp.x = ((uint32_t)__bfloat16_as_ushort(h1) << 16) | __bfloat16_as_ushort(h0);
    hp.y = ((uint32_t)__bfloat16_as_ushort(h3) << 16) | __bfloat16_as_ushort(h2);
    lp.x = pack2_bf16(v.x - __bfloat162float(h0), v.y - __bfloat162float(h1));
    lp.y = pack2_bf16(v.z - __bfloat162float(h2), v.w - __bfloat162float(h3));
    ((uint2*)hi)[i] = hp;
    ((uint2*)lo)[i] = lp;
}

// ---------------------------------------------------------------------------
// bf16x3 HMMA GEMM, cp.async double-buffered.
// C[M,N] = A[M,K] @ Bt[N,K]^T + bias.  All operands bf16 hi/lo, pre-split.
// BM=BN=128, BK=32, 256 thr (8 warps, 2x4), warp tile 64x32.
// ---------------------------------------------------------------------------
#define GSB 40                       // smem row stride (halfs)
#define GAS (128 * GSB)              // halfs per array
#define GSTG (4 * GAS)               // halfs per stage (Ah,Al,Bh,Bl)
#define GEMM_SMEM (2 * GSTG * 2)     // bytes = 81920

__global__ __launch_bounds__(256, 1) void gemm_mma_kernel(
    const __nv_bfloat16* __restrict__ Ahg, const __nv_bfloat16* __restrict__ Alg,
    const __nv_bfloat16* __restrict__ Bhg, const __nv_bfloat16* __restrict__ Blg,
    const float* __restrict__ bias, float* __restrict__ Cout,
    int M, int N, int K)
{
    extern __shared__ __nv_bfloat16 gsm[];
    const uint32_t sb = smem_u32(gsm);

    const int tid = threadIdx.x;
    const int wid = tid >> 5;
    const int l   = tid & 31;
    const int wm  = wid >> 2;
    const int wn  = wid & 3;
    const int bm  = blockIdx.y * 128;
    const int bn  = blockIdx.x * 128;

    const int a_row = l & 15;
    const int a_col = (l >> 4) * 8;
    const int b_row = (l & 7) + ((l >> 4) & 1) * 8;
    const int b_col = ((l >> 3) & 1) * 8;

    // stage prefetch: 4 arrays x 128 rows x 4 chunks(16B) = 2048 chunks, 8/thread
    auto prefetch = [&](int kt, int st) {
#pragma unroll
        for (int i = 0; i < 8; i++) {
            const int c   = i * 256 + tid;
            const int arr = c >> 9;            // 0:Ah 1:Al 2:Bh 3:Bl
            const int r   = (c >> 2) & 127;
            const int c16 = c & 3;
            const uint32_t sa = sb + 2 * (st * GSTG + arr * GAS + r * GSB + c16 * 8);
            const __nv_bfloat16* g;
            if (arr == 0)      g = Ahg + (size_t)(bm + r) * K + kt + c16 * 8;
            else if (arr == 1) g = Alg + (size_t)(bm + r) * K + kt + c16 * 8;
            else if (arr == 2) g = Bhg + (size_t)(bn + r) * K + kt + c16 * 8;
            else               g = Blg + (size_t)(bn + r) * K + kt + c16 * 8;
            cp16(sa, g);
        }
        cp_commit();
    };

    float acc[4][4][4];
#pragma unroll
    for (int i = 0; i < 4; i++)
#pragma unroll
        for (int j = 0; j < 4; j++)
#pragma unroll
            for (int t = 0; t < 4; t++) acc[i][j][t] = 0.f;

    const int nk = K / 32;
    prefetch(0, 0);

    for (int it = 0; it < nk; it++) {
        const int st = it & 1;
        if (it + 1 < nk) { prefetch((it + 1) * 32, st ^ 1); cp_wait1(); }
        else             { cp_wait0(); }
        __syncthreads();

        const uint32_t uAh = sb + 2 * (st * GSTG + 0 * GAS);
        const uint32_t uAl = sb + 2 * (st * GSTG + 1 * GAS);
        const uint32_t uBh = sb + 2 * (st * GSTG + 2 * GAS);
        const uint32_t uBl = sb + 2 * (st * GSTG + 3 * GAS);

#pragma unroll
        for (int kh = 0; kh < 2; kh++) {
            const int kc = kh * 16;
            uint32_t af[4][4], bf[4][2];
#pragma unroll
            for (int ti = 0; ti < 4; ti++)
                ldm4(af[ti], uAh + 2 * ((wm * 64 + ti * 16 + a_row) * GSB + kc + a_col));
#pragma unroll
            for (int bp = 0; bp < 2; bp++) {
                uint32_t r4[4];
                ldm4(r4, uBh + 2 * ((wn * 32 + bp * 16 + b_row) * GSB + kc + b_col));
                bf[bp * 2 + 0][0] = r4[0]; bf[bp * 2 + 0][1] = r4[1];
                bf[bp * 2 + 1][0] = r4[2]; bf[bp * 2 + 1][1] = r4[3];
            }
#pragma unroll
            for (int ti = 0; ti < 4; ti++)
#pragma unroll
                for (int nj = 0; nj < 4; nj++)
                    mma_bf16(acc[ti][nj], af[ti], bf[nj]);
#pragma unroll
            for (int bp = 0; bp < 2; bp++) {
                uint32_t r4[4];
                ldm4(r4, uBl + 2 * ((wn * 32 + bp * 16 + b_row) * GSB + kc + b_col));
                bf[bp * 2 + 0][0] = r4[0]; bf[bp * 2 + 0][1] = r4[1];
                bf[bp * 2 + 1][0] = r4[2]; bf[bp * 2 + 1][1] = r4[3];
            }
#pragma unroll
            for (int ti = 0; ti < 4; ti++)
#pragma unroll
                for (int nj = 0; nj < 4; nj++)
                    mma_bf16(acc[ti][nj], af[ti], bf[nj]);
#pragma unroll
            for (int bp = 0; bp < 2; bp++) {
                uint32_t r4[4];
                ldm4(r4, uBh + 2 * ((wn * 32 + bp * 16 + b_row) * GSB + kc + b_col));
                bf[bp * 2 + 0][0] = r4[0]; bf[bp * 2 + 0][1] = r4[1];
                bf[bp * 2 + 1][0] = r4[2]; bf[bp * 2 + 1][1] = r4[3];
            }
#pragma unroll
            for (int ti = 0; ti < 4; ti++)
                ldm4(af[ti], uAl + 2 * ((wm * 64 + ti * 16 + a_row) * GSB + kc + a_col));
#pragma unroll
            for (int ti = 0; ti < 4; ti++)
#pragma unroll
                for (int nj = 0; nj < 4; nj++)
                    mma_bf16(acc[ti][nj], af[ti], bf[nj]);
        }
        __syncthreads();
    }

    const int row_in = l >> 2;
    const int col_in = (l & 3) * 2;
#pragma unroll
    for (int ti = 0; ti < 4; ti++) {
#pragma unroll
        for (int nj = 0; nj < 4; nj++) {
            const int col = bn + wn * 32 + nj * 8 + col_in;
            const float b0 = bias[col], b1 = bias[col + 1];
            const int r0 = bm + wm * 64 + ti * 16 + row_in;
            float2 v0 = { acc[ti][nj][0] + b0, acc[ti][nj][1] + b1 };
            float2 v1 = { acc[ti][nj][2] + b0, acc[ti][nj][3] + b1 };
            *(float2*)(Cout + (size_t)r0 * N + col) = v0;
            *(float2*)(Cout + (size_t)(r0 + 8) * N + col) = v1;
        }
    }
}

// ---------------------------------------------------------------------------
// RoPE + scale(Q) + hi/lo split of Q,K into [b,h,n,64] bf16 (unchanged)
// ---------------------------------------------------------------------------
__global__ void rope_split_kernel(const float* __restrict__ qkv,
                                  const int* __restrict__ ph,
                                  const int* __restrict__ pw,
                                  __nv_bfloat16* __restrict__ Qh,
                                  __nv_bfloat16* __restrict__ Ql,
                                  __nv_bfloat16* __restrict__ Kh,
                                  __nv_bfloat16* __restrict__ Kl)
{
    const int idx = blockIdx.x * blockDim.x + threadIdx.x;
    const int j    = idx & 15;
    const int half = (idx >> 4) & 1;
    const int s    = (idx >> 5) & 1;
    const int head = (idx >> 6) % 12;
    const int row  = idx / 768;
    if (row >= M_TOT) return;

    const float pos = (float)(half ? pw[row] : ph[row]);
    const size_t base = (size_t)row * QKV_N + s * 768 + head * 64 + half * 32;
    const float t0 = qkv[base + j];
    const float t1 = qkv[base + j + 16];

    const float L = 9.210340371976184f / 16.0f;
    const int k0 = j >> 1;
    const float f0 = pos * expf(-L * (float)k0);
    const float f1 = pos * expf(-L * (float)(k0 + 8));
    float c0, s0, c1, s1;
    sincosf(f0, &s0, &c0);
    sincosf(f1, &s1, &c1);

    float o0 = t0 * c0 - t1 * s0;
    float o1 = t1 * c1 + t0 * s1;
    if (s == 0) { o0 *= 0.125f; o1 *= 0.125f; }

    const int b = row >> 10, n = row & 1023;
    const size_t ob = ((size_t)(b * 12 + head) * N_ + n) * 64 + half * 32 + j;
    __nv_bfloat16* hi = s ? Kh : Qh;
    __nv_bfloat16* lo = s ? Kl : Ql;
    const __nv_bfloat16 h0 = __float2bfloat16(o0);
    const __nv_bfloat16 h1 = __float2bfloat16(o1);
    hi[ob]      = h0;
    hi[ob + 16] = h1;
    lo[ob]      = __float2bfloat16(o0 - __bfloat162float(h0));
    lo[ob + 16] = __float2bfloat16(o1 - __bfloat162float(h1));
}

// ---------------------------------------------------------------------------
// V transpose + split (unchanged)
// ---------------------------------------------------------------------------
__global__ void v_split_kernel(const float* __restrict__ qkv,
                               __nv_bfloat16* __restrict__ Vh,
                               __nv_bfloat16* __restrict__ Vl)
{
    __shared__ float ts[64][65];
    const int tid = threadIdx.x;
    const int n0 = blockIdx.x * 64;
    const int h  = blockIdx.y;
    const int b  = blockIdx.z;
    const int bh = b * 12 + h;

#pragma unroll
    for (int i = 0; i < 16; i++) {
        const int li = i * 256 + tid;
        const int r = li >> 6, c = li & 63;
        ts[r][c] = qkv[(size_t)(b * N_ + n0 + r) * QKV_N + 1536 + h * 64 + c];
    }
    __syncthreads();
#pragma unroll
    for (int i = 0; i < 8; i++) {
        const int li = i * 256 + tid;
        const int d = li >> 5, c2 = (li & 31) * 2;
        const float v0 = ts[c2][d], v1 = ts[c2 + 1][d];
        const __nv_bfloat16 h0 = __float2bfloat16(v0);
        const __nv_bfloat16 h1 = __float2bfloat16(v1);
        const size_t ob = ((size_t)bh * 64 + d) * N_ + n0 + c2;
        *(uint32_t*)&Vh[ob] =
            ((uint32_t)__bfloat16_as_ushort(h1) << 16) | __bfloat16_as_ushort(h0);
        *(uint32_t*)&Vl[ob] =
            pack2_bf16(v0 - __bfloat162float(h0), v1 - __bfloat162float(h1));
    }
}

// ---------------------------------------------------------------------------
// Tensor-core flash attention (unchanged from R5)
// ---------------------------------------------------------------------------
#define ATS 72
#define AAS (64 * ATS)
#define ATT_SMEM (2 * 4 * AAS * 2)

__global__ __launch_bounds__(256, 1) void attn_mma_kernel(
    const __nv_bfloat16* __restrict__ Qh, const __nv_bfloat16* __restrict__ Ql,
    const __nv_bfloat16* __restrict__ Kh, const __nv_bfloat16* __restrict__ Kl,
    const __nv_bfloat16* __restrict__ Vh, const __nv_bfloat16* __restrict__ Vl,
    float* __restrict__ out)
{
    extern __shared__ __nv_bfloat16 smh[];
    const uint32_t sb = smem_u32(smh);

    const int tid = threadIdx.x;
    const int wid = tid >> 5;
    const int l   = tid & 31;
    const int qb  = blockIdx.x;
    const int h   = blockIdx.y;
    const int b   = blockIdx.z;
    const int bh  = b * H_ + h;
    const int q0  = qb * 128;
    const int wrow = wid * 16;

    const int b_row = (l & 7) + ((l >> 4) & 1) * 8;
    const int b_col = ((l >> 3) & 1) * 8;

    const uint32_t* q32h = (const uint32_t*)(Qh + ((size_t)bh * N_ + q0) * 64);
    const uint32_t* q32l = (const uint32_t*)(Ql + ((size_t)bh * N_ + q0) * 64);
    uint32_t qfh[4][4], qfl[4][4];
    {
        const int r0 = wrow + (l >> 2);
        const int cb = (l & 3) * 2;
#pragma unroll
        for (int t = 0; t < 4; t++) {
            const int c0 = t * 16 + cb;
            qfh[t][0] = q32h[(r0 * 64 + c0) >> 1];
            qfh[t][1] = q32h[((r0 + 8) * 64 + c0) >> 1];
            qfh[t][2] = q32h[(r0 * 64 + c0 + 8) >> 1];
            qfh[t][3] = q32h[((r0 + 8) * 64 + c0 + 8) >> 1];
            qfl[t][0] = q32l[(r0 * 64 + c0) >> 1];
            qfl[t][1] = q32l[((r0 + 8) * 64 + c0) >> 1];
            qfl[t][2] = q32l[(r0 * 64 + c0 + 8) >> 1];
            qfl[t][3] = q32l[((r0 + 8) * 64 + c0 + 8) >> 1];
        }
    }

    const __nv_bfloat16* gKh = Kh + (size_t)bh * N_ * 64;
    const __nv_bfloat16* gKl = Kl + (size_t)bh * N_ * 64;
    const __nv_bfloat16* gVh = Vh + (size_t)bh * 64 * N_;
    const __nv_bfloat16* gVl = Vl + (size_t)bh * 64 * N_;

    auto prefetch = [&](int kb, int st) {
#pragma unroll
        for (int i = 0; i < 8; i++) {
            const int c   = i * 256 + tid;
            const int arr = c >> 9;
            const int r   = (c >> 3) & 63;
            const int c16 = c & 7;
            const uint32_t sa = sb + 2 * ((st * 4 + arr) * AAS + r * ATS + c16 * 8);
            const __nv_bfloat16* g;
            if (arr == 0)      g = gKh + (size_t)(kb * 64 + r) * 64 + c16 * 8;
            else if (arr == 1) g = gKl + (size_t)(kb * 64 + r) * 64 + c16 * 8;
            else if (arr == 2) g = gVh + (size_t)r * N_ + kb * 64 + c16 * 8;
            else               g = gVl + (size_t)r * N_ + kb * 64 + c16 * 8;
            cp16(sa, g);
        }
        cp_commit();
    };

    float acc[8][4];
    float mrun[2] = { -1e30f, -1e30f }, lrun[2] = { 0.f, 0.f };
#pragma unroll
    for (int j = 0; j < 8; j++)
#pragma unroll
        for (int t = 0; t < 4; t++) acc[j][t] = 0.f;

    prefetch(0, 0);

    for (int kb = 0; kb < 16; kb++) {
        const int st = kb & 1;
        if (kb + 1 < 16) { prefetch(kb + 1, st ^ 1); cp_wait1(); }
        else             { cp_wait0(); }
        __syncthreads();

        const uint32_t uKh = sb + 2 * ((st * 4 + 0) * AAS);
        const uint32_t uKl = sb + 2 * ((st * 4 + 1) * AAS);
        const uint32_t uVh = sb + 2 * ((st * 4 + 2) * AAS);
        const uint32_t uVl = sb + 2 * ((st * 4 + 3) * AAS);

        float sv[8][4];
#pragma unroll
        for (int j = 0; j < 8; j++)
#pragma unroll
            for (int t = 0; t < 4; t++) sv[j][t] = 0.f;

#pragma unroll
        for (int t = 0; t < 4; t++) {
#pragma unroll
            for (int bp = 0; bp < 4; bp++) {
                uint32_t rh[4], rl[4];
                ldm4(rh, uKh + 2 * ((bp * 16 + b_row) * ATS + t * 16 + b_col));
                ldm4(rl, uKl + 2 * ((bp * 16 + b_row) * ATS + t * 16 + b_col));
                mma_bf16(sv[2 * bp],     qfh[t], rh);
                mma_bf16(sv[2 * bp + 1], qfh[t], rh + 2);
                mma_bf16(sv[2 * bp],     qfl[t], rh);
                mma_bf16(sv[2 * bp + 1], qfl[t], rh + 2);
                mma_bf16(sv[2 * bp],     qfh[t], rl);
                mma_bf16(sv[2 * bp + 1], qfh[t], rl + 2);
            }
        }

#pragma unroll
        for (int i = 0; i < 2; i++) {
            float mx = -1e30f;
#pragma unroll
            for (int j = 0; j < 8; j++)
                mx = fmaxf(mx, fmaxf(sv[j][2 * i], sv[j][2 * i + 1]));
            mx = fmaxf(mx, __shfl_xor_sync(0xffffffffu, mx, 1));
            mx = fmaxf(mx, __shfl_xor_sync(0xffffffffu, mx, 2));
            const float mnew = fmaxf(mrun[i], mx);
            const float corr = __expf(mrun[i] - mnew);
            float rs = 0.f;
#pragma unroll
            for (int j = 0; j < 8; j++) {
                const float p0 = __expf(sv[j][2 * i] - mnew);
                const float p1 = __expf(sv[j][2 * i + 1] - mnew);
                sv[j][2 * i] = p0; sv[j][2 * i + 1] = p1;
                rs += p0 + p1;
            }
            rs += __shfl_xor_sync(0xffffffffu, rs, 1);
            rs += __shfl_xor_sync(0xffffffffu, rs, 2);
            lrun[i] = lrun[i] * corr + rs;
#pragma unroll
            for (int j = 0; j < 8; j++) {
                acc[j][2 * i] *= corr;
                acc[j][2 * i + 1] *= corr;
            }
            mrun[i] = mnew;
        }

        uint32_t pfh[4][4], pfl[4][4];
#pragma unroll
        for (int t = 0; t < 4; t++) {
#pragma unroll
            for (int q = 0; q < 4; q++) {
                const int j = 2 * t + (q >> 1);
                const float p0 = sv[j][(q & 1) * 2];
                const float p1 = sv[j][(q & 1) * 2 + 1];
                const __nv_bfloat16 h0 = __float2bfloat16(p0);
                const __nv_bfloat16 h1 = __float2bfloat16(p1);
                pfh[t][q] = ((uint32_t)__bfloat16_as_ushort(h1) << 16) |
                            __bfloat16_as_ushort(h0);
                pfl[t][q] = pack2_bf16(p0 - __bfloat162float(h0),
                                       p1 - __bfloat162float(h1));
            }
        }

#pragma unroll
        for (int t = 0; t < 4; t++) {
#pragma unroll
            for (int bp = 0; bp < 4; bp++) {
                uint32_t rh[4], rl[4];
                ldm4(rh, uVh + 2 * ((bp * 16 + b_row) * ATS + t * 16 + b_col));
                ldm4(rl, uVl + 2 * ((bp * 16 + b_row) * ATS + t * 16 + b_col));
                mma_bf16(acc[2 * bp],     pfh[t], rh);
                mma_bf16(acc[2 * bp + 1], pfh[t], rh + 2);
                mma_bf16(acc[2 * bp],     pfl[t], rh);
                mma_bf16(acc[2 * bp + 1], pfl[t], rh + 2);
                mma_bf16(acc[2 * bp],     pfh[t], rl);
                mma_bf16(acc[2 * bp + 1], pfh[t], rl + 2);
            }
        }
        __syncthreads();
    }

    const float il0 = 1.f / lrun[0];
    const float il1 = 1.f / lrun[1];
    const int r0 = q0 + wrow + (l >> 2);
    const int cb = h * 64 + (l & 3) * 2;
#pragma unroll
    for (int j = 0; j < 8; j++) {
        float2 v0 = { acc[j][0] * il0, acc[j][1] * il0 };
        float2 v1 = { acc[j][2] * il1, acc[j][3] * il1 };
        *(float2*)(out + (size_t)(b * N_ + r0) * C_ + cb + j * 8) = v0;
        *(float2*)(out + (size_t)(b * N_ + r0 + 8) * C_ + cb + j * 8) = v1;
    }
}

// ---------------------------------------------------------------------------
extern "C" void kernel_launch(void* const* d_in, const int* in_sizes, int n_in,
                              void* d_out, int out_size)
{
    const float* x     = (const float*)d_in[0];
    const float* Wqkv  = (const float*)d_in[1];
    const float* bqkv  = (const float*)d_in[2];
    const float* Wproj = (const float*)d_in[3];
    const float* bproj = (const float*)d_in[4];
    const int*   ph    = (const int*)d_in[5];
    const int*   pw    = (const int*)d_in[6];
    float*       out   = (float*)d_out;

    float *qkv = nullptr, *attn = nullptr;
    __nv_bfloat16 *wqh, *wql, *wph, *wpl, *ah, *al;
    __nv_bfloat16 *aQh, *aQl, *aKh, *aKl, *aVh, *aVl;
    cudaGetSymbolAddress((void**)&qkv,  g_qkv);
    cudaGetSymbolAddress((void**)&attn, g_attn);
    cudaGetSymbolAddress((void**)&wqh,  g_wqkv_hi);
    cudaGetSymbolAddress((void**)&wql,  g_wqkv_lo);
    cudaGetSymbolAddress((void**)&wph,  g_wproj_hi);
    cudaGetSymbolAddress((void**)&wpl,  g_wproj_lo);
    cudaGetSymbolAddress((void**)&ah,   g_ah);
    cudaGetSymbolAddress((void**)&al,   g_al);
    cudaGetSymbolAddress((void**)&aQh,  g_Qh);
    cudaGetSymbolAddress((void**)&aQl,  g_Ql);
    cudaGetSymbolAddress((void**)&aKh,  g_Kh);
    cudaGetSymbolAddress((void**)&aKl,  g_Kl);
    cudaGetSymbolAddress((void**)&aVh,  g_Vh);
    cudaGetSymbolAddress((void**)&aVl,  g_Vl);

    static bool attr_set = false;
    if (!attr_set) {
        cudaFuncSetAttribute(attn_mma_kernel,
                             cudaFuncAttributeMaxDynamicSharedMemorySize, ATT_SMEM);
        cudaFuncSetAttribute(gemm_mma_kernel,
                             cudaFuncAttributeMaxDynamicSharedMemorySize, GEMM_SMEM);
        attr_set = true;
    }

    const int a_total4 = M_TOT * K_DIM / 4;

    // 0) Weight transpose + bf16 split
    split_w_kernel<<<dim3(QKV_N / 32, K_DIM / 32), dim3(32, 8)>>>(Wqkv, wqh, wql, K_DIM, QKV_N);
    split_w_kernel<<<dim3(C_ / 32, K_DIM / 32), dim3(32, 8)>>>(Wproj, wph, wpl, K_DIM, C_);

    // 1) QKV projection (bf16x3, double-buffered)
    split_a_kernel<<<(a_total4 + 255) / 256, 256>>>(x, ah, al, a_total4);
    gemm_mma_kernel<<<dim3(QKV_N / 128, M_TOT / 128), 256, GEMM_SMEM>>>(
        ah, al, wqh, wql, bqkv, qkv, M_TOT, QKV_N, K_DIM);

    // 2) RoPE + scale + split Q,K ; transpose + split V
    {
        const int total = M_TOT * 12 * 2 * 2 * 16;
        rope_split_kernel<<<(total + 255) / 256, 256>>>(qkv, ph, pw, aQh, aQl, aKh, aKl);
        v_split_kernel<<<dim3(N_ / 64, H_, B_), 256>>>(qkv, aVh, aVl);
    }

    // 3) Tensor-core flash attention
    attn_mma_kernel<<<dim3(N_ / 128, H_, B_), 256, ATT_SMEM>>>(
        aQh, aQl, aKh, aKl, aVh, aVl, attn);

    // 4) Output projection (bf16x3, double-buffered)
    split_a_kernel<<<(a_total4 + 255) / 256, 256>>>(attn, ah, al, a_total4);
    gemm_mma_kernel<<<dim3(C_ / 128, M_TOT / 128), 256, GEMM_SMEM>>>(
        ah, al, wph, wpl, bproj, out, M_TOT, C_, K_DIM);
}

// round 7
// speedup vs baseline: 2.4020x; 1.0729x over previous
#include <cuda_runtime.h>
#include <cuda_bf16.h>
#include <cstdint>

#define B_    16
#define N_    1024
#define C_    768
#define H_    12
#define M_TOT (B_ * N_)        // 16384
#define QKV_N (3 * C_)         // 2304
#define K_DIM 768
#define BH_   (B_ * H_)        // 192

// ---------------------------------------------------------------------------
// Scratch (__device__ globals only)
// ---------------------------------------------------------------------------
__device__ __align__(16) float g_qkv[(size_t)M_TOT * QKV_N];
__device__ __align__(16) float g_attn[(size_t)M_TOT * C_];
__device__ __align__(16) __nv_bfloat16 g_wqkv_hi[(size_t)QKV_N * K_DIM];
__device__ __align__(16) __nv_bfloat16 g_wqkv_lo[(size_t)QKV_N * K_DIM];
__device__ __align__(16) __nv_bfloat16 g_wproj_hi[(size_t)C_ * K_DIM];
__device__ __align__(16) __nv_bfloat16 g_wproj_lo[(size_t)C_ * K_DIM];
__device__ __align__(16) __nv_bfloat16 g_ah[(size_t)M_TOT * K_DIM];
__device__ __align__(16) __nv_bfloat16 g_al[(size_t)M_TOT * K_DIM];
__device__ __align__(16) __nv_bfloat16 g_Qh[(size_t)BH_ * N_ * 64];
__device__ __align__(16) __nv_bfloat16 g_Ql[(size_t)BH_ * N_ * 64];
__device__ __align__(16) __nv_bfloat16 g_Kh[(size_t)BH_ * N_ * 64];
__device__ __align__(16) __nv_bfloat16 g_Kl[(size_t)BH_ * N_ * 64];
__device__ __align__(16) __nv_bfloat16 g_Vh[(size_t)BH_ * 64 * N_];
__device__ __align__(16) __nv_bfloat16 g_Vl[(size_t)BH_ * 64 * N_];

// ---------------------------------------------------------------------------
// mma.sync / ldmatrix / cp.async helpers
// ---------------------------------------------------------------------------
__device__ __forceinline__ uint32_t smem_u32(const void* p) {
    uint32_t a;
    asm("{ .reg .u64 t; cvta.to.shared.u64 t, %1; cvt.u32.u64 %0, t; }"
        : "=r"(a) : "l"(p));
    return a;
}
__device__ __forceinline__ void ldm4(uint32_t* r, uint32_t addr) {
    asm volatile("ldmatrix.sync.aligned.m8n8.x4.shared.b16 {%0,%1,%2,%3}, [%4];"
                 : "=r"(r[0]), "=r"(r[1]), "=r"(r[2]), "=r"(r[3]) : "r"(addr));
}
__device__ __forceinline__ void mma_bf16(float* c, const uint32_t* a, const uint32_t* b) {
    asm volatile("mma.sync.aligned.m16n8k16.row.col.f32.bf16.bf16.f32 "
                 "{%0,%1,%2,%3}, {%4,%5,%6,%7}, {%8,%9}, {%0,%1,%2,%3};"
                 : "+f"(c[0]), "+f"(c[1]), "+f"(c[2]), "+f"(c[3])
                 : "r"(a[0]), "r"(a[1]), "r"(a[2]), "r"(a[3]),
                   "r"(b[0]), "r"(b[1]));
}
__device__ __forceinline__ void cp16(uint32_t sa, const void* g) {
    asm volatile("cp.async.cg.shared.global [%0], [%1], 16;" :: "r"(sa), "l"(g));
}
__device__ __forceinline__ void cp_commit() {
    asm volatile("cp.async.commit_group;" ::: "memory");
}
__device__ __forceinline__ void cp_wait1() {
    asm volatile("cp.async.wait_group 1;" ::: "memory");
}
__device__ __forceinline__ void cp_wait0() {
    asm volatile("cp.async.wait_group 0;" ::: "memory");
}
__device__ __forceinline__ uint32_t pack2_bf16(float a, float b) {
    return ((uint32_t)__bfloat16_as_ushort(__float2bfloat16(b)) << 16) |
           (uint32_t)__bfloat16_as_ushort(__float2bfloat16(a));
}

// ---------------------------------------------------------------------------
// Weight prep (unchanged)
// ---------------------------------------------------------------------------
__global__ void split_w_kernel(const float* __restrict__ W,
                               __nv_bfloat16* __restrict__ hi,
                               __nv_bfloat16* __restrict__ lo,
                               int K, int N) {
    __shared__ float t[32][33];
    const int tx = threadIdx.x, ty = threadIdx.y;
    const int n0 = blockIdx.x * 32, k0 = blockIdx.y * 32;
#pragma unroll
    for (int j = 0; j < 4; j++) {
        const int k = k0 + ty + j * 8;
        t[ty + j * 8][tx] = W[(size_t)k * N + n0 + tx];
    }
    __syncthreads();
#pragma unroll
    for (int j = 0; j < 4; j++) {
        const int n = n0 + ty + j * 8;
        const int k = k0 + tx;
        const float w = t[tx][ty + j * 8];
        const __nv_bfloat16 h = __float2bfloat16(w);
        hi[(size_t)n * K + k] = h;
        lo[(size_t)n * K + k] = __float2bfloat16(w - __bfloat162float(h));
    }
}

// ---------------------------------------------------------------------------
// Activation split (unchanged)
// ---------------------------------------------------------------------------
__global__ void split_a_kernel(const float* __restrict__ A,
                               __nv_bfloat16* __restrict__ hi,
                               __nv_bfloat16* __restrict__ lo,
                               int total4)
{
    const int i = blockIdx.x * blockDim.x + threadIdx.x;
    if (i >= total4) return;
    const float4 v = ((const float4*)A)[i];
    const __nv_bfloat16 h0 = __float2bfloat16(v.x);
    const __nv_bfloat16 h1 = __float2bfloat16(v.y);
    const __nv_bfloat16 h2 = __float2bfloat16(v.z);
    const __nv_bfloat16 h3 = __float2bfloat16(v.w);
    uint2 hp, lp;
    hp.x = ((uint32_t)__bfloat16_as_ushort(h1) << 16) | __bfloat16_as_ushort(h0);
    hp.y = ((uint32_t)__bfloat16_as_ushort(h3) << 16) | __bfloat16_as_ushort(h2);
    lp.x = pack2_bf16(v.x - __bfloat162float(h0), v.y - __bfloat162float(h1));
    lp.y = pack2_bf16(v.z - __bfloat162float(h2), v.w - __bfloat162float(h3));
    ((uint2*)hi)[i] = hp;
    ((uint2*)lo)[i] = lp;
}

// ---------------------------------------------------------------------------
// bf16x3 HMMA GEMM, cp.async double-buffered, 2 CTAs/SM.
// ---------------------------------------------------------------------------
#define GSB 40
#define GAS (128 * GSB)
#define GSTG (4 * GAS)
#define GEMM_SMEM (2 * GSTG * 2)     // 81920 B

__global__ __launch_bounds__(256, 2) void gemm_mma_kernel(
    const __nv_bfloat16* __restrict__ Ahg, const __nv_bfloat16* __restrict__ Alg,
    const __nv_bfloat16* __restrict__ Bhg, const __nv_bfloat16* __restrict__ Blg,
    const float* __restrict__ bias, float* __restrict__ Cout,
    int M, int N, int K)
{
    extern __shared__ __nv_bfloat16 gsm[];
    const uint32_t sb = smem_u32(gsm);

    const int tid = threadIdx.x;
    const int wid = tid >> 5;
    const int l   = tid & 31;
    const int wm  = wid >> 2;
    const int wn  = wid & 3;
    const int bm  = blockIdx.y * 128;
    const int bn  = blockIdx.x * 128;

    const int a_row = l & 15;
    const int a_col = (l >> 4) * 8;
    const int b_row = (l & 7) + ((l >> 4) & 1) * 8;
    const int b_col = ((l >> 3) & 1) * 8;

    auto prefetch = [&](int kt, int st) {
#pragma unroll
        for (int i = 0; i < 8; i++) {
            const int c   = i * 256 + tid;
            const int arr = c >> 9;
            const int r   = (c >> 2) & 127;
            const int c16 = c & 3;
            const uint32_t sa = sb + 2 * (st * GSTG + arr * GAS + r * GSB + c16 * 8);
            const __nv_bfloat16* g;
            if (arr == 0)      g = Ahg + (size_t)(bm + r) * K + kt + c16 * 8;
            else if (arr == 1) g = Alg + (size_t)(bm + r) * K + kt + c16 * 8;
            else if (arr == 2) g = Bhg + (size_t)(bn + r) * K + kt + c16 * 8;
            else               g = Blg + (size_t)(bn + r) * K + kt + c16 * 8;
            cp16(sa, g);
        }
        cp_commit();
    };

    float acc[4][4][4];
#pragma unroll
    for (int i = 0; i < 4; i++)
#pragma unroll
        for (int j = 0; j < 4; j++)
#pragma unroll
            for (int t = 0; t < 4; t++) acc[i][j][t] = 0.f;

    const int nk = K / 32;
    prefetch(0, 0);

    for (int it = 0; it < nk; it++) {
        const int st = it & 1;
        if (it + 1 < nk) { prefetch((it + 1) * 32, st ^ 1); cp_wait1(); }
        else             { cp_wait0(); }
        __syncthreads();

        const uint32_t uAh = sb + 2 * (st * GSTG + 0 * GAS);
        const uint32_t uAl = sb + 2 * (st * GSTG + 1 * GAS);
        const uint32_t uBh = sb + 2 * (st * GSTG + 2 * GAS);
        const uint32_t uBl = sb + 2 * (st * GSTG + 3 * GAS);

#pragma unroll
        for (int kh = 0; kh < 2; kh++) {
            const int kc = kh * 16;
            uint32_t af[4][4], bfh[4][2], bfl[4][2];

            // Ah + Bh + Bl fragments (Bh kept persistent across passes)
#pragma unroll
            for (int ti = 0; ti < 4; ti++)
                ldm4(af[ti], uAh + 2 * ((wm * 64 + ti * 16 + a_row) * GSB + kc + a_col));
#pragma unroll
            for (int bp = 0; bp < 2; bp++) {
                uint32_t r4[4];
                ldm4(r4, uBh + 2 * ((wn * 32 + bp * 16 + b_row) * GSB + kc + b_col));
                bfh[bp * 2 + 0][0] = r4[0]; bfh[bp * 2 + 0][1] = r4[1];
                bfh[bp * 2 + 1][0] = r4[2]; bfh[bp * 2 + 1][1] = r4[3];
            }
#pragma unroll
            for (int bp = 0; bp < 2; bp++) {
                uint32_t r4[4];
                ldm4(r4, uBl + 2 * ((wn * 32 + bp * 16 + b_row) * GSB + kc + b_col));
                bfl[bp * 2 + 0][0] = r4[0]; bfl[bp * 2 + 0][1] = r4[1];
                bfl[bp * 2 + 1][0] = r4[2]; bfl[bp * 2 + 1][1] = r4[3];
            }

            // Pass 1: Ah * Bh
#pragma unroll
            for (int ti = 0; ti < 4; ti++)
#pragma unroll
                for (int nj = 0; nj < 4; nj++)
                    mma_bf16(acc[ti][nj], af[ti], bfh[nj]);
            // Pass 2: Ah * Bl
#pragma unroll
            for (int ti = 0; ti < 4; ti++)
#pragma unroll
                for (int nj = 0; nj < 4; nj++)
                    mma_bf16(acc[ti][nj], af[ti], bfl[nj]);
            // Pass 3: Al * Bh (overwrite af)
#pragma unroll
            for (int ti = 0; ti < 4; ti++)
                ldm4(af[ti], uAl + 2 * ((wm * 64 + ti * 16 + a_row) * GSB + kc + a_col));
#pragma unroll
            for (int ti = 0; ti < 4; ti++)
#pragma unroll
                for (int nj = 0; nj < 4; nj++)
                    mma_bf16(acc[ti][nj], af[ti], bfh[nj]);
        }
        __syncthreads();
    }

    const int row_in = l >> 2;
    const int col_in = (l & 3) * 2;
#pragma unroll
    for (int ti = 0; ti < 4; ti++) {
#pragma unroll
        for (int nj = 0; nj < 4; nj++) {
            const int col = bn + wn * 32 + nj * 8 + col_in;
            const float b0 = bias[col], b1 = bias[col + 1];
            const int r0 = bm + wm * 64 + ti * 16 + row_in;
            float2 v0 = { acc[ti][nj][0] + b0, acc[ti][nj][1] + b1 };
            float2 v1 = { acc[ti][nj][2] + b0, acc[ti][nj][3] + b1 };
            *(float2*)(Cout + (size_t)r0 * N + col) = v0;
            *(float2*)(Cout + (size_t)(r0 + 8) * N + col) = v1;
        }
    }
}

// ---------------------------------------------------------------------------
// RoPE + scale(Q) + hi/lo split of Q,K (unchanged)
// ---------------------------------------------------------------------------
__global__ void rope_split_kernel(const float* __restrict__ qkv,
                                  const int* __restrict__ ph,
                                  const int* __restrict__ pw,
                                  __nv_bfloat16* __restrict__ Qh,
                                  __nv_bfloat16* __restrict__ Ql,
                                  __nv_bfloat16* __restrict__ Kh,
                                  __nv_bfloat16* __restrict__ Kl)
{
    const int idx = blockIdx.x * blockDim.x + threadIdx.x;
    const int j    = idx & 15;
    const int half = (idx >> 4) & 1;
    const int s    = (idx >> 5) & 1;
    const int head = (idx >> 6) % 12;
    const int row  = idx / 768;
    if (row >= M_TOT) return;

    const float pos = (float)(half ? pw[row] : ph[row]);
    const size_t base = (size_t)row * QKV_N + s * 768 + head * 64 + half * 32;
    const float t0 = qkv[base + j];
    const float t1 = qkv[base + j + 16];

    const float L = 9.210340371976184f / 16.0f;
    const int k0 = j >> 1;
    const float f0 = pos * expf(-L * (float)k0);
    const float f1 = pos * expf(-L * (float)(k0 + 8));
    float c0, s0, c1, s1;
    sincosf(f0, &s0, &c0);
    sincosf(f1, &s1, &c1);

    float o0 = t0 * c0 - t1 * s0;
    float o1 = t1 * c1 + t0 * s1;
    if (s == 0) { o0 *= 0.125f; o1 *= 0.125f; }

    const int b = row >> 10, n = row & 1023;
    const size_t ob = ((size_t)(b * 12 + head) * N_ + n) * 64 + half * 32 + j;
    __nv_bfloat16* hi = s ? Kh : Qh;
    __nv_bfloat16* lo = s ? Kl : Ql;
    const __nv_bfloat16 h0 = __float2bfloat16(o0);
    const __nv_bfloat16 h1 = __float2bfloat16(o1);
    hi[ob]      = h0;
    hi[ob + 16] = h1;
    lo[ob]      = __float2bfloat16(o0 - __bfloat162float(h0));
    lo[ob + 16] = __float2bfloat16(o1 - __bfloat162float(h1));
}

// ---------------------------------------------------------------------------
// V transpose + split (unchanged)
// ---------------------------------------------------------------------------
__global__ void v_split_kernel(const float* __restrict__ qkv,
                               __nv_bfloat16* __restrict__ Vh,
                               __nv_bfloat16* __restrict__ Vl)
{
    __shared__ float ts[64][65];
    const int tid = threadIdx.x;
    const int n0 = blockIdx.x * 64;
    const int h  = blockIdx.y;
    const int b  = blockIdx.z;
    const int bh = b * 12 + h;

#pragma unroll
    for (int i = 0; i < 16; i++) {
        const int li = i * 256 + tid;
        const int r = li >> 6, c = li & 63;
        ts[r][c] = qkv[(size_t)(b * N_ + n0 + r) * QKV_N + 1536 + h * 64 + c];
    }
    __syncthreads();
#pragma unroll
    for (int i = 0; i < 8; i++) {
        const int li = i * 256 + tid;
        const int d = li >> 5, c2 = (li & 31) * 2;
        const float v0 = ts[c2][d], v1 = ts[c2 + 1][d];
        const __nv_bfloat16 h0 = __float2bfloat16(v0);
        const __nv_bfloat16 h1 = __float2bfloat16(v1);
        const size_t ob = ((size_t)bh * 64 + d) * N_ + n0 + c2;
        *(uint32_t*)&Vh[ob] =
            ((uint32_t)__bfloat16_as_ushort(h1) << 16) | __bfloat16_as_ushort(h0);
        *(uint32_t*)&Vl[ob] =
            pack2_bf16(v0 - __bfloat162float(h0), v1 - __bfloat162float(h1));
    }
}

// ---------------------------------------------------------------------------
// Tensor-core flash attention (unchanged)
// ---------------------------------------------------------------------------
#define ATS 72
#define AAS (64 * ATS)
#define ATT_SMEM (2 * 4 * AAS * 2)

__global__ __launch_bounds__(256, 1) void attn_mma_kernel(
    const __nv_bfloat16* __restrict__ Qh, const __nv_bfloat16* __restrict__ Ql,
    const __nv_bfloat16* __restrict__ Kh, const __nv_bfloat16* __restrict__ Kl,
    const __nv_bfloat16* __restrict__ Vh, const __nv_bfloat16* __restrict__ Vl,
    float* __restrict__ out)
{
    extern __shared__ __nv_bfloat16 smh[];
    const uint32_t sb = smem_u32(smh);

    const int tid = threadIdx.x;
    const int wid = tid >> 5;
    const int l   = tid & 31;
    const int qb  = blockIdx.x;
    const int h   = blockIdx.y;
    const int b   = blockIdx.z;
    const int bh  = b * H_ + h;
    const int q0  = qb * 128;
    const int wrow = wid * 16;

    const int b_row = (l & 7) + ((l >> 4) & 1) * 8;
    const int b_col = ((l >> 3) & 1) * 8;

    const uint32_t* q32h = (const uint32_t*)(Qh + ((size_t)bh * N_ + q0) * 64);
    const uint32_t* q32l = (const uint32_t*)(Ql + ((size_t)bh * N_ + q0) * 64);
    uint32_t qfh[4][4], qfl[4][4];
    {
        const int r0 = wrow + (l >> 2);
        const int cb = (l & 3) * 2;
#pragma unroll
        for (int t = 0; t < 4; t++) {
            const int c0 = t * 16 + cb;
            qfh[t][0] = q32h[(r0 * 64 + c0) >> 1];
            qfh[t][1] = q32h[((r0 + 8) * 64 + c0) >> 1];
            qfh[t][2] = q32h[(r0 * 64 + c0 + 8) >> 1];
            qfh[t][3] = q32h[((r0 + 8) * 64 + c0 + 8) >> 1];
            qfl[t][0] = q32l[(r0 * 64 + c0) >> 1];
            qfl[t][1] = q32l[((r0 + 8) * 64 + c0) >> 1];
            qfl[t][2] = q32l[(r0 * 64 + c0 + 8) >> 1];
            qfl[t][3] = q32l[((r0 + 8) * 64 + c0 + 8) >> 1];
        }
    }

    const __nv_bfloat16* gKh = Kh + (size_t)bh * N_ * 64;
    const __nv_bfloat16* gKl = Kl + (size_t)bh * N_ * 64;
    const __nv_bfloat16* gVh = Vh + (size_t)bh * 64 * N_;
    const __nv_bfloat16* gVl = Vl + (size_t)bh * 64 * N_;

    auto prefetch = [&](int kb, int st) {
#pragma unroll
        for (int i = 0; i < 8; i++) {
            const int c   = i * 256 + tid;
            const int arr = c >> 9;
            const int r   = (c >> 3) & 63;
            const int c16 = c & 7;
            const uint32_t sa = sb + 2 * ((st * 4 + arr) * AAS + r * ATS + c16 * 8);
            const __nv_bfloat16* g;
            if (arr == 0)      g = gKh + (size_t)(kb * 64 + r) * 64 + c16 * 8;
            else if (arr == 1) g = gKl + (size_t)(kb * 64 + r) * 64 + c16 * 8;
            else if (arr == 2) g = gVh + (size_t)r * N_ + kb * 64 + c16 * 8;
            else               g = gVl + (size_t)r * N_ + kb * 64 + c16 * 8;
            cp16(sa, g);
        }
        cp_commit();
    };

    float acc[8][4];
    float mrun[2] = { -1e30f, -1e30f }, lrun[2] = { 0.f, 0.f };
#pragma unroll
    for (int j = 0; j < 8; j++)
#pragma unroll
        for (int t = 0; t < 4; t++) acc[j][t] = 0.f;

    prefetch(0, 0);

    for (int kb = 0; kb < 16; kb++) {
        const int st = kb & 1;
        if (kb + 1 < 16) { prefetch(kb + 1, st ^ 1); cp_wait1(); }
        else             { cp_wait0(); }
        __syncthreads();

        const uint32_t uKh = sb + 2 * ((st * 4 + 0) * AAS);
        const uint32_t uKl = sb + 2 * ((st * 4 + 1) * AAS);
        const uint32_t uVh = sb + 2 * ((st * 4 + 2) * AAS);
        const uint32_t uVl = sb + 2 * ((st * 4 + 3) * AAS);

        float sv[8][4];
#pragma unroll
        for (int j = 0; j < 8; j++)
#pragma unroll
            for (int t = 0; t < 4; t++) sv[j][t] = 0.f;

#pragma unroll
        for (int t = 0; t < 4; t++) {
#pragma unroll
            for (int bp = 0; bp < 4; bp++) {
                uint32_t rh[4], rl[4];
                ldm4(rh, uKh + 2 * ((bp * 16 + b_row) * ATS + t * 16 + b_col));
                ldm4(rl, uKl + 2 * ((bp * 16 + b_row) * ATS + t * 16 + b_col));
                mma_bf16(sv[2 * bp],     qfh[t], rh);
                mma_bf16(sv[2 * bp + 1], qfh[t], rh + 2);
                mma_bf16(sv[2 * bp],     qfl[t], rh);
                mma_bf16(sv[2 * bp + 1], qfl[t], rh + 2);
                mma_bf16(sv[2 * bp],     qfh[t], rl);
                mma_bf16(sv[2 * bp + 1], qfh[t], rl + 2);
            }
        }

#pragma unroll
        for (int i = 0; i < 2; i++) {
            float mx = -1e30f;
#pragma unroll
            for (int j = 0; j < 8; j++)
                mx = fmaxf(mx, fmaxf(sv[j][2 * i], sv[j][2 * i + 1]));
            mx = fmaxf(mx, __shfl_xor_sync(0xffffffffu, mx, 1));
            mx = fmaxf(mx, __shfl_xor_sync(0xffffffffu, mx, 2));
            const float mnew = fmaxf(mrun[i], mx);
            const float corr = __expf(mrun[i] - mnew);
            float rs = 0.f;
#pragma unroll
            for (int j = 0; j < 8; j++) {
                const float p0 = __expf(sv[j][2 * i] - mnew);
                const float p1 = __expf(sv[j][2 * i + 1] - mnew);
                sv[j][2 * i] = p0; sv[j][2 * i + 1] = p1;
                rs += p0 + p1;
            }
            rs += __shfl_xor_sync(0xffffffffu, rs, 1);
            rs += __shfl_xor_sync(0xffffffffu, rs, 2);
            lrun[i] = lrun[i] * corr + rs;
#pragma unroll
            for (int j = 0; j < 8; j++) {
                acc[j][2 * i] *= corr;
                acc[j][2 * i + 1] *= corr;
            }
            mrun[i] = mnew;
        }

        uint32_t pfh[4][4], pfl[4][4];
#pragma unroll
        for (int t = 0; t < 4; t++) {
#pragma unroll
            for (int q = 0; q < 4; q++) {
                const int j = 2 * t + (q >> 1);
                const float p0 = sv[j][(q & 1) * 2];
                const float p1 = sv[j][(q & 1) * 2 + 1];
                const __nv_bfloat16 h0 = __float2bfloat16(p0);
                const __nv_bfloat16 h1 = __float2bfloat16(p1);
                pfh[t][q] = ((uint32_t)__bfloat16_as_ushort(h1) << 16) |
                            __bfloat16_as_ushort(h0);
                pfl[t][q] = pack2_bf16(p0 - __bfloat162float(h0),
                                       p1 - __bfloat162float(h1));
            }
        }

#pragma unroll
        for (int t = 0; t < 4; t++) {
#pragma unroll
            for (int bp = 0; bp < 4; bp++) {
                uint32_t rh[4], rl[4];
                ldm4(rh, uVh + 2 * ((bp * 16 + b_row) * ATS + t * 16 + b_col));
                ldm4(rl, uVl + 2 * ((bp * 16 + b_row) * ATS + t * 16 + b_col));
                mma_bf16(acc[2 * bp],     pfh[t], rh);
                mma_bf16(acc[2 * bp + 1], pfh[t], rh + 2);
                mma_bf16(acc[2 * bp],     pfl[t], rh);
                mma_bf16(acc[2 * bp + 1], pfl[t], rh + 2);
                mma_bf16(acc[2 * bp],     pfh[t], rl);
                mma_bf16(acc[2 * bp + 1], pfh[t], rl + 2);
            }
        }
        __syncthreads();
    }

    const float il0 = 1.f / lrun[0];
    const float il1 = 1.f / lrun[1];
    const int r0 = q0 + wrow + (l >> 2);
    const int cb = h * 64 + (l & 3) * 2;
#pragma unroll
    for (int j = 0; j < 8; j++) {
        float2 v0 = { acc[j][0] * il0, acc[j][1] * il0 };
        float2 v1 = { acc[j][2] * il1, acc[j][3] * il1 };
        *(float2*)(out + (size_t)(b * N_ + r0) * C_ + cb + j * 8) = v0;
        *(float2*)(out + (size_t)(b * N_ + r0 + 8) * C_ + cb + j * 8) = v1;
    }
}

// ---------------------------------------------------------------------------
extern "C" void kernel_launch(void* const* d_in, const int* in_sizes, int n_in,
                              void* d_out, int out_size)
{
    const float* x     = (const float*)d_in[0];
    const float* Wqkv  = (const float*)d_in[1];
    const float* bqkv  = (const float*)d_in[2];
    const float* Wproj = (const float*)d_in[3];
    const float* bproj = (const float*)d_in[4];
    const int*   ph    = (const int*)d_in[5];
    const int*   pw    = (const int*)d_in[6];
    float*       out   = (float*)d_out;

    float *qkv = nullptr, *attn = nullptr;
    __nv_bfloat16 *wqh, *wql, *wph, *wpl, *ah, *al;
    __nv_bfloat16 *aQh, *aQl, *aKh, *aKl, *aVh, *aVl;
    cudaGetSymbolAddress((void**)&qkv,  g_qkv);
    cudaGetSymbolAddress((void**)&attn, g_attn);
    cudaGetSymbolAddress((void**)&wqh,  g_wqkv_hi);
    cudaGetSymbolAddress((void**)&wql,  g_wqkv_lo);
    cudaGetSymbolAddress((void**)&wph,  g_wproj_hi);
    cudaGetSymbolAddress((void**)&wpl,  g_wproj_lo);
    cudaGetSymbolAddress((void**)&ah,   g_ah);
    cudaGetSymbolAddress((void**)&al,   g_al);
    cudaGetSymbolAddress((void**)&aQh,  g_Qh);
    cudaGetSymbolAddress((void**)&aQl,  g_Ql);
    cudaGetSymbolAddress((void**)&aKh,  g_Kh);
    cudaGetSymbolAddress((void**)&aKl,  g_Kl);
    cudaGetSymbolAddress((void**)&aVh,  g_Vh);
    cudaGetSymbolAddress((void**)&aVl,  g_Vl);

    static bool attr_set = false;
    if (!attr_set) {
        cudaFuncSetAttribute(attn_mma_kernel,
                             cudaFuncAttributeMaxDynamicSharedMemorySize, ATT_SMEM);
        cudaFuncSetAttribute(gemm_mma_kernel,
                             cudaFuncAttributeMaxDynamicSharedMemorySize, GEMM_SMEM);
        attr_set = true;
    }

    const int a_total4 = M_TOT * K_DIM / 4;

    // 0) Weight transpose + bf16 split
    split_w_kernel<<<dim3(QKV_N / 32, K_DIM / 32), dim3(32, 8)>>>(Wqkv, wqh, wql, K_DIM, QKV_N);
    split_w_kernel<<<dim3(C_ / 32, K_DIM / 32), dim3(32, 8)>>>(Wproj, wph, wpl, K_DIM, C_);

    // 1) QKV projection
    split_a_kernel<<<(a_total4 + 255) / 256, 256>>>(x, ah, al, a_total4);
    gemm_mma_kernel<<<dim3(QKV_N / 128, M_TOT / 128), 256, GEMM_SMEM>>>(
        ah, al, wqh, wql, bqkv, qkv, M_TOT, QKV_N, K_DIM);

    // 2) RoPE + splits
    {
        const int total = M_TOT * 12 * 2 * 2 * 16;
        rope_split_kernel<<<(total + 255) / 256, 256>>>(qkv, ph, pw, aQh, aQl, aKh, aKl);
        v_split_kernel<<<dim3(N_ / 64, H_, B_), 256>>>(qkv, aVh, aVl);
    }

    // 3) Tensor-core flash attention
    attn_mma_kernel<<<dim3(N_ / 128, H_, B_), 256, ATT_SMEM>>>(
        aQh, aQl, aKh, aKl, aVh, aVl, attn);

    // 4) Output projection
    split_a_kernel<<<(a_total4 + 255) / 256, 256>>>(attn, ah, al, a_total4);
    gemm_mma_kernel<<<dim3(C_ / 128, M_TOT / 128), 256, GEMM_SMEM>>>(
        ah, al, wph, wpl, bproj, out, M_TOT, C_, K_DIM);
}

// round 10
// speedup vs baseline: 2.4633x; 1.0255x over previous
#include <cuda_runtime.h>
#include <cuda_bf16.h>
#include <cstdint>

#define B_    16
#define N_    1024
#define C_    768
#define H_    12
#define M_TOT (B_ * N_)        // 16384
#define QKV_N (3 * C_)         // 2304
#define K_DIM 768
#define BH_   (B_ * H_)        // 192

// ---------------------------------------------------------------------------
// Scratch (__device__ globals only)
// ---------------------------------------------------------------------------
__device__ __align__(16) float g_qkv[(size_t)M_TOT * QKV_N];   // only V third used
__device__ __align__(16) __nv_bfloat16 g_wqkv_hi[(size_t)QKV_N * K_DIM];
__device__ __align__(16) __nv_bfloat16 g_wqkv_lo[(size_t)QKV_N * K_DIM];
__device__ __align__(16) __nv_bfloat16 g_wproj_hi[(size_t)C_ * K_DIM];
__device__ __align__(16) __nv_bfloat16 g_wproj_lo[(size_t)C_ * K_DIM];
__device__ __align__(16) __nv_bfloat16 g_ah[(size_t)M_TOT * K_DIM];  // x split, then attn-out split
__device__ __align__(16) __nv_bfloat16 g_al[(size_t)M_TOT * K_DIM];
__device__ __align__(16) __nv_bfloat16 g_Qh[(size_t)BH_ * N_ * 64];
__device__ __align__(16) __nv_bfloat16 g_Ql[(size_t)BH_ * N_ * 64];
__device__ __align__(16) __nv_bfloat16 g_Kh[(size_t)BH_ * N_ * 64];
__device__ __align__(16) __nv_bfloat16 g_Kl[(size_t)BH_ * N_ * 64];
__device__ __align__(16) __nv_bfloat16 g_Vh[(size_t)BH_ * 64 * N_];
__device__ __align__(16) __nv_bfloat16 g_Vl[(size_t)BH_ * 64 * N_];

// ---------------------------------------------------------------------------
// helpers
// ---------------------------------------------------------------------------
__device__ __forceinline__ uint32_t smem_u32(const void* p) {
    uint32_t a;
    asm("{ .reg .u64 t; cvta.to.shared.u64 t, %1; cvt.u32.u64 %0, t; }"
        : "=r"(a) : "l"(p));
    return a;
}
__device__ __forceinline__ void ldm4(uint32_t* r, uint32_t addr) {
    asm volatile("ldmatrix.sync.aligned.m8n8.x4.shared.b16 {%0,%1,%2,%3}, [%4];"
                 : "=r"(r[0]), "=r"(r[1]), "=r"(r[2]), "=r"(r[3]) : "r"(addr));
}
__device__ __forceinline__ void mma_bf16(float* c, const uint32_t* a, const uint32_t* b) {
    asm volatile("mma.sync.aligned.m16n8k16.row.col.f32.bf16.bf16.f32 "
                 "{%0,%1,%2,%3}, {%4,%5,%6,%7}, {%8,%9}, {%0,%1,%2,%3};"
                 : "+f"(c[0]), "+f"(c[1]), "+f"(c[2]), "+f"(c[3])
                 : "r"(a[0]), "r"(a[1]), "r"(a[2]), "r"(a[3]),
                   "r"(b[0]), "r"(b[1]));
}
__device__ __forceinline__ void cp16(uint32_t sa, const void* g) {
    asm volatile("cp.async.cg.shared.global [%0], [%1], 16;" :: "r"(sa), "l"(g));
}
__device__ __forceinline__ void cp_commit() {
    asm volatile("cp.async.commit_group;" ::: "memory");
}
__device__ __forceinline__ void cp_wait1() {
    asm volatile("cp.async.wait_group 1;" ::: "memory");
}
__device__ __forceinline__ void cp_wait0() {
    asm volatile("cp.async.wait_group 0;" ::: "memory");
}
__device__ __forceinline__ uint32_t pack2_bf16(float a, float b) {
    return ((uint32_t)__bfloat16_as_ushort(__float2bfloat16(b)) << 16) |
           (uint32_t)__bfloat16_as_ushort(__float2bfloat16(a));
}

// ---------------------------------------------------------------------------
// Weight prep: W [K,N] fp32 -> hi/lo bf16 [N,K]
// ---------------------------------------------------------------------------
__global__ void split_w_kernel(const float* __restrict__ W,
                               __nv_bfloat16* __restrict__ hi,
                               __nv_bfloat16* __restrict__ lo,
                               int K, int N) {
    __shared__ float t[32][33];
    const int tx = threadIdx.x, ty = threadIdx.y;
    const int n0 = blockIdx.x * 32, k0 = blockIdx.y * 32;
#pragma unroll
    for (int j = 0; j < 4; j++) {
        const int k = k0 + ty + j * 8;
        t[ty + j * 8][tx] = W[(size_t)k * N + n0 + tx];
    }
    __syncthreads();
#pragma unroll
    for (int j = 0; j < 4; j++) {
        const int n = n0 + ty + j * 8;
        const int k = k0 + tx;
        const float w = t[tx][ty + j * 8];
        const __nv_bfloat16 h = __float2bfloat16(w);
        hi[(size_t)n * K + k] = h;
        lo[(size_t)n * K + k] = __float2bfloat16(w - __bfloat162float(h));
    }
}

// ---------------------------------------------------------------------------
// Activation split: A [M,K] fp32 -> hi/lo bf16
// ---------------------------------------------------------------------------
__global__ void split_a_kernel(const float* __restrict__ A,
                               __nv_bfloat16* __restrict__ hi,
                               __nv_bfloat16* __restrict__ lo,
                               int total4)
{
    const int i = blockIdx.x * blockDim.x + threadIdx.x;
    if (i >= total4) return;
    const float4 v = ((const float4*)A)[i];
    const __nv_bfloat16 h0 = __float2bfloat16(v.x);
    const __nv_bfloat16 h1 = __float2bfloat16(v.y);
    const __nv_bfloat16 h2 = __float2bfloat16(v.z);
    const __nv_bfloat16 h3 = __float2bfloat16(v.w);
    uint2 hp, lp;
    hp.x = ((uint32_t)__bfloat16_as_ushort(h1) << 16) | __bfloat16_as_ushort(h0);
    hp.y = ((uint32_t)__bfloat16_as_ushort(h3) << 16) | __bfloat16_as_ushort(h2);
    lp.x = pack2_bf16(v.x - __bfloat162float(h0), v.y - __bfloat162float(h1));
    lp.y = pack2_bf16(v.z - __bfloat162float(h2), v.w - __bfloat162float(h3));
    ((uint2*)hi)[i] = hp;
    ((uint2*)lo)[i] = lp;
}

// ---------------------------------------------------------------------------
// bf16x3 HMMA GEMM, cp.async double-buffered, 2 CTAs/SM.
// MODE 0: fp32 out + bias (proj). MODE 1: QKV — V band -> fp32 Cout,
// Q/K bands -> RoPE applied in-register, bf16 hi/lo split to Qh/Ql/Kh/Kl.
// ---------------------------------------------------------------------------
#define GSB 40
#define GAS (128 * GSB)
#define GSTG (4 * GAS)
#define GEMM_SMEM (2 * GSTG * 2)     // 81920 B

template <int MODE>
__global__ __launch_bounds__(256, 2) void gemm_mma_kernel(
    const __nv_bfloat16* __restrict__ Ahg, const __nv_bfloat16* __restrict__ Alg,
    const __nv_bfloat16* __restrict__ Bhg, const __nv_bfloat16* __restrict__ Blg,
    const float* __restrict__ bias, float* __restrict__ Cout,
    __nv_bfloat16* __restrict__ Qh, __nv_bfloat16* __restrict__ Ql,
    __nv_bfloat16* __restrict__ Kh, __nv_bfloat16* __restrict__ Kl,
    int M, int N, int K)
{
    extern __shared__ __nv_bfloat16 gsm[];
    const uint32_t sb = smem_u32(gsm);

    const int tid = threadIdx.x;
    const int wid = tid >> 5;
    const int l   = tid & 31;
    const int wm  = wid >> 2;
    const int wn  = wid & 3;
    const int bm  = blockIdx.y * 128;
    const int bn  = blockIdx.x * 128;

    const int a_row = l & 15;
    const int a_col = (l >> 4) * 8;
    const int b_row = (l & 7) + ((l >> 4) & 1) * 8;
    const int b_col = ((l >> 3) & 1) * 8;

    auto prefetch = [&](int kt, int st) {
#pragma unroll
        for (int i = 0; i < 8; i++) {
            const int c   = i * 256 + tid;
            const int arr = c >> 9;
            const int r   = (c >> 2) & 127;
            const int c16 = c & 3;
            const uint32_t sa = sb + 2 * (st * GSTG + arr * GAS + r * GSB + c16 * 8);
            const __nv_bfloat16* g;
            if (arr == 0)      g = Ahg + (size_t)(bm + r) * K + kt + c16 * 8;
            else if (arr == 1) g = Alg + (size_t)(bm + r) * K + kt + c16 * 8;
            else if (arr == 2) g = Bhg + (size_t)(bn + r) * K + kt + c16 * 8;
            else               g = Blg + (size_t)(bn + r) * K + kt + c16 * 8;
            cp16(sa, g);
        }
        cp_commit();
    };

    float acc[4][4][4];
#pragma unroll
    for (int i = 0; i < 4; i++)
#pragma unroll
        for (int j = 0; j < 4; j++)
#pragma unroll
            for (int t = 0; t < 4; t++) acc[i][j][t] = 0.f;

    const int nk = K / 32;
    prefetch(0, 0);

    for (int it = 0; it < nk; it++) {
        const int st = it & 1;
        if (it + 1 < nk) { prefetch((it + 1) * 32, st ^ 1); cp_wait1(); }
        else             { cp_wait0(); }
        __syncthreads();

        const uint32_t uAh = sb + 2 * (st * GSTG + 0 * GAS);
        const uint32_t uAl = sb + 2 * (st * GSTG + 1 * GAS);
        const uint32_t uBh = sb + 2 * (st * GSTG + 2 * GAS);
        const uint32_t uBl = sb + 2 * (st * GSTG + 3 * GAS);

#pragma unroll
        for (int kh = 0; kh < 2; kh++) {
            const int kc = kh * 16;
            uint32_t af[4][4], bfh[4][2], bfl[4][2];
#pragma unroll
            for (int ti = 0; ti < 4; ti++)
                ldm4(af[ti], uAh + 2 * ((wm * 64 + ti * 16 + a_row) * GSB + kc + a_col));
#pragma unroll
            for (int bp = 0; bp < 2; bp++) {
                uint32_t r4[4];
                ldm4(r4, uBh + 2 * ((wn * 32 + bp * 16 + b_row) * GSB + kc + b_col));
                bfh[bp * 2 + 0][0] = r4[0]; bfh[bp * 2 + 0][1] = r4[1];
                bfh[bp * 2 + 1][0] = r4[2]; bfh[bp * 2 + 1][1] = r4[3];
            }
#pragma unroll
            for (int bp = 0; bp < 2; bp++) {
                uint32_t r4[4];
                ldm4(r4, uBl + 2 * ((wn * 32 + bp * 16 + b_row) * GSB + kc + b_col));
                bfl[bp * 2 + 0][0] = r4[0]; bfl[bp * 2 + 0][1] = r4[1];
                bfl[bp * 2 + 1][0] = r4[2]; bfl[bp * 2 + 1][1] = r4[3];
            }
#pragma unroll
            for (int ti = 0; ti < 4; ti++)
#pragma unroll
                for (int nj = 0; nj < 4; nj++)
                    mma_bf16(acc[ti][nj], af[ti], bfh[nj]);
#pragma unroll
            for (int ti = 0; ti < 4; ti++)
#pragma unroll
                for (int nj = 0; nj < 4; nj++)
                    mma_bf16(acc[ti][nj], af[ti], bfl[nj]);
#pragma unroll
            for (int ti = 0; ti < 4; ti++)
                ldm4(af[ti], uAl + 2 * ((wm * 64 + ti * 16 + a_row) * GSB + kc + a_col));
#pragma unroll
            for (int ti = 0; ti < 4; ti++)
#pragma unroll
                for (int nj = 0; nj < 4; nj++)
                    mma_bf16(acc[ti][nj], af[ti], bfh[nj]);
        }
        __syncthreads();
    }

    const int row_in = l >> 2;
    const int col_in = (l & 3) * 2;
    const int col0base = bn + wn * 32;

    if (MODE == 0 || col0base >= 2 * 768) {
        // plain fp32 + bias store (proj output, or V band of QKV)
#pragma unroll
        for (int ti = 0; ti < 4; ti++) {
#pragma unroll
            for (int nj = 0; nj < 4; nj++) {
                const int col = col0base + nj * 8 + col_in;
                const float b0 = bias[col], b1 = bias[col + 1];
                const int r0 = bm + wm * 64 + ti * 16 + row_in;
                float2 v0 = { acc[ti][nj][0] + b0, acc[ti][nj][1] + b1 };
                float2 v1 = { acc[ti][nj][2] + b0, acc[ti][nj][3] + b1 };
                *(float2*)(Cout + (size_t)r0 * N + col) = v0;
                *(float2*)(Cout + (size_t)(r0 + 8) * N + col) = v1;
            }
        }
    } else {
        // Q/K band: RoPE in-register + bf16 hi/lo split store
        const int s    = col0base / 768;                 // 0=Q, 1=K
        const int head = (col0base % 768) / 64;
        const int half = (col0base % 64) >> 5;           // 0=h, 1=w
        __nv_bfloat16* dh = s ? Kh : Qh;
        __nv_bfloat16* dl = s ? Kl : Ql;
        const float qs = s ? 1.0f : 0.125f;              // fold 1/sqrt(64) into Q
        const float L = 9.210340371976184f / 16.0f;      // ln(10000)/16

#pragma unroll
        for (int nj = 0; nj < 2; nj++) {
            const int jj  = nj * 8 + col_in;             // 0..14 even
            const int k0  = jj >> 1;
            const float fe0 = expf(-L * (float)k0);
            const float fe1 = expf(-L * (float)(k0 + 8));
            const int jcol = col0base + jj;
            const float bA0 = bias[jcol],      bA1 = bias[jcol + 1];
            const float bB0 = bias[jcol + 16], bB1 = bias[jcol + 17];
#pragma unroll
            for (int ti = 0; ti < 4; ti++) {
#pragma unroll
                for (int kk = 0; kk < 4; kk++) {
                    const int row = bm + wm * 64 + ti * 16 + row_in + (kk >> 1) * 8;
                    const int j   = jj + (kk & 1);
                    const float t0 = acc[ti][nj][kk]     + ((kk & 1) ? bA1 : bA0);
                    const float t1 = acc[ti][nj + 2][kk] + ((kk & 1) ? bB1 : bB0);
                    const int bb = row >> 10, n = row & 1023;
                    const float pos = (float)(half ? (n & 31) : (n >> 5));
                    float s0, c0, s1, c1;
                    sincosf(pos * fe0, &s0, &c0);
                    sincosf(pos * fe1, &s1, &c1);
                    const float o0 = (t0 * c0 - t1 * s0) * qs;
                    const float o1 = (t1 * c1 + t0 * s1) * qs;
                    const size_t ob = ((size_t)(bb * 12 + head) * N_ + n) * 64
                                      + half * 32 + j;
                    const __nv_bfloat16 h0 = __float2bfloat16(o0);
                    const __nv_bfloat16 h1 = __float2bfloat16(o1);
                    dh[ob]      = h0;
                    dh[ob + 16] = h1;
                    dl[ob]      = __float2bfloat16(o0 - __bfloat162float(h0));
                    dl[ob + 16] = __float2bfloat16(o1 - __bfloat162float(h1));
                }
            }
        }
    }
}

// ---------------------------------------------------------------------------
// V transpose + split (reads V third of g_qkv)
// ---------------------------------------------------------------------------
__global__ void v_split_kernel(const float* __restrict__ qkv,
                               __nv_bfloat16* __restrict__ Vh,
                               __nv_bfloat16* __restrict__ Vl)
{
    __shared__ float ts[64][65];
    const int tid = threadIdx.x;
    const int n0 = blockIdx.x * 64;
    const int h  = blockIdx.y;
    const int b  = blockIdx.z;
    const int bh = b * 12 + h;

#pragma unroll
    for (int i = 0; i < 16; i++) {
        const int li = i * 256 + tid;
        const int r = li >> 6, c = li & 63;
        ts[r][c] = qkv[(size_t)(b * N_ + n0 + r) * QKV_N + 1536 + h * 64 + c];
    }
    __syncthreads();
#pragma unroll
    for (int i = 0; i < 8; i++) {
        const int li = i * 256 + tid;
        const int d = li >> 5, c2 = (li & 31) * 2;
        const float v0 = ts[c2][d], v1 = ts[c2 + 1][d];
        const __nv_bfloat16 h0 = __float2bfloat16(v0);
        const __nv_bfloat16 h1 = __float2bfloat16(v1);
        const size_t ob = ((size_t)bh * 64 + d) * N_ + n0 + c2;
        *(uint32_t*)&Vh[ob] =
            ((uint32_t)__bfloat16_as_ushort(h1) << 16) | __bfloat16_as_ushort(h0);
        *(uint32_t*)&Vl[ob] =
            pack2_bf16(v0 - __bfloat162float(h0), v1 - __bfloat162float(h1));
    }
}

// ---------------------------------------------------------------------------
// Tensor-core flash attention (bf16x3), 2 CTAs/SM, split-output epilogue.
// ---------------------------------------------------------------------------
#define ATS 72
#define AAS (64 * ATS)
#define ATT_SMEM (2 * 4 * AAS * 2)   // 73728 B

__global__ __launch_bounds__(256, 2) void attn_mma_kernel(
    const __nv_bfloat16* __restrict__ Qh, const __nv_bfloat16* __restrict__ Ql,
    const __nv_bfloat16* __restrict__ Kh, const __nv_bfloat16* __restrict__ Kl,
    const __nv_bfloat16* __restrict__ Vh, const __nv_bfloat16* __restrict__ Vl,
    __nv_bfloat16* __restrict__ oh, __nv_bfloat16* __restrict__ ol)
{
    extern __shared__ __nv_bfloat16 smh[];
    const uint32_t sb = smem_u32(smh);

    const int tid = threadIdx.x;
    const int wid = tid >> 5;
    const int l   = tid & 31;
    const int qb  = blockIdx.x;
    const int h   = blockIdx.y;
    const int b   = blockIdx.z;
    const int bh  = b * H_ + h;
    const int q0  = qb * 128;
    const int wrow = wid * 16;

    const int b_row = (l & 7) + ((l >> 4) & 1) * 8;
    const int b_col = ((l >> 3) & 1) * 8;

    const uint32_t* q32h = (const uint32_t*)(Qh + ((size_t)bh * N_ + q0) * 64);
    const uint32_t* q32l = (const uint32_t*)(Ql + ((size_t)bh * N_ + q0) * 64);
    uint32_t qfh[4][4], qfl[4][4];
    {
        const int r0 = wrow + (l >> 2);
        const int cb = (l & 3) * 2;
#pragma unroll
        for (int t = 0; t < 4; t++) {
            const int c0 = t * 16 + cb;
            qfh[t][0] = q32h[(r0 * 64 + c0) >> 1];
            qfh[t][1] = q32h[((r0 + 8) * 64 + c0) >> 1];
            qfh[t][2] = q32h[(r0 * 64 + c0 + 8) >> 1];
            qfh[t][3] = q32h[((r0 + 8) * 64 + c0 + 8) >> 1];
            qfl[t][0] = q32l[(r0 * 64 + c0) >> 1];
            qfl[t][1] = q32l[((r0 + 8) * 64 + c0) >> 1];
            qfl[t][2] = q32l[(r0 * 64 + c0 + 8) >> 1];
            qfl[t][3] = q32l[((r0 + 8) * 64 + c0 + 8) >> 1];
        }
    }

    const __nv_bfloat16* gKh = Kh + (size_t)bh * N_ * 64;
    const __nv_bfloat16* gKl = Kl + (size_t)bh * N_ * 64;
    const __nv_bfloat16* gVh = Vh + (size_t)bh * 64 * N_;
    const __nv_bfloat16* gVl = Vl + (size_t)bh * 64 * N_;

    auto prefetch = [&](int kb, int st) {
#pragma unroll
        for (int i = 0; i < 8; i++) {
            const int c   = i * 256 + tid;
            const int arr = c >> 9;
            const int r   = (c >> 3) & 63;
            const int c16 = c & 7;
            const uint32_t sa = sb + 2 * ((st * 4 + arr) * AAS + r * ATS + c16 * 8);
            const __nv_bfloat16* g;
            if (arr == 0)      g = gKh + (size_t)(kb * 64 + r) * 64 + c16 * 8;
            else if (arr == 1) g = gKl + (size_t)(kb * 64 + r) * 64 + c16 * 8;
            else if (arr == 2) g = gVh + (size_t)r * N_ + kb * 64 + c16 * 8;
            else               g = gVl + (size_t)r * N_ + kb * 64 + c16 * 8;
            cp16(sa, g);
        }
        cp_commit();
    };

    float acc[8][4];
    float mrun[2] = { -1e30f, -1e30f }, lrun[2] = { 0.f, 0.f };
#pragma unroll
    for (int j = 0; j < 8; j++)
#pragma unroll
        for (int t = 0; t < 4; t++) acc[j][t] = 0.f;

    prefetch(0, 0);

    for (int kb = 0; kb < 16; kb++) {
        const int st = kb & 1;
        if (kb + 1 < 16) { prefetch(kb + 1, st ^ 1); cp_wait1(); }
        else             { cp_wait0(); }
        __syncthreads();

        const uint32_t uKh = sb + 2 * ((st * 4 + 0) * AAS);
        const uint32_t uKl = sb + 2 * ((st * 4 + 1) * AAS);
        const uint32_t uVh = sb + 2 * ((st * 4 + 2) * AAS);
        const uint32_t uVl = sb + 2 * ((st * 4 + 3) * AAS);

        float sv[8][4];
#pragma unroll
        for (int j = 0; j < 8; j++)
#pragma unroll
            for (int t = 0; t < 4; t++) sv[j][t] = 0.f;

#pragma unroll
        for (int t = 0; t < 4; t++) {
#pragma unroll
            for (int bp = 0; bp < 4; bp++) {
                uint32_t rh[4], rl[4];
                ldm4(rh, uKh + 2 * ((bp * 16 + b_row) * ATS + t * 16 + b_col));
                ldm4(rl, uKl + 2 * ((bp * 16 + b_row) * ATS + t * 16 + b_col));
                mma_bf16(sv[2 * bp],     qfh[t], rh);
                mma_bf16(sv[2 * bp + 1], qfh[t], rh + 2);
                mma_bf16(sv[2 * bp],     qfl[t], rh);
                mma_bf16(sv[2 * bp + 1], qfl[t], rh + 2);
                mma_bf16(sv[2 * bp],     qfh[t], rl);
                mma_bf16(sv[2 * bp + 1], qfh[t], rl + 2);
            }
        }

#pragma unroll
        for (int i = 0; i < 2; i++) {
            float mx = -1e30f;
#pragma unroll
            for (int j = 0; j < 8; j++)
                mx = fmaxf(mx, fmaxf(sv[j][2 * i], sv[j][2 * i + 1]));
            mx = fmaxf(mx, __shfl_xor_sync(0xffffffffu, mx, 1));
            mx = fmaxf(mx, __shfl_xor_sync(0xffffffffu, mx, 2));
            const float mnew = fmaxf(mrun[i], mx);
            const float corr = __expf(mrun[i] - mnew);
            float rs = 0.f;
#pragma unroll
            for (int j = 0; j < 8; j++) {
                const float p0 = __expf(sv[j][2 * i] - mnew);
                const float p1 = __expf(sv[j][2 * i + 1] - mnew);
                sv[j][2 * i] = p0; sv[j][2 * i + 1] = p1;
                rs += p0 + p1;
            }
            rs += __shfl_xor_sync(0xffffffffu, rs, 1);
            rs += __shfl_xor_sync(0xffffffffu, rs, 2);
            lrun[i] = lrun[i] * corr + rs;
#pragma unroll
            for (int j = 0; j < 8; j++) {
                acc[j][2 * i] *= corr;
                acc[j][2 * i + 1] *= corr;
            }
            mrun[i] = mnew;
        }

        uint32_t pfh[4][4], pfl[4][4];
#pragma unroll
        for (int t = 0; t < 4; t++) {
#pragma unroll
            for (int q = 0; q < 4; q++) {
                const int j = 2 * t + (q >> 1);
                const float p0 = sv[j][(q & 1) * 2];
                const float p1 = sv[j][(q & 1) * 2 + 1];
                const __nv_bfloat16 h0 = __float2bfloat16(p0);
                const __nv_bfloat16 h1 = __float2bfloat16(p1);
                pfh[t][q] = ((uint32_t)__bfloat16_as_ushort(h1) << 16) |
                            __bfloat16_as_ushort(h0);
                pfl[t][q] = pack2_bf16(p0 - __bfloat162float(h0),
                                       p1 - __bfloat162float(h1));
            }
        }

#pragma unroll
        for (int t = 0; t < 4; t++) {
#pragma unroll
            for (int bp = 0; bp < 4; bp++) {
                uint32_t rh[4], rl[4];
                ldm4(rh, uVh + 2 * ((bp * 16 + b_row) * ATS + t * 16 + b_col));
                ldm4(rl, uVl + 2 * ((bp * 16 + b_row) * ATS + t * 16 + b_col));
                mma_bf16(acc[2 * bp],     pfh[t], rh);
                mma_bf16(acc[2 * bp + 1], pfh[t], rh + 2);
                mma_bf16(acc[2 * bp],     pfl[t], rh);
                mma_bf16(acc[2 * bp + 1], pfl[t], rh + 2);
                mma_bf16(acc[2 * bp],     pfh[t], rl);
                mma_bf16(acc[2 * bp + 1], pfh[t], rl + 2);
            }
        }
        __syncthreads();
    }

    // normalize + bf16 hi/lo split store (proj A operand)
    const float il0 = 1.f / lrun[0];
    const float il1 = 1.f / lrun[1];
    const int r0 = q0 + wrow + (l >> 2);
    const int cb = h * 64 + (l & 3) * 2;
#pragma unroll
    for (int j = 0; j < 8; j++) {
        const float a0 = acc[j][0] * il0, a1 = acc[j][1] * il0;
        const float a2 = acc[j][2] * il1, a3 = acc[j][3] * il1;
        const __nv_bfloat16 h0 = __float2bfloat16(a0);
        const __nv_bfloat16 h1 = __float2bfloat16(a1);
        const __nv_bfloat16 h2 = __float2bfloat16(a2);
        const __nv_bfloat16 h3 = __float2bfloat16(a3);
        const size_t o0 = (size_t)(b * N_ + r0) * C_ + cb + j * 8;
        const size_t o1 = (size_t)(b * N_ + r0 + 8) * C_ + cb + j * 8;
        *(uint32_t*)&oh[o0] =
            ((uint32_t)__bfloat16_as_ushort(h1) << 16) | __bfloat16_as_ushort(h0);
        *(uint32_t*)&oh[o1] =
            ((uint32_t)__bfloat16_as_ushort(h3) << 16) | __bfloat16_as_ushort(h2);
        *(uint32_t*)&ol[o0] = pack2_bf16(a0 - __bfloat162float(h0),
                                         a1 - __bfloat162float(h1));
        *(uint32_t*)&ol[o1] = pack2_bf16(a2 - __bfloat162float(h2),
                                         a3 - __bfloat162float(h3));
    }
}

// ---------------------------------------------------------------------------
extern "C" void kernel_launch(void* const* d_in, const int* in_sizes, int n_in,
                              void* d_out, int out_size)
{
    const float* x     = (const float*)d_in[0];
    const float* Wqkv  = (const float*)d_in[1];
    const float* bqkv  = (const float*)d_in[2];
    const float* Wproj = (const float*)d_in[3];
    const float* bproj = (const float*)d_in[4];
    float*       out   = (float*)d_out;

    float* qkv = nullptr;
    __nv_bfloat16 *wqh, *wql, *wph, *wpl, *ah, *al;
    __nv_bfloat16 *aQh, *aQl, *aKh, *aKl, *aVh, *aVl;
    cudaGetSymbolAddress((void**)&qkv, g_qkv);
    cudaGetSymbolAddress((void**)&wqh, g_wqkv_hi);
    cudaGetSymbolAddress((void**)&wql, g_wqkv_lo);
    cudaGetSymbolAddress((void**)&wph, g_wproj_hi);
    cudaGetSymbolAddress((void**)&wpl, g_wproj_lo);
    cudaGetSymbolAddress((void**)&ah,  g_ah);
    cudaGetSymbolAddress((void**)&al,  g_al);
    cudaGetSymbolAddress((void**)&aQh, g_Qh);
    cudaGetSymbolAddress((void**)&aQl, g_Ql);
    cudaGetSymbolAddress((void**)&aKh, g_Kh);
    cudaGetSymbolAddress((void**)&aKl, g_Kl);
    cudaGetSymbolAddress((void**)&aVh, g_Vh);
    cudaGetSymbolAddress((void**)&aVl, g_Vl);

    static bool attr_set = false;
    if (!attr_set) {
        cudaFuncSetAttribute(attn_mma_kernel,
                             cudaFuncAttributeMaxDynamicSharedMemorySize, ATT_SMEM);
        cudaFuncSetAttribute(gemm_mma_kernel<0>,
                             cudaFuncAttributeMaxDynamicSharedMemorySize, GEMM_SMEM);
        cudaFuncSetAttribute(gemm_mma_kernel<1>,
                             cudaFuncAttributeMaxDynamicSharedMemorySize, GEMM_SMEM);
        attr_set = true;
    }

    const int a_total4 = M_TOT * K_DIM / 4;

    // 0) Weight splits + x split
    split_w_kernel<<<dim3(QKV_N / 32, K_DIM / 32), dim3(32, 8)>>>(Wqkv, wqh, wql, K_DIM, QKV_N);
    split_w_kernel<<<dim3(C_ / 32, K_DIM / 32), dim3(32, 8)>>>(Wproj, wph, wpl, K_DIM, C_);
    split_a_kernel<<<(a_total4 + 255) / 256, 256>>>(x, ah, al, a_total4);

    // 1) QKV projection + fused RoPE/split epilogue (V -> g_qkv fp32)
    gemm_mma_kernel<1><<<dim3(QKV_N / 128, M_TOT / 128), 256, GEMM_SMEM>>>(
        ah, al, wqh, wql, bqkv, qkv, aQh, aQl, aKh, aKl, M_TOT, QKV_N, K_DIM);

    // 2) V transpose + split
    v_split_kernel<<<dim3(N_ / 64, H_, B_), 256>>>(qkv, aVh, aVl);

    // 3) Flash attention (writes split proj input into g_ah/g_al)
    attn_mma_kernel<<<dim3(N_ / 128, H_, B_), 256, ATT_SMEM>>>(
        aQh, aQl, aKh, aKl, aVh, aVl, ah, al);

    // 4) Output projection
    gemm_mma_kernel<0><<<dim3(C_ / 128, M_TOT / 128), 256, GEMM_SMEM>>>(
        ah, al, wph, wpl, bproj, out, nullptr, nullptr, nullptr, nullptr,
        M_TOT, C_, K_DIM);
}

// round 12
// speedup vs baseline: 2.6903x; 1.0921x over previous
#include <cuda_runtime.h>
#include <cuda_bf16.h>
#include <cstdint>

#define B_    16
#define N_    1024
#define C_    768
#define H_    12
#define M_TOT (B_ * N_)        // 16384
#define QKV_N (3 * C_)         // 2304
#define K_DIM 768
#define BH_   (B_ * H_)        // 192

// ---------------------------------------------------------------------------
// Scratch (__device__ globals only)
// ---------------------------------------------------------------------------
__device__ __align__(16) float g_qkv[(size_t)M_TOT * QKV_N];   // only V third used
__device__ __align__(16) float2 g_rope[16][32];                 // (cos,sin)[k][pos]
__device__ __align__(16) __nv_bfloat16 g_wqkv_hi[(size_t)QKV_N * K_DIM];
__device__ __align__(16) __nv_bfloat16 g_wqkv_lo[(size_t)QKV_N * K_DIM];
__device__ __align__(16) __nv_bfloat16 g_wproj_hi[(size_t)C_ * K_DIM];
__device__ __align__(16) __nv_bfloat16 g_wproj_lo[(size_t)C_ * K_DIM];
__device__ __align__(16) __nv_bfloat16 g_ah[(size_t)M_TOT * K_DIM];
__device__ __align__(16) __nv_bfloat16 g_al[(size_t)M_TOT * K_DIM];
__device__ __align__(16) __nv_bfloat16 g_Qh[(size_t)BH_ * N_ * 64];
__device__ __align__(16) __nv_bfloat16 g_Ql[(size_t)BH_ * N_ * 64];
__device__ __align__(16) __nv_bfloat16 g_Kh[(size_t)BH_ * N_ * 64];
__device__ __align__(16) __nv_bfloat16 g_Kl[(size_t)BH_ * N_ * 64];
__device__ __align__(16) __nv_bfloat16 g_Vh[(size_t)BH_ * 64 * N_];
__device__ __align__(16) __nv_bfloat16 g_Vl[(size_t)BH_ * 64 * N_];

// ---------------------------------------------------------------------------
// helpers
// ---------------------------------------------------------------------------
__device__ __forceinline__ uint32_t smem_u32(const void* p) {
    uint32_t a;
    asm("{ .reg .u64 t; cvta.to.shared.u64 t, %1; cvt.u32.u64 %0, t; }"
        : "=r"(a) : "l"(p));
    return a;
}
__device__ __forceinline__ void ldm4(uint32_t* r, uint32_t addr) {
    asm volatile("ldmatrix.sync.aligned.m8n8.x4.shared.b16 {%0,%1,%2,%3}, [%4];"
                 : "=r"(r[0]), "=r"(r[1]), "=r"(r[2]), "=r"(r[3]) : "r"(addr));
}
__device__ __forceinline__ void mma_bf16(float* c, const uint32_t* a, const uint32_t* b) {
    asm volatile("mma.sync.aligned.m16n8k16.row.col.f32.bf16.bf16.f32 "
                 "{%0,%1,%2,%3}, {%4,%5,%6,%7}, {%8,%9}, {%0,%1,%2,%3};"
                 : "+f"(c[0]), "+f"(c[1]), "+f"(c[2]), "+f"(c[3])
                 : "r"(a[0]), "r"(a[1]), "r"(a[2]), "r"(a[3]),
                   "r"(b[0]), "r"(b[1]));
}
__device__ __forceinline__ void cp16(uint32_t sa, const void* g) {
    asm volatile("cp.async.cg.shared.global [%0], [%1], 16;" :: "r"(sa), "l"(g));
}
__device__ __forceinline__ void cp_commit() {
    asm volatile("cp.async.commit_group;" ::: "memory");
}
__device__ __forceinline__ void cp_wait1() {
    asm volatile("cp.async.wait_group 1;" ::: "memory");
}
__device__ __forceinline__ void cp_wait0() {
    asm volatile("cp.async.wait_group 0;" ::: "memory");
}
__device__ __forceinline__ uint32_t pack2_bf16(float a, float b) {
    return ((uint32_t)__bfloat16_as_ushort(__float2bfloat16(b)) << 16) |
           (uint32_t)__bfloat16_as_ushort(__float2bfloat16(a));
}

// ---------------------------------------------------------------------------
// RoPE table init (bit-identical expressions to the R10 in-epilogue math)
// ---------------------------------------------------------------------------
__global__ void rope_init_kernel() {
    const int idx = threadIdx.x;           // 0..511
    const int k = idx >> 5, pos = idx & 31;
    const float L = 9.210340371976184f / 16.0f;
    const float ang = (float)pos * expf(-L * (float)k);
    float s, c;
    sincosf(ang, &s, &c);
    g_rope[k][pos] = make_float2(c, s);
}

// ---------------------------------------------------------------------------
// Weight prep: W [K,N] fp32 -> hi/lo bf16 [N,K]
// ---------------------------------------------------------------------------
__global__ void split_w_kernel(const float* __restrict__ W,
                               __nv_bfloat16* __restrict__ hi,
                               __nv_bfloat16* __restrict__ lo,
                               int K, int N) {
    __shared__ float t[32][33];
    const int tx = threadIdx.x, ty = threadIdx.y;
    const int n0 = blockIdx.x * 32, k0 = blockIdx.y * 32;
#pragma unroll
    for (int j = 0; j < 4; j++) {
        const int k = k0 + ty + j * 8;
        t[ty + j * 8][tx] = W[(size_t)k * N + n0 + tx];
    }
    __syncthreads();
#pragma unroll
    for (int j = 0; j < 4; j++) {
        const int n = n0 + ty + j * 8;
        const int k = k0 + tx;
        const float w = t[tx][ty + j * 8];
        const __nv_bfloat16 h = __float2bfloat16(w);
        hi[(size_t)n * K + k] = h;
        lo[(size_t)n * K + k] = __float2bfloat16(w - __bfloat162float(h));
    }
}

// ---------------------------------------------------------------------------
// Activation split
// ---------------------------------------------------------------------------
__global__ void split_a_kernel(const float* __restrict__ A,
                               __nv_bfloat16* __restrict__ hi,
                               __nv_bfloat16* __restrict__ lo,
                               int total4)
{
    const int i = blockIdx.x * blockDim.x + threadIdx.x;
    if (i >= total4) return;
    const float4 v = ((const float4*)A)[i];
    const __nv_bfloat16 h0 = __float2bfloat16(v.x);
    const __nv_bfloat16 h1 = __float2bfloat16(v.y);
    const __nv_bfloat16 h2 = __float2bfloat16(v.z);
    const __nv_bfloat16 h3 = __float2bfloat16(v.w);
    uint2 hp, lp;
    hp.x = ((uint32_t)__bfloat16_as_ushort(h1) << 16) | __bfloat16_as_ushort(h0);
    hp.y = ((uint32_t)__bfloat16_as_ushort(h3) << 16) | __bfloat16_as_ushort(h2);
    lp.x = pack2_bf16(v.x - __bfloat162float(h0), v.y - __bfloat162float(h1));
    lp.y = pack2_bf16(v.z - __bfloat162float(h2), v.w - __bfloat162float(h3));
    ((uint2*)hi)[i] = hp;
    ((uint2*)lo)[i] = lp;
}

// ---------------------------------------------------------------------------
// bf16x3 HMMA GEMM, XOR-swizzled smem (64B rows), 3-stage cp.async.
// FIXED ordering: wait -> sync -> prefetch -> compute (one sync/iter).
// MODE 0: fp32 out + bias. MODE 1: QKV with fused RoPE (table) epilogue.
// ---------------------------------------------------------------------------
#define GAS (128 * 32)               // 4096 halfs per array
#define GSTG (4 * GAS)               // 16384 halfs per stage
#define GEMM_SMEM (3 * GSTG * 2)     // 98304 B

template <int MODE>
__global__ __launch_bounds__(256, 2) void gemm_mma_kernel(
    const __nv_bfloat16* __restrict__ Ahg, const __nv_bfloat16* __restrict__ Alg,
    const __nv_bfloat16* __restrict__ Bhg, const __nv_bfloat16* __restrict__ Blg,
    const float* __restrict__ bias, float* __restrict__ Cout,
    __nv_bfloat16* __restrict__ Qh, __nv_bfloat16* __restrict__ Ql,
    __nv_bfloat16* __restrict__ Kh, __nv_bfloat16* __restrict__ Kl,
    int M, int N, int K)
{
    extern __shared__ __nv_bfloat16 gsm[];
    const uint32_t sb = smem_u32(gsm);

    const int tid = threadIdx.x;
    const int wid = tid >> 5;
    const int l   = tid & 31;
    const int wm  = wid >> 2;
    const int wn  = wid & 3;
    const int bm  = blockIdx.y * 128;
    const int bn  = blockIdx.x * 128;

    const int a_row = l & 15;
    const int a_col = (l >> 4) * 8;
    const int b_row = (l & 7) + ((l >> 4) & 1) * 8;
    const int b_col = ((l >> 3) & 1) * 8;
    const int axor  = (a_row >> 1) & 3;
    const int bxor  = (b_row >> 1) & 3;

    auto prefetch = [&](int kt, int st) {
#pragma unroll
        for (int i = 0; i < 8; i++) {
            const int c   = i * 256 + tid;
            const int arr = c >> 9;
            const int r   = (c >> 2) & 127;
            const int c16 = c & 3;
            const int off = r * 32 + ((c16 ^ ((r >> 1) & 3)) << 3);
            const uint32_t sa = sb + 2 * (st * GSTG + arr * GAS + off);
            const __nv_bfloat16* g;
            if (arr == 0)      g = Ahg + (size_t)(bm + r) * K + kt + c16 * 8;
            else if (arr == 1) g = Alg + (size_t)(bm + r) * K + kt + c16 * 8;
            else if (arr == 2) g = Bhg + (size_t)(bn + r) * K + kt + c16 * 8;
            else               g = Blg + (size_t)(bn + r) * K + kt + c16 * 8;
            cp16(sa, g);
        }
        cp_commit();
    };

    float acc[4][4][4];
#pragma unroll
    for (int i = 0; i < 4; i++)
#pragma unroll
        for (int j = 0; j < 4; j++)
#pragma unroll
            for (int t = 0; t < 4; t++) acc[i][j][t] = 0.f;

    const int nk = K / 32;                  // 24
    prefetch(0, 0);
    prefetch(32, 1);

    for (int it = 0; it < nk; it++) {
        const int st = it % 3;
        if (it + 1 < nk) cp_wait1();        // my group `it` complete
        else             cp_wait0();
        __syncthreads();                    // everyone's group `it` visible;
                                            // stage (it+2)%3 retired by all warps
        if (it + 2 < nk) prefetch((it + 2) * 32, (it + 2) % 3);

        const uint32_t uAh = sb + 2 * (st * GSTG + 0 * GAS);
        const uint32_t uAl = sb + 2 * (st * GSTG + 1 * GAS);
        const uint32_t uBh = sb + 2 * (st * GSTG + 2 * GAS);
        const uint32_t uBl = sb + 2 * (st * GSTG + 3 * GAS);

#pragma unroll
        for (int kh = 0; kh < 2; kh++) {
            const int kc = kh * 16;
            const int ac = ((kc + a_col) >> 3) ^ axor;
            const int bc = ((kc + b_col) >> 3) ^ bxor;
            uint32_t af[4][4], bfh[4][2], bfl[4][2];
#pragma unroll
            for (int ti = 0; ti < 4; ti++)
                ldm4(af[ti], uAh + 2 * ((wm * 64 + ti * 16 + a_row) * 32 + ac * 8));
#pragma unroll
            for (int bp = 0; bp < 2; bp++) {
                uint32_t r4[4];
                ldm4(r4, uBh + 2 * ((wn * 32 + bp * 16 + b_row) * 32 + bc * 8));
                bfh[bp * 2 + 0][0] = r4[0]; bfh[bp * 2 + 0][1] = r4[1];
                bfh[bp * 2 + 1][0] = r4[2]; bfh[bp * 2 + 1][1] = r4[3];
            }
#pragma unroll
            for (int bp = 0; bp < 2; bp++) {
                uint32_t r4[4];
                ldm4(r4, uBl + 2 * ((wn * 32 + bp * 16 + b_row) * 32 + bc * 8));
                bfl[bp * 2 + 0][0] = r4[0]; bfl[bp * 2 + 0][1] = r4[1];
                bfl[bp * 2 + 1][0] = r4[2]; bfl[bp * 2 + 1][1] = r4[3];
            }
#pragma unroll
            for (int ti = 0; ti < 4; ti++)
#pragma unroll
                for (int nj = 0; nj < 4; nj++)
                    mma_bf16(acc[ti][nj], af[ti], bfh[nj]);
#pragma unroll
            for (int ti = 0; ti < 4; ti++)
#pragma unroll
                for (int nj = 0; nj < 4; nj++)
                    mma_bf16(acc[ti][nj], af[ti], bfl[nj]);
#pragma unroll
            for (int ti = 0; ti < 4; ti++)
                ldm4(af[ti], uAl + 2 * ((wm * 64 + ti * 16 + a_row) * 32 + ac * 8));
#pragma unroll
            for (int ti = 0; ti < 4; ti++)
#pragma unroll
                for (int nj = 0; nj < 4; nj++)
                    mma_bf16(acc[ti][nj], af[ti], bfh[nj]);
        }
    }

    const int row_in = l >> 2;
    const int col_in = (l & 3) * 2;
    const int col0base = bn + wn * 32;

    if (MODE == 0 || col0base >= 2 * 768) {
#pragma unroll
        for (int ti = 0; ti < 4; ti++) {
#pragma unroll
            for (int nj = 0; nj < 4; nj++) {
                const int col = col0base + nj * 8 + col_in;
                const float b0 = bias[col], b1 = bias[col + 1];
                const int r0 = bm + wm * 64 + ti * 16 + row_in;
                float2 v0 = { acc[ti][nj][0] + b0, acc[ti][nj][1] + b1 };
                float2 v1 = { acc[ti][nj][2] + b0, acc[ti][nj][3] + b1 };
                *(float2*)(Cout + (size_t)r0 * N + col) = v0;
                *(float2*)(Cout + (size_t)(r0 + 8) * N + col) = v1;
            }
        }
    } else {
        // Q/K band: RoPE via table + bf16 hi/lo split store
        const int s    = col0base / 768;
        const int head = (col0base % 768) / 64;
        const int half = (col0base % 64) >> 5;
        __nv_bfloat16* dh = s ? Kh : Qh;
        __nv_bfloat16* dl = s ? Kl : Ql;
        const float qs = s ? 1.0f : 0.125f;

#pragma unroll
        for (int nj = 0; nj < 2; nj++) {
            const int jj  = nj * 8 + col_in;
            const int k0  = jj >> 1;
            const int jcol = col0base + jj;
            const float bA0 = bias[jcol],      bA1 = bias[jcol + 1];
            const float bB0 = bias[jcol + 16], bB1 = bias[jcol + 17];
#pragma unroll
            for (int ti = 0; ti < 4; ti++) {
#pragma unroll
                for (int kk = 0; kk < 4; kk++) {
                    const int row = bm + wm * 64 + ti * 16 + row_in + (kk >> 1) * 8;
                    const int j   = jj + (kk & 1);
                    const float t0 = acc[ti][nj][kk]     + ((kk & 1) ? bA1 : bA0);
                    const float t1 = acc[ti][nj + 2][kk] + ((kk & 1) ? bB1 : bB0);
                    const int bb = row >> 10, n = row & 1023;
                    const int pos = half ? (n & 31) : (n >> 5);
                    const float2 cs0 = g_rope[k0][pos];
                    const float2 cs1 = g_rope[k0 + 8][pos];
                    const float o0 = (t0 * cs0.x - t1 * cs0.y) * qs;
                    const float o1 = (t1 * cs1.x + t0 * cs1.y) * qs;
                    const size_t ob = ((size_t)(bb * 12 + head) * N_ + n) * 64
                                      + half * 32 + j;
                    const __nv_bfloat16 h0 = __float2bfloat16(o0);
                    const __nv_bfloat16 h1 = __float2bfloat16(o1);
                    dh[ob]      = h0;
                    dh[ob + 16] = h1;
                    dl[ob]      = __float2bfloat16(o0 - __bfloat162float(h0));
                    dl[ob + 16] = __float2bfloat16(o1 - __bfloat162float(h1));
                }
            }
        }
    }
}

// ---------------------------------------------------------------------------
// V transpose + split (reads V third of g_qkv)
// ---------------------------------------------------------------------------
__global__ void v_split_kernel(const float* __restrict__ qkv,
                               __nv_bfloat16* __restrict__ Vh,
                               __nv_bfloat16* __restrict__ Vl)
{
    __shared__ float ts[64][65];
    const int tid = threadIdx.x;
    const int n0 = blockIdx.x * 64;
    const int h  = blockIdx.y;
    const int b  = blockIdx.z;
    const int bh = b * 12 + h;

#pragma unroll
    for (int i = 0; i < 16; i++) {
        const int li = i * 256 + tid;
        const int r = li >> 6, c = li & 63;
        ts[r][c] = qkv[(size_t)(b * N_ + n0 + r) * QKV_N + 1536 + h * 64 + c];
    }
    __syncthreads();
#pragma unroll
    for (int i = 0; i < 8; i++) {
        const int li = i * 256 + tid;
        const int d = li >> 5, c2 = (li & 31) * 2;
        const float v0 = ts[c2][d], v1 = ts[c2 + 1][d];
        const __nv_bfloat16 h0 = __float2bfloat16(v0);
        const __nv_bfloat16 h1 = __float2bfloat16(v1);
        const size_t ob = ((size_t)bh * 64 + d) * N_ + n0 + c2;
        *(uint32_t*)&Vh[ob] =
            ((uint32_t)__bfloat16_as_ushort(h1) << 16) | __bfloat16_as_ushort(h0);
        *(uint32_t*)&Vl[ob] =
            pack2_bf16(v0 - __bfloat162float(h0), v1 - __bfloat162float(h1));
    }
}

// ---------------------------------------------------------------------------
// Tensor-core flash attention (bf16x3), 2 CTAs/SM (unchanged from R10)
// ---------------------------------------------------------------------------
#define ATS 72
#define AAS (64 * ATS)
#define ATT_SMEM (2 * 4 * AAS * 2)   // 73728 B

__global__ __launch_bounds__(256, 2) void attn_mma_kernel(
    const __nv_bfloat16* __restrict__ Qh, const __nv_bfloat16* __restrict__ Ql,
    const __nv_bfloat16* __restrict__ Kh, const __nv_bfloat16* __restrict__ Kl,
    const __nv_bfloat16* __restrict__ Vh, const __nv_bfloat16* __restrict__ Vl,
    __nv_bfloat16* __restrict__ oh, __nv_bfloat16* __restrict__ ol)
{
    extern __shared__ __nv_bfloat16 smh[];
    const uint32_t sb = smem_u32(smh);

    const int tid = threadIdx.x;
    const int wid = tid >> 5;
    const int l   = tid & 31;
    const int qb  = blockIdx.x;
    const int h   = blockIdx.y;
    const int b   = blockIdx.z;
    const int bh  = b * H_ + h;
    const int q0  = qb * 128;
    const int wrow = wid * 16;

    const int b_row = (l & 7) + ((l >> 4) & 1) * 8;
    const int b_col = ((l >> 3) & 1) * 8;

    const uint32_t* q32h = (const uint32_t*)(Qh + ((size_t)bh * N_ + q0) * 64);
    const uint32_t* q32l = (const uint32_t*)(Ql + ((size_t)bh * N_ + q0) * 64);
    uint32_t qfh[4][4], qfl[4][4];
    {
        const int r0 = wrow + (l >> 2);
        const int cb = (l & 3) * 2;
#pragma unroll
        for (int t = 0; t < 4; t++) {
            const int c0 = t * 16 + cb;
            qfh[t][0] = q32h[(r0 * 64 + c0) >> 1];
            qfh[t][1] = q32h[((r0 + 8) * 64 + c0) >> 1];
            qfh[t][2] = q32h[(r0 * 64 + c0 + 8) >> 1];
            qfh[t][3] = q32h[((r0 + 8) * 64 + c0 + 8) >> 1];
            qfl[t][0] = q32l[(r0 * 64 + c0) >> 1];
            qfl[t][1] = q32l[((r0 + 8) * 64 + c0) >> 1];
            qfl[t][2] = q32l[(r0 * 64 + c0 + 8) >> 1];
            qfl[t][3] = q32l[((r0 + 8) * 64 + c0 + 8) >> 1];
        }
    }

    const __nv_bfloat16* gKh = Kh + (size_t)bh * N_ * 64;
    const __nv_bfloat16* gKl = Kl + (size_t)bh * N_ * 64;
    const __nv_bfloat16* gVh = Vh + (size_t)bh * 64 * N_;
    const __nv_bfloat16* gVl = Vl + (size_t)bh * 64 * N_;

    auto prefetch = [&](int kb, int st) {
#pragma unroll
        for (int i = 0; i < 8; i++) {
            const int c   = i * 256 + tid;
            const int arr = c >> 9;
            const int r   = (c >> 3) & 63;
            const int c16 = c & 7;
            const uint32_t sa = sb + 2 * ((st * 4 + arr) * AAS + r * ATS + c16 * 8);
            const __nv_bfloat16* g;
            if (arr == 0)      g = gKh + (size_t)(kb * 64 + r) * 64 + c16 * 8;
            else if (arr == 1) g = gKl + (size_t)(kb * 64 + r) * 64 + c16 * 8;
            else if (arr == 2) g = gVh + (size_t)r * N_ + kb * 64 + c16 * 8;
            else               g = gVl + (size_t)r * N_ + kb * 64 + c16 * 8;
            cp16(sa, g);
        }
        cp_commit();
    };

    float acc[8][4];
    float mrun[2] = { -1e30f, -1e30f }, lrun[2] = { 0.f, 0.f };
#pragma unroll
    for (int j = 0; j < 8; j++)
#pragma unroll
        for (int t = 0; t < 4; t++) acc[j][t] = 0.f;

    prefetch(0, 0);

    for (int kb = 0; kb < 16; kb++) {
        const int st = kb & 1;
        if (kb + 1 < 16) { prefetch(kb + 1, st ^ 1); cp_wait1(); }
        else             { cp_wait0(); }
        __syncthreads();

        const uint32_t uKh = sb + 2 * ((st * 4 + 0) * AAS);
        const uint32_t uKl = sb + 2 * ((st * 4 + 1) * AAS);
        const uint32_t uVh = sb + 2 * ((st * 4 + 2) * AAS);
        const uint32_t uVl = sb + 2 * ((st * 4 + 3) * AAS);

        float sv[8][4];
#pragma unroll
        for (int j = 0; j < 8; j++)
#pragma unroll
            for (int t = 0; t < 4; t++) sv[j][t] = 0.f;

#pragma unroll
        for (int t = 0; t < 4; t++) {
#pragma unroll
            for (int bp = 0; bp < 4; bp++) {
                uint32_t rh[4], rl[4];
                ldm4(rh, uKh + 2 * ((bp * 16 + b_row) * ATS + t * 16 + b_col));
                ldm4(rl, uKl + 2 * ((bp * 16 + b_row) * ATS + t * 16 + b_col));
                mma_bf16(sv[2 * bp],     qfh[t], rh);
                mma_bf16(sv[2 * bp + 1], qfh[t], rh + 2);
                mma_bf16(sv[2 * bp],     qfl[t], rh);
                mma_bf16(sv[2 * bp + 1], qfl[t], rh + 2);
                mma_bf16(sv[2 * bp],     qfh[t], rl);
                mma_bf16(sv[2 * bp + 1], qfh[t], rl + 2);
            }
        }

#pragma unroll
        for (int i = 0; i < 2; i++) {
            float mx = -1e30f;
#pragma unroll
            for (int j = 0; j < 8; j++)
                mx = fmaxf(mx, fmaxf(sv[j][2 * i], sv[j][2 * i + 1]));
            mx = fmaxf(mx, __shfl_xor_sync(0xffffffffu, mx, 1));
            mx = fmaxf(mx, __shfl_xor_sync(0xffffffffu, mx, 2));
            const float mnew = fmaxf(mrun[i], mx);
            const float corr = __expf(mrun[i] - mnew);
            float rs = 0.f;
#pragma unroll
            for (int j = 0; j < 8; j++) {
                const float p0 = __expf(sv[j][2 * i] - mnew);
                const float p1 = __expf(sv[j][2 * i + 1] - mnew);
                sv[j][2 * i] = p0; sv[j][2 * i + 1] = p1;
                rs += p0 + p1;
            }
            rs += __shfl_xor_sync(0xffffffffu, rs, 1);
            rs += __shfl_xor_sync(0xffffffffu, rs, 2);
            lrun[i] = lrun[i] * corr + rs;
#pragma unroll
            for (int j = 0; j < 8; j++) {
                acc[j][2 * i] *= corr;
                acc[j][2 * i + 1] *= corr;
            }
            mrun[i] = mnew;
        }

        uint32_t pfh[4][4], pfl[4][4];
#pragma unroll
        for (int t = 0; t < 4; t++) {
#pragma unroll
            for (int q = 0; q < 4; q++) {
                const int j = 2 * t + (q >> 1);
                const float p0 = sv[j][(q & 1) * 2];
                const float p1 = sv[j][(q & 1) * 2 + 1];
                const __nv_bfloat16 h0 = __float2bfloat16(p0);
                const __nv_bfloat16 h1 = __float2bfloat16(p1);
                pfh[t][q] = ((uint32_t)__bfloat16_as_ushort(h1) << 16) |
                            __bfloat16_as_ushort(h0);
                pfl[t][q] = pack2_bf16(p0 - __bfloat162float(h0),
                                       p1 - __bfloat162float(h1));
            }
        }

#pragma unroll
        for (int t = 0; t < 4; t++) {
#pragma unroll
            for (int bp = 0; bp < 4; bp++) {
                uint32_t rh[4], rl[4];
                ldm4(rh, uVh + 2 * ((bp * 16 + b_row) * ATS + t * 16 + b_col));
                ldm4(rl, uVl + 2 * ((bp * 16 + b_row) * ATS + t * 16 + b_col));
                mma_bf16(acc[2 * bp],     pfh[t], rh);
                mma_bf16(acc[2 * bp + 1], pfh[t], rh + 2);
                mma_bf16(acc[2 * bp],     pfl[t], rh);
                mma_bf16(acc[2 * bp + 1], pfl[t], rh + 2);
                mma_bf16(acc[2 * bp],     pfh[t], rl);
                mma_bf16(acc[2 * bp + 1], pfh[t], rl + 2);
            }
        }
        __syncthreads();
    }

    const float il0 = 1.f / lrun[0];
    const float il1 = 1.f / lrun[1];
    const int r0 = q0 + wrow + (l >> 2);
    const int cb = h * 64 + (l & 3) * 2;
#pragma unroll
    for (int j = 0; j < 8; j++) {
        const float a0 = acc[j][0] * il0, a1 = acc[j][1] * il0;
        const float a2 = acc[j][2] * il1, a3 = acc[j][3] * il1;
        const __nv_bfloat16 h0 = __float2bfloat16(a0);
        const __nv_bfloat16 h1 = __float2bfloat16(a1);
        const __nv_bfloat16 h2 = __float2bfloat16(a2);
        const __nv_bfloat16 h3 = __float2bfloat16(a3);
        const size_t o0 = (size_t)(b * N_ + r0) * C_ + cb + j * 8;
        const size_t o1 = (size_t)(b * N_ + r0 + 8) * C_ + cb + j * 8;
        *(uint32_t*)&oh[o0] =
            ((uint32_t)__bfloat16_as_ushort(h1) << 16) | __bfloat16_as_ushort(h0);
        *(uint32_t*)&oh[o1] =
            ((uint32_t)__bfloat16_as_ushort(h3) << 16) | __bfloat16_as_ushort(h2);
        *(uint32_t*)&ol[o0] = pack2_bf16(a0 - __bfloat162float(h0),
                                         a1 - __bfloat162float(h1));
        *(uint32_t*)&ol[o1] = pack2_bf16(a2 - __bfloat162float(h2),
                                         a3 - __bfloat162float(h3));
    }
}

// ---------------------------------------------------------------------------
extern "C" void kernel_launch(void* const* d_in, const int* in_sizes, int n_in,
                              void* d_out, int out_size)
{
    const float* x     = (const float*)d_in[0];
    const float* Wqkv  = (const float*)d_in[1];
    const float* bqkv  = (const float*)d_in[2];
    const float* Wproj = (const float*)d_in[3];
    const float* bproj = (const float*)d_in[4];
    float*       out   = (float*)d_out;

    float* qkv = nullptr;
    __nv_bfloat16 *wqh, *wql, *wph, *wpl, *ah, *al;
    __nv_bfloat16 *aQh, *aQl, *aKh, *aKl, *aVh, *aVl;
    cudaGetSymbolAddress((void**)&qkv, g_qkv);
    cudaGetSymbolAddress((void**)&wqh, g_wqkv_hi);
    cudaGetSymbolAddress((void**)&wql, g_wqkv_lo);
    cudaGetSymbolAddress((void**)&wph, g_wproj_hi);
    cudaGetSymbolAddress((void**)&wpl, g_wproj_lo);
    cudaGetSymbolAddress((void**)&ah,  g_ah);
    cudaGetSymbolAddress((void**)&al,  g_al);
    cudaGetSymbolAddress((void**)&aQh, g_Qh);
    cudaGetSymbolAddress((void**)&aQl, g_Ql);
    cudaGetSymbolAddress((void**)&aKh, g_Kh);
    cudaGetSymbolAddress((void**)&aKl, g_Kl);
    cudaGetSymbolAddress((void**)&aVh, g_Vh);
    cudaGetSymbolAddress((void**)&aVl, g_Vl);

    static bool attr_set = false;
    if (!attr_set) {
        cudaFuncSetAttribute(attn_mma_kernel,
                             cudaFuncAttributeMaxDynamicSharedMemorySize, ATT_SMEM);
        cudaFuncSetAttribute(gemm_mma_kernel<0>,
                             cudaFuncAttributeMaxDynamicSharedMemorySize, GEMM_SMEM);
        cudaFuncSetAttribute(gemm_mma_kernel<1>,
                             cudaFuncAttributeMaxDynamicSharedMemorySize, GEMM_SMEM);
        attr_set = true;
    }

    const int a_total4 = M_TOT * K_DIM / 4;

    // 0) RoPE table + weight splits + x split
    rope_init_kernel<<<1, 512>>>();
    split_w_kernel<<<dim3(QKV_N / 32, K_DIM / 32), dim3(32, 8)>>>(Wqkv, wqh, wql, K_DIM, QKV_N);
    split_w_kernel<<<dim3(C_ / 32, K_DIM / 32), dim3(32, 8)>>>(Wproj, wph, wpl, K_DIM, C_);
    split_a_kernel<<<(a_total4 + 255) / 256, 256>>>(x, ah, al, a_total4);

    // 1) QKV projection + fused RoPE/split epilogue (V -> g_qkv fp32)
    gemm_mma_kernel<1><<<dim3(QKV_N / 128, M_TOT / 128), 256, GEMM_SMEM>>>(
        ah, al, wqh, wql, bqkv, qkv, aQh, aQl, aKh, aKl, M_TOT, QKV_N, K_DIM);

    // 2) V transpose + split
    v_split_kernel<<<dim3(N_ / 64, H_, B_), 256>>>(qkv, aVh, aVl);

    // 3) Flash attention (writes split proj input into g_ah/g_al)
    attn_mma_kernel<<<dim3(N_ / 128, H_, B_), 256, ATT_SMEM>>>(
        aQh, aQl, aKh, aKl, aVh, aVl, ah, al);

    // 4) Output projection
    gemm_mma_kernel<0><<<dim3(C_ / 128, M_TOT / 128), 256, GEMM_SMEM>>>(
        ah, al, wph, wpl, bproj, out, nullptr, nullptr, nullptr, nullptr,
        M_TOT, C_, K_DIM);
}

// round 13
// speedup vs baseline: 2.7623x; 1.0268x over previous
#include <cuda_runtime.h>
#include <cuda_bf16.h>
#include <cstdint>

#define B_    16
#define N_    1024
#define C_    768
#define H_    12
#define M_TOT (B_ * N_)        // 16384
#define QKV_N (3 * C_)         // 2304
#define K_DIM 768
#define BH_   (B_ * H_)        // 192

// ---------------------------------------------------------------------------
// Scratch (__device__ globals only)
// ---------------------------------------------------------------------------
__device__ __align__(16) float g_qkv[(size_t)M_TOT * QKV_N];   // only V third used
__device__ __align__(16) float2 g_rope[16][32];                 // (cos,sin)[k][pos]
__device__ __align__(16) __nv_bfloat16 g_wqkv_hi[(size_t)QKV_N * K_DIM];
__device__ __align__(16) __nv_bfloat16 g_wqkv_lo[(size_t)QKV_N * K_DIM];
__device__ __align__(16) __nv_bfloat16 g_wproj_hi[(size_t)C_ * K_DIM];
__device__ __align__(16) __nv_bfloat16 g_wproj_lo[(size_t)C_ * K_DIM];
__device__ __align__(16) __nv_bfloat16 g_ah[(size_t)M_TOT * K_DIM];
__device__ __align__(16) __nv_bfloat16 g_al[(size_t)M_TOT * K_DIM];
__device__ __align__(16) __nv_bfloat16 g_Qh[(size_t)BH_ * N_ * 64];
__device__ __align__(16) __nv_bfloat16 g_Ql[(size_t)BH_ * N_ * 64];
__device__ __align__(16) __nv_bfloat16 g_Kh[(size_t)BH_ * N_ * 64];
__device__ __align__(16) __nv_bfloat16 g_Kl[(size_t)BH_ * N_ * 64];
__device__ __align__(16) __nv_bfloat16 g_Vh[(size_t)BH_ * 64 * N_];
__device__ __align__(16) __nv_bfloat16 g_Vl[(size_t)BH_ * 64 * N_];

// ---------------------------------------------------------------------------
// helpers
// ---------------------------------------------------------------------------
__device__ __forceinline__ uint32_t smem_u32(const void* p) {
    uint32_t a;
    asm("{ .reg .u64 t; cvta.to.shared.u64 t, %1; cvt.u32.u64 %0, t; }"
        : "=r"(a) : "l"(p));
    return a;
}
__device__ __forceinline__ void ldm4(uint32_t* r, uint32_t addr) {
    asm volatile("ldmatrix.sync.aligned.m8n8.x4.shared.b16 {%0,%1,%2,%3}, [%4];"
                 : "=r"(r[0]), "=r"(r[1]), "=r"(r[2]), "=r"(r[3]) : "r"(addr));
}
__device__ __forceinline__ void mma_bf16(float* c, const uint32_t* a, const uint32_t* b) {
    asm volatile("mma.sync.aligned.m16n8k16.row.col.f32.bf16.bf16.f32 "
                 "{%0,%1,%2,%3}, {%4,%5,%6,%7}, {%8,%9}, {%0,%1,%2,%3};"
                 : "+f"(c[0]), "+f"(c[1]), "+f"(c[2]), "+f"(c[3])
                 : "r"(a[0]), "r"(a[1]), "r"(a[2]), "r"(a[3]),
                   "r"(b[0]), "r"(b[1]));
}
__device__ __forceinline__ void cp16(uint32_t sa, const void* g) {
    asm volatile("cp.async.cg.shared.global [%0], [%1], 16;" :: "r"(sa), "l"(g));
}
__device__ __forceinline__ void cp_commit() {
    asm volatile("cp.async.commit_group;" ::: "memory");
}
__device__ __forceinline__ void cp_wait1() {
    asm volatile("cp.async.wait_group 1;" ::: "memory");
}
__device__ __forceinline__ void cp_wait0() {
    asm volatile("cp.async.wait_group 0;" ::: "memory");
}
__device__ __forceinline__ uint32_t pack2_bf16(float a, float b) {
    return ((uint32_t)__bfloat16_as_ushort(__float2bfloat16(b)) << 16) |
           (uint32_t)__bfloat16_as_ushort(__float2bfloat16(a));
}

// ---------------------------------------------------------------------------
// RoPE table init (bit-identical expressions to the in-epilogue math)
// ---------------------------------------------------------------------------
__global__ void rope_init_kernel() {
    const int idx = threadIdx.x;           // 0..511
    const int k = idx >> 5, pos = idx & 31;
    const float L = 9.210340371976184f / 16.0f;
    const float ang = (float)pos * expf(-L * (float)k);
    float s, c;
    sincosf(ang, &s, &c);
    g_rope[k][pos] = make_float2(c, s);
}

// ---------------------------------------------------------------------------
// Weight prep: W [K,N] fp32 -> hi/lo bf16 [N,K]
// ---------------------------------------------------------------------------
__global__ void split_w_kernel(const float* __restrict__ W,
                               __nv_bfloat16* __restrict__ hi,
                               __nv_bfloat16* __restrict__ lo,
                               int K, int N) {
    __shared__ float t[32][33];
    const int tx = threadIdx.x, ty = threadIdx.y;
    const int n0 = blockIdx.x * 32, k0 = blockIdx.y * 32;
#pragma unroll
    for (int j = 0; j < 4; j++) {
        const int k = k0 + ty + j * 8;
        t[ty + j * 8][tx] = W[(size_t)k * N + n0 + tx];
    }
    __syncthreads();
#pragma unroll
    for (int j = 0; j < 4; j++) {
        const int n = n0 + ty + j * 8;
        const int k = k0 + tx;
        const float w = t[tx][ty + j * 8];
        const __nv_bfloat16 h = __float2bfloat16(w);
        hi[(size_t)n * K + k] = h;
        lo[(size_t)n * K + k] = __float2bfloat16(w - __bfloat162float(h));
    }
}

// ---------------------------------------------------------------------------
// Activation split
// ---------------------------------------------------------------------------
__global__ void split_a_kernel(const float* __restrict__ A,
                               __nv_bfloat16* __restrict__ hi,
                               __nv_bfloat16* __restrict__ lo,
                               int total4)
{
    const int i = blockIdx.x * blockDim.x + threadIdx.x;
    if (i >= total4) return;
    const float4 v = ((const float4*)A)[i];
    const __nv_bfloat16 h0 = __float2bfloat16(v.x);
    const __nv_bfloat16 h1 = __float2bfloat16(v.y);
    const __nv_bfloat16 h2 = __float2bfloat16(v.z);
    const __nv_bfloat16 h3 = __float2bfloat16(v.w);
    uint2 hp, lp;
    hp.x = ((uint32_t)__bfloat16_as_ushort(h1) << 16) | __bfloat16_as_ushort(h0);
    hp.y = ((uint32_t)__bfloat16_as_ushort(h3) << 16) | __bfloat16_as_ushort(h2);
    lp.x = pack2_bf16(v.x - __bfloat162float(h0), v.y - __bfloat162float(h1));
    lp.y = pack2_bf16(v.z - __bfloat162float(h2), v.w - __bfloat162float(h3));
    ((uint2*)hi)[i] = hp;
    ((uint2*)lo)[i] = lp;
}

// ---------------------------------------------------------------------------
// bf16x3 HMMA GEMM (unchanged from R12 — proven)
// ---------------------------------------------------------------------------
#define GAS (128 * 32)               // 4096 halfs per array
#define GSTG (4 * GAS)               // 16384 halfs per stage
#define GEMM_SMEM (3 * GSTG * 2)     // 98304 B

template <int MODE>
__global__ __launch_bounds__(256, 2) void gemm_mma_kernel(
    const __nv_bfloat16* __restrict__ Ahg, const __nv_bfloat16* __restrict__ Alg,
    const __nv_bfloat16* __restrict__ Bhg, const __nv_bfloat16* __restrict__ Blg,
    const float* __restrict__ bias, float* __restrict__ Cout,
    __nv_bfloat16* __restrict__ Qh, __nv_bfloat16* __restrict__ Ql,
    __nv_bfloat16* __restrict__ Kh, __nv_bfloat16* __restrict__ Kl,
    int M, int N, int K)
{
    extern __shared__ __nv_bfloat16 gsm[];
    const uint32_t sb = smem_u32(gsm);

    const int tid = threadIdx.x;
    const int wid = tid >> 5;
    const int l   = tid & 31;
    const int wm  = wid >> 2;
    const int wn  = wid & 3;
    const int bm  = blockIdx.y * 128;
    const int bn  = blockIdx.x * 128;

    const int a_row = l & 15;
    const int a_col = (l >> 4) * 8;
    const int b_row = (l & 7) + ((l >> 4) & 1) * 8;
    const int b_col = ((l >> 3) & 1) * 8;
    const int axor  = (a_row >> 1) & 3;
    const int bxor  = (b_row >> 1) & 3;

    auto prefetch = [&](int kt, int st) {
#pragma unroll
        for (int i = 0; i < 8; i++) {
            const int c   = i * 256 + tid;
            const int arr = c >> 9;
            const int r   = (c >> 2) & 127;
            const int c16 = c & 3;
            const int off = r * 32 + ((c16 ^ ((r >> 1) & 3)) << 3);
            const uint32_t sa = sb + 2 * (st * GSTG + arr * GAS + off);
            const __nv_bfloat16* g;
            if (arr == 0)      g = Ahg + (size_t)(bm + r) * K + kt + c16 * 8;
            else if (arr == 1) g = Alg + (size_t)(bm + r) * K + kt + c16 * 8;
            else if (arr == 2) g = Bhg + (size_t)(bn + r) * K + kt + c16 * 8;
            else               g = Blg + (size_t)(bn + r) * K + kt + c16 * 8;
            cp16(sa, g);
        }
        cp_commit();
    };

    float acc[4][4][4];
#pragma unroll
    for (int i = 0; i < 4; i++)
#pragma unroll
        for (int j = 0; j < 4; j++)
#pragma unroll
            for (int t = 0; t < 4; t++) acc[i][j][t] = 0.f;

    const int nk = K / 32;                  // 24
    prefetch(0, 0);
    prefetch(32, 1);

    for (int it = 0; it < nk; it++) {
        const int st = it % 3;
        if (it + 1 < nk) cp_wait1();
        else             cp_wait0();
        __syncthreads();
        if (it + 2 < nk) prefetch((it + 2) * 32, (it + 2) % 3);

        const uint32_t uAh = sb + 2 * (st * GSTG + 0 * GAS);
        const uint32_t uAl = sb + 2 * (st * GSTG + 1 * GAS);
        const uint32_t uBh = sb + 2 * (st * GSTG + 2 * GAS);
        const uint32_t uBl = sb + 2 * (st * GSTG + 3 * GAS);

#pragma unroll
        for (int kh = 0; kh < 2; kh++) {
            const int kc = kh * 16;
            const int ac = ((kc + a_col) >> 3) ^ axor;
            const int bc = ((kc + b_col) >> 3) ^ bxor;
            uint32_t af[4][4], bfh[4][2], bfl[4][2];
#pragma unroll
            for (int ti = 0; ti < 4; ti++)
                ldm4(af[ti], uAh + 2 * ((wm * 64 + ti * 16 + a_row) * 32 + ac * 8));
#pragma unroll
            for (int bp = 0; bp < 2; bp++) {
                uint32_t r4[4];
                ldm4(r4, uBh + 2 * ((wn * 32 + bp * 16 + b_row) * 32 + bc * 8));
                bfh[bp * 2 + 0][0] = r4[0]; bfh[bp * 2 + 0][1] = r4[1];
                bfh[bp * 2 + 1][0] = r4[2]; bfh[bp * 2 + 1][1] = r4[3];
            }
#pragma unroll
            for (int bp = 0; bp < 2; bp++) {
                uint32_t r4[4];
                ldm4(r4, uBl + 2 * ((wn * 32 + bp * 16 + b_row) * 32 + bc * 8));
                bfl[bp * 2 + 0][0] = r4[0]; bfl[bp * 2 + 0][1] = r4[1];
                bfl[bp * 2 + 1][0] = r4[2]; bfl[bp * 2 + 1][1] = r4[3];
            }
#pragma unroll
            for (int ti = 0; ti < 4; ti++)
#pragma unroll
                for (int nj = 0; nj < 4; nj++)
                    mma_bf16(acc[ti][nj], af[ti], bfh[nj]);
#pragma unroll
            for (int ti = 0; ti < 4; ti++)
#pragma unroll
                for (int nj = 0; nj < 4; nj++)
                    mma_bf16(acc[ti][nj], af[ti], bfl[nj]);
#pragma unroll
            for (int ti = 0; ti < 4; ti++)
                ldm4(af[ti], uAl + 2 * ((wm * 64 + ti * 16 + a_row) * 32 + ac * 8));
#pragma unroll
            for (int ti = 0; ti < 4; ti++)
#pragma unroll
                for (int nj = 0; nj < 4; nj++)
                    mma_bf16(acc[ti][nj], af[ti], bfh[nj]);
        }
    }

    const int row_in = l >> 2;
    const int col_in = (l & 3) * 2;
    const int col0base = bn + wn * 32;

    if (MODE == 0 || col0base >= 2 * 768) {
#pragma unroll
        for (int ti = 0; ti < 4; ti++) {
#pragma unroll
            for (int nj = 0; nj < 4; nj++) {
                const int col = col0base + nj * 8 + col_in;
                const float b0 = bias[col], b1 = bias[col + 1];
                const int r0 = bm + wm * 64 + ti * 16 + row_in;
                float2 v0 = { acc[ti][nj][0] + b0, acc[ti][nj][1] + b1 };
                float2 v1 = { acc[ti][nj][2] + b0, acc[ti][nj][3] + b1 };
                *(float2*)(Cout + (size_t)r0 * N + col) = v0;
                *(float2*)(Cout + (size_t)(r0 + 8) * N + col) = v1;
            }
        }
    } else {
        const int s    = col0base / 768;
        const int head = (col0base % 768) / 64;
        const int half = (col0base % 64) >> 5;
        __nv_bfloat16* dh = s ? Kh : Qh;
        __nv_bfloat16* dl = s ? Kl : Ql;
        const float qs = s ? 1.0f : 0.125f;

#pragma unroll
        for (int nj = 0; nj < 2; nj++) {
            const int jj  = nj * 8 + col_in;
            const int k0  = jj >> 1;
            const int jcol = col0base + jj;
            const float bA0 = bias[jcol],      bA1 = bias[jcol + 1];
            const float bB0 = bias[jcol + 16], bB1 = bias[jcol + 17];
#pragma unroll
            for (int ti = 0; ti < 4; ti++) {
#pragma unroll
                for (int kk = 0; kk < 4; kk++) {
                    const int row = bm + wm * 64 + ti * 16 + row_in + (kk >> 1) * 8;
                    const int j   = jj + (kk & 1);
                    const float t0 = acc[ti][nj][kk]     + ((kk & 1) ? bA1 : bA0);
                    const float t1 = acc[ti][nj + 2][kk] + ((kk & 1) ? bB1 : bB0);
                    const int bb = row >> 10, n = row & 1023;
                    const int pos = half ? (n & 31) : (n >> 5);
                    const float2 cs0 = g_rope[k0][pos];
                    const float2 cs1 = g_rope[k0 + 8][pos];
                    const float o0 = (t0 * cs0.x - t1 * cs0.y) * qs;
                    const float o1 = (t1 * cs1.x + t0 * cs1.y) * qs;
                    const size_t ob = ((size_t)(bb * 12 + head) * N_ + n) * 64
                                      + half * 32 + j;
                    const __nv_bfloat16 h0 = __float2bfloat16(o0);
                    const __nv_bfloat16 h1 = __float2bfloat16(o1);
                    dh[ob]      = h0;
                    dh[ob + 16] = h1;
                    dl[ob]      = __float2bfloat16(o0 - __bfloat162float(h0));
                    dl[ob + 16] = __float2bfloat16(o1 - __bfloat162float(h1));
                }
            }
        }
    }
}

// ---------------------------------------------------------------------------
// V transpose + split (reads V third of g_qkv)
// ---------------------------------------------------------------------------
__global__ void v_split_kernel(const float* __restrict__ qkv,
                               __nv_bfloat16* __restrict__ Vh,
                               __nv_bfloat16* __restrict__ Vl)
{
    __shared__ float ts[64][65];
    const int tid = threadIdx.x;
    const int n0 = blockIdx.x * 64;
    const int h  = blockIdx.y;
    const int b  = blockIdx.z;
    const int bh = b * 12 + h;

#pragma unroll
    for (int i = 0; i < 16; i++) {
        const int li = i * 256 + tid;
        const int r = li >> 6, c = li & 63;
        ts[r][c] = qkv[(size_t)(b * N_ + n0 + r) * QKV_N + 1536 + h * 64 + c];
    }
    __syncthreads();
#pragma unroll
    for (int i = 0; i < 8; i++) {
        const int li = i * 256 + tid;
        const int d = li >> 5, c2 = (li & 31) * 2;
        const float v0 = ts[c2][d], v1 = ts[c2 + 1][d];
        const __nv_bfloat16 h0 = __float2bfloat16(v0);
        const __nv_bfloat16 h1 = __float2bfloat16(v1);
        const size_t ob = ((size_t)bh * 64 + d) * N_ + n0 + c2;
        *(uint32_t*)&Vh[ob] =
            ((uint32_t)__bfloat16_as_ushort(h1) << 16) | __bfloat16_as_ushort(h0);
        *(uint32_t*)&Vl[ob] =
            pack2_bf16(v0 - __bfloat162float(h0), v1 - __bfloat162float(h1));
    }
}

// ---------------------------------------------------------------------------
// Tensor-core flash attention (bf16x3), XOR-8 swizzled unpadded smem,
// 3-stage cp.async, ONE sync per key-block, 2 CTAs/SM.
// ---------------------------------------------------------------------------
#define AAS2 (64 * 64)               // 4096 halfs per array (64 rows x 128B)
#define ASTG (4 * AAS2)              // 16384 halfs per stage
#define ATT_SMEM (3 * ASTG * 2)      // 98304 B

__global__ __launch_bounds__(256, 2) void attn_mma_kernel(
    const __nv_bfloat16* __restrict__ Qh, const __nv_bfloat16* __restrict__ Ql,
    const __nv_bfloat16* __restrict__ Kh, const __nv_bfloat16* __restrict__ Kl,
    const __nv_bfloat16* __restrict__ Vh, const __nv_bfloat16* __restrict__ Vl,
    __nv_bfloat16* __restrict__ oh, __nv_bfloat16* __restrict__ ol)
{
    extern __shared__ __nv_bfloat16 smh[];
    const uint32_t sb = smem_u32(smh);

    const int tid = threadIdx.x;
    const int wid = tid >> 5;
    const int l   = tid & 31;
    const int qb  = blockIdx.x;
    const int h   = blockIdx.y;
    const int b   = blockIdx.z;
    const int bh  = b * H_ + h;
    const int q0  = qb * 128;
    const int wrow = wid * 16;

    const int b_row = (l & 7) + ((l >> 4) & 1) * 8;
    const int b_col = ((l >> 3) & 1) * 8;
    const int bxor8 = b_row & 7;              // XOR-8 swizzle, constant/thread

    const uint32_t* q32h = (const uint32_t*)(Qh + ((size_t)bh * N_ + q0) * 64);
    const uint32_t* q32l = (const uint32_t*)(Ql + ((size_t)bh * N_ + q0) * 64);
    uint32_t qfh[4][4], qfl[4][4];
    {
        const int r0 = wrow + (l >> 2);
        const int cb = (l & 3) * 2;
#pragma unroll
        for (int t = 0; t < 4; t++) {
            const int c0 = t * 16 + cb;
            qfh[t][0] = q32h[(r0 * 64 + c0) >> 1];
            qfh[t][1] = q32h[((r0 + 8) * 64 + c0) >> 1];
            qfh[t][2] = q32h[(r0 * 64 + c0 + 8) >> 1];
            qfh[t][3] = q32h[((r0 + 8) * 64 + c0 + 8) >> 1];
            qfl[t][0] = q32l[(r0 * 64 + c0) >> 1];
            qfl[t][1] = q32l[((r0 + 8) * 64 + c0) >> 1];
            qfl[t][2] = q32l[(r0 * 64 + c0 + 8) >> 1];
            qfl[t][3] = q32l[((r0 + 8) * 64 + c0 + 8) >> 1];
        }
    }

    const __nv_bfloat16* gKh = Kh + (size_t)bh * N_ * 64;
    const __nv_bfloat16* gKl = Kl + (size_t)bh * N_ * 64;
    const __nv_bfloat16* gVh = Vh + (size_t)bh * 64 * N_;
    const __nv_bfloat16* gVl = Vl + (size_t)bh * 64 * N_;

    // 4 arrays x 64 rows x 8 chunks(16B) = 2048 chunks per stage, 8/thread
    auto prefetch = [&](int kb, int st) {
#pragma unroll
        for (int i = 0; i < 8; i++) {
            const int c   = i * 256 + tid;
            const int arr = c >> 9;
            const int r   = (c >> 3) & 63;
            const int c16 = c & 7;
            const int off = r * 64 + ((c16 ^ (r & 7)) << 3);
            const uint32_t sa = sb + 2 * (st * ASTG + arr * AAS2 + off);
            const __nv_bfloat16* g;
            if (arr == 0)      g = gKh + (size_t)(kb * 64 + r) * 64 + c16 * 8;
            else if (arr == 1) g = gKl + (size_t)(kb * 64 + r) * 64 + c16 * 8;
            else if (arr == 2) g = gVh + (size_t)r * N_ + kb * 64 + c16 * 8;
            else               g = gVl + (size_t)r * N_ + kb * 64 + c16 * 8;
            cp16(sa, g);
        }
        cp_commit();
    };

    float acc[8][4];
    float mrun[2] = { -1e30f, -1e30f }, lrun[2] = { 0.f, 0.f };
#pragma unroll
    for (int j = 0; j < 8; j++)
#pragma unroll
        for (int t = 0; t < 4; t++) acc[j][t] = 0.f;

    prefetch(0, 0);
    prefetch(1, 1);

    for (int kb = 0; kb < 16; kb++) {
        const int st = kb % 3;
        if (kb + 1 < 16) cp_wait1();
        else             cp_wait0();
        __syncthreads();
        if (kb + 2 < 16) prefetch(kb + 2, (kb + 2) % 3);

        const uint32_t uKh = sb + 2 * (st * ASTG + 0 * AAS2);
        const uint32_t uKl = sb + 2 * (st * ASTG + 1 * AAS2);
        const uint32_t uVh = sb + 2 * (st * ASTG + 2 * AAS2);
        const uint32_t uVl = sb + 2 * (st * ASTG + 3 * AAS2);

        float sv[8][4];
#pragma unroll
        for (int j = 0; j < 8; j++)
#pragma unroll
            for (int t = 0; t < 4; t++) sv[j][t] = 0.f;

#pragma unroll
        for (int t = 0; t < 4; t++) {
            const int lc = ((t * 16 + b_col) >> 3);          // logical chunk
#pragma unroll
            for (int bp = 0; bp < 4; bp++) {
                const int roff = (bp * 16 + b_row) * 64 + ((lc ^ bxor8) << 3);
                uint32_t rh[4], rl[4];
                ldm4(rh, uKh + 2 * roff);
                ldm4(rl, uKl + 2 * roff);
                mma_bf16(sv[2 * bp],     qfh[t], rh);
                mma_bf16(sv[2 * bp + 1], qfh[t], rh + 2);
                mma_bf16(sv[2 * bp],     qfl[t], rh);
                mma_bf16(sv[2 * bp + 1], qfl[t], rh + 2);
                mma_bf16(sv[2 * bp],     qfh[t], rl);
                mma_bf16(sv[2 * bp + 1], qfh[t], rl + 2);
            }
        }

#pragma unroll
        for (int i = 0; i < 2; i++) {
            float mx = -1e30f;
#pragma unroll
            for (int j = 0; j < 8; j++)
                mx = fmaxf(mx, fmaxf(sv[j][2 * i], sv[j][2 * i + 1]));
            mx = fmaxf(mx, __shfl_xor_sync(0xffffffffu, mx, 1));
            mx = fmaxf(mx, __shfl_xor_sync(0xffffffffu, mx, 2));
            const float mnew = fmaxf(mrun[i], mx);
            const float corr = __expf(mrun[i] - mnew);
            float rs = 0.f;
#pragma unroll
            for (int j = 0; j < 8; j++) {
                const float p0 = __expf(sv[j][2 * i] - mnew);
                const float p1 = __expf(sv[j][2 * i + 1] - mnew);
                sv[j][2 * i] = p0; sv[j][2 * i + 1] = p1;
                rs += p0 + p1;
            }
            rs += __shfl_xor_sync(0xffffffffu, rs, 1);
            rs += __shfl_xor_sync(0xffffffffu, rs, 2);
            lrun[i] = lrun[i] * corr + rs;
#pragma unroll
            for (int j = 0; j < 8; j++) {
                acc[j][2 * i] *= corr;
                acc[j][2 * i + 1] *= corr;
            }
            mrun[i] = mnew;
        }

        uint32_t pfh[4][4], pfl[4][4];
#pragma unroll
        for (int t = 0; t < 4; t++) {
#pragma unroll
            for (int q = 0; q < 4; q++) {
                const int j = 2 * t + (q >> 1);
                const float p0 = sv[j][(q & 1) * 2];
                const float p1 = sv[j][(q & 1) * 2 + 1];
                const __nv_bfloat16 h0 = __float2bfloat16(p0);
                const __nv_bfloat16 h1 = __float2bfloat16(p1);
                pfh[t][q] = ((uint32_t)__bfloat16_as_ushort(h1) << 16) |
                            __bfloat16_as_ushort(h0);
                pfl[t][q] = pack2_bf16(p0 - __bfloat162float(h0),
                                       p1 - __bfloat162float(h1));
            }
        }

#pragma unroll
        for (int t = 0; t < 4; t++) {
            const int lc = ((t * 16 + b_col) >> 3);
#pragma unroll
            for (int bp = 0; bp < 4; bp++) {
                const int roff = (bp * 16 + b_row) * 64 + ((lc ^ bxor8) << 3);
                uint32_t rh[4], rl[4];
                ldm4(rh, uVh + 2 * roff);
                ldm4(rl, uVl + 2 * roff);
                mma_bf16(acc[2 * bp],     pfh[t], rh);
                mma_bf16(acc[2 * bp + 1], pfh[t], rh + 2);
                mma_bf16(acc[2 * bp],     pfl[t], rh);
                mma_bf16(acc[2 * bp + 1], pfl[t], rh + 2);
                mma_bf16(acc[2 * bp],     pfh[t], rl);
                mma_bf16(acc[2 * bp + 1], pfh[t], rl + 2);
            }
        }
    }

    const float il0 = 1.f / lrun[0];
    const float il1 = 1.f / lrun[1];
    const int r0 = q0 + wrow + (l >> 2);
    const int cb = h * 64 + (l & 3) * 2;
#pragma unroll
    for (int j = 0; j < 8; j++) {
        const float a0 = acc[j][0] * il0, a1 = acc[j][1] * il0;
        const float a2 = acc[j][2] * il1, a3 = acc[j][3] * il1;
        const __nv_bfloat16 h0 = __float2bfloat16(a0);
        const __nv_bfloat16 h1 = __float2bfloat16(a1);
        const __nv_bfloat16 h2 = __float2bfloat16(a2);
        const __nv_bfloat16 h3 = __float2bfloat16(a3);
        const size_t o0 = (size_t)(b * N_ + r0) * C_ + cb + j * 8;
        const size_t o1 = (size_t)(b * N_ + r0 + 8) * C_ + cb + j * 8;
        *(uint32_t*)&oh[o0] =
            ((uint32_t)__bfloat16_as_ushort(h1) << 16) | __bfloat16_as_ushort(h0);
        *(uint32_t*)&oh[o1] =
            ((uint32_t)__bfloat16_as_ushort(h3) << 16) | __bfloat16_as_ushort(h2);
        *(uint32_t*)&ol[o0] = pack2_bf16(a0 - __bfloat162float(h0),
                                         a1 - __bfloat162float(h1));
        *(uint32_t*)&ol[o1] = pack2_bf16(a2 - __bfloat162float(h2),
                                         a3 - __bfloat162float(h3));
    }
}

// ---------------------------------------------------------------------------
extern "C" void kernel_launch(void* const* d_in, const int* in_sizes, int n_in,
                              void* d_out, int out_size)
{
    const float* x     = (const float*)d_in[0];
    const float* Wqkv  = (const float*)d_in[1];
    const float* bqkv  = (const float*)d_in[2];
    const float* Wproj = (const float*)d_in[3];
    const float* bproj = (const float*)d_in[4];
    float*       out   = (float*)d_out;

    float* qkv = nullptr;
    __nv_bfloat16 *wqh, *wql, *wph, *wpl, *ah, *al;
    __nv_bfloat16 *aQh, *aQl, *aKh, *aKl, *aVh, *aVl;
    cudaGetSymbolAddress((void**)&qkv, g_qkv);
    cudaGetSymbolAddress((void**)&wqh, g_wqkv_hi);
    cudaGetSymbolAddress((void**)&wql, g_wqkv_lo);
    cudaGetSymbolAddress((void**)&wph, g_wproj_hi);
    cudaGetSymbolAddress((void**)&wpl, g_wproj_lo);
    cudaGetSymbolAddress((void**)&ah,  g_ah);
    cudaGetSymbolAddress((void**)&al,  g_al);
    cudaGetSymbolAddress((void**)&aQh, g_Qh);
    cudaGetSymbolAddress((void**)&aQl, g_Ql);
    cudaGetSymbolAddress((void**)&aKh, g_Kh);
    cudaGetSymbolAddress((void**)&aKl, g_Kl);
    cudaGetSymbolAddress((void**)&aVh, g_Vh);
    cudaGetSymbolAddress((void**)&aVl, g_Vl);

    static bool attr_set = false;
    if (!attr_set) {
        cudaFuncSetAttribute(attn_mma_kernel,
                             cudaFuncAttributeMaxDynamicSharedMemorySize, ATT_SMEM);
        cudaFuncSetAttribute(gemm_mma_kernel<0>,
                             cudaFuncAttributeMaxDynamicSharedMemorySize, GEMM_SMEM);
        cudaFuncSetAttribute(gemm_mma_kernel<1>,
                             cudaFuncAttributeMaxDynamicSharedMemorySize, GEMM_SMEM);
        attr_set = true;
    }

    const int a_total4 = M_TOT * K_DIM / 4;

    // 0) RoPE table + weight splits + x split
    rope_init_kernel<<<1, 512>>>();
    split_w_kernel<<<dim3(QKV_N / 32, K_DIM / 32), dim3(32, 8)>>>(Wqkv, wqh, wql, K_DIM, QKV_N);
    split_w_kernel<<<dim3(C_ / 32, K_DIM / 32), dim3(32, 8)>>>(Wproj, wph, wpl, K_DIM, C_);
    split_a_kernel<<<(a_total4 + 255) / 256, 256>>>(x, ah, al, a_total4);

    // 1) QKV projection + fused RoPE/split epilogue (V -> g_qkv fp32)
    gemm_mma_kernel<1><<<dim3(QKV_N / 128, M_TOT / 128), 256, GEMM_SMEM>>>(
        ah, al, wqh, wql, bqkv, qkv, aQh, aQl, aKh, aKl, M_TOT, QKV_N, K_DIM);

    // 2) V transpose + split
    v_split_kernel<<<dim3(N_ / 64, H_, B_), 256>>>(qkv, aVh, aVl);

    // 3) Flash attention (writes split proj input into g_ah/g_al)
    attn_mma_kernel<<<dim3(N_ / 128, H_, B_), 256, ATT_SMEM>>>(
        aQh, aQl, aKh, aKl, aVh, aVl, ah, al);

    // 4) Output projection
    gemm_mma_kernel<0><<<dim3(C_ / 128, M_TOT / 128), 256, GEMM_SMEM>>>(
        ah, al, wph, wpl, bproj, out, nullptr, nullptr, nullptr, nullptr,
        M_TOT, C_, K_DIM);
}

// round 14
// speedup vs baseline: 2.9091x; 1.0531x over previous
#include <cuda_runtime.h>
#include <cuda_bf16.h>
#include <cstdint>

#define B_    16
#define N_    1024
#define C_    768
#define H_    12
#define M_TOT (B_ * N_)        // 16384
#define QKV_N (3 * C_)         // 2304
#define K_DIM 768
#define BH_   (B_ * H_)        // 192

// ---------------------------------------------------------------------------
// Scratch (__device__ globals only)
// ---------------------------------------------------------------------------
__device__ __align__(16) float g_qkv[(size_t)M_TOT * QKV_N];   // only V third used
__device__ __align__(16) float2 g_rope[16][32];                 // (cos,sin)[k][pos]
__device__ __align__(16) __nv_bfloat16 g_wqkv_hi[(size_t)QKV_N * K_DIM];
__device__ __align__(16) __nv_bfloat16 g_wqkv_lo[(size_t)QKV_N * K_DIM];
__device__ __align__(16) __nv_bfloat16 g_wproj_hi[(size_t)C_ * K_DIM];
__device__ __align__(16) __nv_bfloat16 g_wproj_lo[(size_t)C_ * K_DIM];
__device__ __align__(16) __nv_bfloat16 g_ah[(size_t)M_TOT * K_DIM];
__device__ __align__(16) __nv_bfloat16 g_al[(size_t)M_TOT * K_DIM];
__device__ __align__(16) __nv_bfloat16 g_Qh[(size_t)BH_ * N_ * 64];
__device__ __align__(16) __nv_bfloat16 g_Ql[(size_t)BH_ * N_ * 64];
__device__ __align__(16) __nv_bfloat16 g_Kh[(size_t)BH_ * N_ * 64];
__device__ __align__(16) __nv_bfloat16 g_Kl[(size_t)BH_ * N_ * 64];
__device__ __align__(16) __nv_bfloat16 g_Vh[(size_t)BH_ * 64 * N_];
__device__ __align__(16) __nv_bfloat16 g_Vl[(size_t)BH_ * 64 * N_];

// ---------------------------------------------------------------------------
// helpers
// ---------------------------------------------------------------------------
__device__ __forceinline__ uint32_t smem_u32(const void* p) {
    uint32_t a;
    asm("{ .reg .u64 t; cvta.to.shared.u64 t, %1; cvt.u32.u64 %0, t; }"
        : "=r"(a) : "l"(p));
    return a;
}
__device__ __forceinline__ void ldm4(uint32_t* r, uint32_t addr) {
    asm volatile("ldmatrix.sync.aligned.m8n8.x4.shared.b16 {%0,%1,%2,%3}, [%4];"
                 : "=r"(r[0]), "=r"(r[1]), "=r"(r[2]), "=r"(r[3]) : "r"(addr));
}
__device__ __forceinline__ void mma_bf16(float* c, const uint32_t* a, const uint32_t* b) {
    asm volatile("mma.sync.aligned.m16n8k16.row.col.f32.bf16.bf16.f32 "
                 "{%0,%1,%2,%3}, {%4,%5,%6,%7}, {%8,%9}, {%0,%1,%2,%3};"
                 : "+f"(c[0]), "+f"(c[1]), "+f"(c[2]), "+f"(c[3])
                 : "r"(a[0]), "r"(a[1]), "r"(a[2]), "r"(a[3]),
                   "r"(b[0]), "r"(b[1]));
}
__device__ __forceinline__ void cp16(uint32_t sa, const void* g) {
    asm volatile("cp.async.cg.shared.global [%0], [%1], 16;" :: "r"(sa), "l"(g));
}
__device__ __forceinline__ void cp_commit() {
    asm volatile("cp.async.commit_group;" ::: "memory");
}
__device__ __forceinline__ void cp_wait1() {
    asm volatile("cp.async.wait_group 1;" ::: "memory");
}
__device__ __forceinline__ void cp_wait0() {
    asm volatile("cp.async.wait_group 0;" ::: "memory");
}
__device__ __forceinline__ uint32_t pack2_bf16(float a, float b) {
    return ((uint32_t)__bfloat16_as_ushort(__float2bfloat16(b)) << 16) |
           (uint32_t)__bfloat16_as_ushort(__float2bfloat16(a));
}

// ---------------------------------------------------------------------------
// RoPE table init (bit-identical expressions to the in-epilogue math)
// ---------------------------------------------------------------------------
__global__ void rope_init_kernel() {
    const int idx = threadIdx.x;           // 0..511
    const int k = idx >> 5, pos = idx & 31;
    const float L = 9.210340371976184f / 16.0f;
    const float ang = (float)pos * expf(-L * (float)k);
    float s, c;
    sincosf(ang, &s, &c);
    g_rope[k][pos] = make_float2(c, s);
}

// ---------------------------------------------------------------------------
// Weight prep: W [K,N] fp32 -> hi/lo bf16 [N,K]
// ---------------------------------------------------------------------------
__global__ void split_w_kernel(const float* __restrict__ W,
                               __nv_bfloat16* __restrict__ hi,
                               __nv_bfloat16* __restrict__ lo,
                               int K, int N) {
    __shared__ float t[32][33];
    const int tx = threadIdx.x, ty = threadIdx.y;
    const int n0 = blockIdx.x * 32, k0 = blockIdx.y * 32;
#pragma unroll
    for (int j = 0; j < 4; j++) {
        const int k = k0 + ty + j * 8;
        t[ty + j * 8][tx] = W[(size_t)k * N + n0 + tx];
    }
    __syncthreads();
#pragma unroll
    for (int j = 0; j < 4; j++) {
        const int n = n0 + ty + j * 8;
        const int k = k0 + tx;
        const float w = t[tx][ty + j * 8];
        const __nv_bfloat16 h = __float2bfloat16(w);
        hi[(size_t)n * K + k] = h;
        lo[(size_t)n * K + k] = __float2bfloat16(w - __bfloat162float(h));
    }
}

// ---------------------------------------------------------------------------
// Activation split
// ---------------------------------------------------------------------------
__global__ void split_a_kernel(const float* __restrict__ A,
                               __nv_bfloat16* __restrict__ hi,
                               __nv_bfloat16* __restrict__ lo,
                               int total4)
{
    const int i = blockIdx.x * blockDim.x + threadIdx.x;
    if (i >= total4) return;
    const float4 v = ((const float4*)A)[i];
    const __nv_bfloat16 h0 = __float2bfloat16(v.x);
    const __nv_bfloat16 h1 = __float2bfloat16(v.y);
    const __nv_bfloat16 h2 = __float2bfloat16(v.z);
    const __nv_bfloat16 h3 = __float2bfloat16(v.w);
    uint2 hp, lp;
    hp.x = ((uint32_t)__bfloat16_as_ushort(h1) << 16) | __bfloat16_as_ushort(h0);
    hp.y = ((uint32_t)__bfloat16_as_ushort(h3) << 16) | __bfloat16_as_ushort(h2);
    lp.x = pack2_bf16(v.x - __bfloat162float(h0), v.y - __bfloat162float(h1));
    lp.y = pack2_bf16(v.z - __bfloat162float(h2), v.w - __bfloat162float(h3));
    ((uint2*)hi)[i] = hp;
    ((uint2*)lo)[i] = lp;
}

// ---------------------------------------------------------------------------
// bf16x3 HMMA GEMM, XOR-swizzled smem, 3-stage cp.async, one sync/iter.
// MODE 0: fp32 out + bias. MODE 1: QKV; Q/K bands RoPE'd + split, smem-staged
// coalesced stores. Branch is CTA-uniform (1536 is a multiple of 128).
// ---------------------------------------------------------------------------
#define GAS (128 * 32)               // 4096 halfs per array
#define GSTG (4 * GAS)               // 16384 halfs per stage
#define GEMM_SMEM (3 * GSTG * 2)     // 98304 B

template <int MODE>
__global__ __launch_bounds__(256, 2) void gemm_mma_kernel(
    const __nv_bfloat16* __restrict__ Ahg, const __nv_bfloat16* __restrict__ Alg,
    const __nv_bfloat16* __restrict__ Bhg, const __nv_bfloat16* __restrict__ Blg,
    const float* __restrict__ bias, float* __restrict__ Cout,
    __nv_bfloat16* __restrict__ Qh, __nv_bfloat16* __restrict__ Ql,
    __nv_bfloat16* __restrict__ Kh, __nv_bfloat16* __restrict__ Kl,
    int M, int N, int K)
{
    extern __shared__ __nv_bfloat16 gsm[];
    const uint32_t sb = smem_u32(gsm);

    const int tid = threadIdx.x;
    const int wid = tid >> 5;
    const int l   = tid & 31;
    const int wm  = wid >> 2;
    const int wn  = wid & 3;
    const int bm  = blockIdx.y * 128;
    const int bn  = blockIdx.x * 128;

    const int a_row = l & 15;
    const int a_col = (l >> 4) * 8;
    const int b_row = (l & 7) + ((l >> 4) & 1) * 8;
    const int b_col = ((l >> 3) & 1) * 8;
    const int axor  = (a_row >> 1) & 3;
    const int bxor  = (b_row >> 1) & 3;

    auto prefetch = [&](int kt, int st) {
#pragma unroll
        for (int i = 0; i < 8; i++) {
            const int c   = i * 256 + tid;
            const int arr = c >> 9;
            const int r   = (c >> 2) & 127;
            const int c16 = c & 3;
            const int off = r * 32 + ((c16 ^ ((r >> 1) & 3)) << 3);
            const uint32_t sa = sb + 2 * (st * GSTG + arr * GAS + off);
            const __nv_bfloat16* g;
            if (arr == 0)      g = Ahg + (size_t)(bm + r) * K + kt + c16 * 8;
            else if (arr == 1) g = Alg + (size_t)(bm + r) * K + kt + c16 * 8;
            else if (arr == 2) g = Bhg + (size_t)(bn + r) * K + kt + c16 * 8;
            else               g = Blg + (size_t)(bn + r) * K + kt + c16 * 8;
            cp16(sa, g);
        }
        cp_commit();
    };

    float acc[4][4][4];
#pragma unroll
    for (int i = 0; i < 4; i++)
#pragma unroll
        for (int j = 0; j < 4; j++)
#pragma unroll
            for (int t = 0; t < 4; t++) acc[i][j][t] = 0.f;

    const int nk = K / 32;                  // 24
    prefetch(0, 0);
    prefetch(32, 1);

    for (int it = 0; it < nk; it++) {
        const int st = it % 3;
        if (it + 1 < nk) cp_wait1();
        else             cp_wait0();
        __syncthreads();
        if (it + 2 < nk) prefetch((it + 2) * 32, (it + 2) % 3);

        const uint32_t uAh = sb + 2 * (st * GSTG + 0 * GAS);
        const uint32_t uAl = sb + 2 * (st * GSTG + 1 * GAS);
        const uint32_t uBh = sb + 2 * (st * GSTG + 2 * GAS);
        const uint32_t uBl = sb + 2 * (st * GSTG + 3 * GAS);

#pragma unroll
        for (int kh = 0; kh < 2; kh++) {
            const int kc = kh * 16;
            const int ac = ((kc + a_col) >> 3) ^ axor;
            const int bc = ((kc + b_col) >> 3) ^ bxor;
            uint32_t af[4][4], bfh[4][2], bfl[4][2];
#pragma unroll
            for (int ti = 0; ti < 4; ti++)
                ldm4(af[ti], uAh + 2 * ((wm * 64 + ti * 16 + a_row) * 32 + ac * 8));
#pragma unroll
            for (int bp = 0; bp < 2; bp++) {
                uint32_t r4[4];
                ldm4(r4, uBh + 2 * ((wn * 32 + bp * 16 + b_row) * 32 + bc * 8));
                bfh[bp * 2 + 0][0] = r4[0]; bfh[bp * 2 + 0][1] = r4[1];
                bfh[bp * 2 + 1][0] = r4[2]; bfh[bp * 2 + 1][1] = r4[3];
            }
#pragma unroll
            for (int bp = 0; bp < 2; bp++) {
                uint32_t r4[4];
                ldm4(r4, uBl + 2 * ((wn * 32 + bp * 16 + b_row) * 32 + bc * 8));
                bfl[bp * 2 + 0][0] = r4[0]; bfl[bp * 2 + 0][1] = r4[1];
                bfl[bp * 2 + 1][0] = r4[2]; bfl[bp * 2 + 1][1] = r4[3];
            }
#pragma unroll
            for (int ti = 0; ti < 4; ti++)
#pragma unroll
                for (int nj = 0; nj < 4; nj++)
                    mma_bf16(acc[ti][nj], af[ti], bfh[nj]);
#pragma unroll
            for (int ti = 0; ti < 4; ti++)
#pragma unroll
                for (int nj = 0; nj < 4; nj++)
                    mma_bf16(acc[ti][nj], af[ti], bfl[nj]);
#pragma unroll
            for (int ti = 0; ti < 4; ti++)
                ldm4(af[ti], uAl + 2 * ((wm * 64 + ti * 16 + a_row) * 32 + ac * 8));
#pragma unroll
            for (int ti = 0; ti < 4; ti++)
#pragma unroll
                for (int nj = 0; nj < 4; nj++)
                    mma_bf16(acc[ti][nj], af[ti], bfh[nj]);
        }
    }

    const int row_in = l >> 2;
    const int col_in = (l & 3) * 2;
    const int col0base = bn + wn * 32;

    if (MODE == 0 || bn >= 2 * 768) {
        // plain fp32 + bias store (proj output, or V band of QKV)
#pragma unroll
        for (int ti = 0; ti < 4; ti++) {
#pragma unroll
            for (int nj = 0; nj < 4; nj++) {
                const int col = col0base + nj * 8 + col_in;
                const float b0 = bias[col], b1 = bias[col + 1];
                const int r0 = bm + wm * 64 + ti * 16 + row_in;
                float2 v0 = { acc[ti][nj][0] + b0, acc[ti][nj][1] + b1 };
                float2 v1 = { acc[ti][nj][2] + b0, acc[ti][nj][3] + b1 };
                *(float2*)(Cout + (size_t)r0 * N + col) = v0;
                *(float2*)(Cout + (size_t)(r0 + 8) * N + col) = v1;
            }
        }
    } else {
        // Q/K band: RoPE via table, stage in smem, coalesced store.
        __syncthreads();   // retire mainloop smem (CTA-uniform branch)

        const int s    = col0base / 768;
        const int head = (col0base % 768) / 64;
        const int half = (col0base % 64) >> 5;
        __nv_bfloat16* dh = s ? Kh : Qh;
        __nv_bfloat16* dl = s ? Kl : Ql;
        const float qs = s ? 1.0f : 0.125f;

        __nv_bfloat16* sth = gsm + wid * 2048;            // 64 rows x 32 halfs
        __nv_bfloat16* stl = gsm + 8 * 2048 + wid * 2048;

#pragma unroll
        for (int nj = 0; nj < 2; nj++) {
            const int jj  = nj * 8 + col_in;
            const int k0  = jj >> 1;
            const int jcol = col0base + jj;
            const float bA0 = bias[jcol],      bA1 = bias[jcol + 1];
            const float bB0 = bias[jcol + 16], bB1 = bias[jcol + 17];
#pragma unroll
            for (int ti = 0; ti < 4; ti++) {
#pragma unroll
                for (int kk = 0; kk < 4; kk++) {
                    const int lrow = ti * 16 + row_in + (kk >> 1) * 8;   // 0..63
                    const int j    = jj + (kk & 1);
                    const float t0 = acc[ti][nj][kk]     + ((kk & 1) ? bA1 : bA0);
                    const float t1 = acc[ti][nj + 2][kk] + ((kk & 1) ? bB1 : bB0);
                    const int n   = (bm + wm * 64 + lrow) & 1023;
                    const int pos = half ? (n & 31) : (n >> 5);
                    const float2 cs0 = g_rope[k0][pos];
                    const float2 cs1 = g_rope[k0 + 8][pos];
                    const float o0 = (t0 * cs0.x - t1 * cs0.y) * qs;
                    const float o1 = (t1 * cs1.x + t0 * cs1.y) * qs;
                    sth[lrow * 32 + j]      = __float2bfloat16(o0);
                    sth[lrow * 32 + j + 16] = __float2bfloat16(o1);
                    stl[lrow * 32 + j]      =
                        __float2bfloat16(o0 - __bfloat162float(__float2bfloat16(o0)));
                    stl[lrow * 32 + j + 16] =
                        __float2bfloat16(o1 - __bfloat162float(__float2bfloat16(o1)));
                }
            }
        }
        __syncwarp();

        // coalesced copy-out: 64 rows x 64B per warp band (hi and lo)
        const int r0g   = bm + wm * 64;
        const int bbW   = r0g >> 10;
        const int nbase = r0g & 1023;
        const size_t gbase = (((size_t)(bbW * 12 + head) * N_) + nbase) * 64
                             + half * 32;
#pragma unroll
        for (int i = 0; i < 8; i++) {
            const int idx = i * 32 + l;
            const int rr  = idx >> 2;
            const int c4  = idx & 3;
            *(uint4*)&dh[gbase + (size_t)rr * 64 + c4 * 8] =
                *(const uint4*)&sth[rr * 32 + c4 * 8];
            *(uint4*)&dl[gbase + (size_t)rr * 64 + c4 * 8] =
                *(const uint4*)&stl[rr * 32 + c4 * 8];
        }
    }
}

// ---------------------------------------------------------------------------
// V transpose + split (reads V third of g_qkv)
// ---------------------------------------------------------------------------
__global__ void v_split_kernel(const float* __restrict__ qkv,
                               __nv_bfloat16* __restrict__ Vh,
                               __nv_bfloat16* __restrict__ Vl)
{
    __shared__ float ts[64][65];
    const int tid = threadIdx.x;
    const int n0 = blockIdx.x * 64;
    const int h  = blockIdx.y;
    const int b  = blockIdx.z;
    const int bh = b * 12 + h;

#pragma unroll
    for (int i = 0; i < 16; i++) {
        const int li = i * 256 + tid;
        const int r = li >> 6, c = li & 63;
        ts[r][c] = qkv[(size_t)(b * N_ + n0 + r) * QKV_N + 1536 + h * 64 + c];
    }
    __syncthreads();
#pragma unroll
    for (int i = 0; i < 8; i++) {
        const int li = i * 256 + tid;
        const int d = li >> 5, c2 = (li & 31) * 2;
        const float v0 = ts[c2][d], v1 = ts[c2 + 1][d];
        const __nv_bfloat16 h0 = __float2bfloat16(v0);
        const __nv_bfloat16 h1 = __float2bfloat16(v1);
        const size_t ob = ((size_t)bh * 64 + d) * N_ + n0 + c2;
        *(uint32_t*)&Vh[ob] =
            ((uint32_t)__bfloat16_as_ushort(h1) << 16) | __bfloat16_as_ushort(h0);
        *(uint32_t*)&Vl[ob] =
            pack2_bf16(v0 - __bfloat162float(h0), v1 - __bfloat162float(h1));
    }
}

// ---------------------------------------------------------------------------
// Tensor-core flash attention (unchanged from R13 — proven)
// ---------------------------------------------------------------------------
#define AAS2 (64 * 64)               // 4096 halfs per array
#define ASTG (4 * AAS2)              // 16384 halfs per stage
#define ATT_SMEM (3 * ASTG * 2)      // 98304 B

__global__ __launch_bounds__(256, 2) void attn_mma_kernel(
    const __nv_bfloat16* __restrict__ Qh, const __nv_bfloat16* __restrict__ Ql,
    const __nv_bfloat16* __restrict__ Kh, const __nv_bfloat16* __restrict__ Kl,
    const __nv_bfloat16* __restrict__ Vh, const __nv_bfloat16* __restrict__ Vl,
    __nv_bfloat16* __restrict__ oh, __nv_bfloat16* __restrict__ ol)
{
    extern __shared__ __nv_bfloat16 smh[];
    const uint32_t sb = smem_u32(smh);

    const int tid = threadIdx.x;
    const int wid = tid >> 5;
    const int l   = tid & 31;
    const int qb  = blockIdx.x;
    const int h   = blockIdx.y;
    const int b   = blockIdx.z;
    const int bh  = b * H_ + h;
    const int q0  = qb * 128;
    const int wrow = wid * 16;

    const int b_row = (l & 7) + ((l >> 4) & 1) * 8;
    const int b_col = ((l >> 3) & 1) * 8;
    const int bxor8 = b_row & 7;

    const uint32_t* q32h = (const uint32_t*)(Qh + ((size_t)bh * N_ + q0) * 64);
    const uint32_t* q32l = (const uint32_t*)(Ql + ((size_t)bh * N_ + q0) * 64);
    uint32_t qfh[4][4], qfl[4][4];
    {
        const int r0 = wrow + (l >> 2);
        const int cb = (l & 3) * 2;
#pragma unroll
        for (int t = 0; t < 4; t++) {
            const int c0 = t * 16 + cb;
            qfh[t][0] = q32h[(r0 * 64 + c0) >> 1];
            qfh[t][1] = q32h[((r0 + 8) * 64 + c0) >> 1];
            qfh[t][2] = q32h[(r0 * 64 + c0 + 8) >> 1];
            qfh[t][3] = q32h[((r0 + 8) * 64 + c0 + 8) >> 1];
            qfl[t][0] = q32l[(r0 * 64 + c0) >> 1];
            qfl[t][1] = q32l[((r0 + 8) * 64 + c0) >> 1];
            qfl[t][2] = q32l[(r0 * 64 + c0 + 8) >> 1];
            qfl[t][3] = q32l[((r0 + 8) * 64 + c0 + 8) >> 1];
        }
    }

    const __nv_bfloat16* gKh = Kh + (size_t)bh * N_ * 64;
    const __nv_bfloat16* gKl = Kl + (size_t)bh * N_ * 64;
    const __nv_bfloat16* gVh = Vh + (size_t)bh * 64 * N_;
    const __nv_bfloat16* gVl = Vl + (size_t)bh * 64 * N_;

    auto prefetch = [&](int kb, int st) {
#pragma unroll
        for (int i = 0; i < 8; i++) {
            const int c   = i * 256 + tid;
            const int arr = c >> 9;
            const int r   = (c >> 3) & 63;
            const int c16 = c & 7;
            const int off = r * 64 + ((c16 ^ (r & 7)) << 3);
            const uint32_t sa = sb + 2 * (st * ASTG + arr * AAS2 + off);
            const __nv_bfloat16* g;
            if (arr == 0)      g = gKh + (size_t)(kb * 64 + r) * 64 + c16 * 8;
            else if (arr == 1) g = gKl + (size_t)(kb * 64 + r) * 64 + c16 * 8;
            else if (arr == 2) g = gVh + (size_t)r * N_ + kb * 64 + c16 * 8;
            else               g = gVl + (size_t)r * N_ + kb * 64 + c16 * 8;
            cp16(sa, g);
        }
        cp_commit();
    };

    float acc[8][4];
    float mrun[2] = { -1e30f, -1e30f }, lrun[2] = { 0.f, 0.f };
#pragma unroll
    for (int j = 0; j < 8; j++)
#pragma unroll
        for (int t = 0; t < 4; t++) acc[j][t] = 0.f;

    prefetch(0, 0);
    prefetch(1, 1);

    for (int kb = 0; kb < 16; kb++) {
        const int st = kb % 3;
        if (kb + 1 < 16) cp_wait1();
        else             cp_wait0();
        __syncthreads();
        if (kb + 2 < 16) prefetch(kb + 2, (kb + 2) % 3);

        const uint32_t uKh = sb + 2 * (st * ASTG + 0 * AAS2);
        const uint32_t uKl = sb + 2 * (st * ASTG + 1 * AAS2);
        const uint32_t uVh = sb + 2 * (st * ASTG + 2 * AAS2);
        const uint32_t uVl = sb + 2 * (st * ASTG + 3 * AAS2);

        float sv[8][4];
#pragma unroll
        for (int j = 0; j < 8; j++)
#pragma unroll
            for (int t = 0; t < 4; t++) sv[j][t] = 0.f;

#pragma unroll
        for (int t = 0; t < 4; t++) {
            const int lc = ((t * 16 + b_col) >> 3);
#pragma unroll
            for (int bp = 0; bp < 4; bp++) {
                const int roff = (bp * 16 + b_row) * 64 + ((lc ^ bxor8) << 3);
                uint32_t rh[4], rl[4];
                ldm4(rh, uKh + 2 * roff);
                ldm4(rl, uKl + 2 * roff);
                mma_bf16(sv[2 * bp],     qfh[t], rh);
                mma_bf16(sv[2 * bp + 1], qfh[t], rh + 2);
                mma_bf16(sv[2 * bp],     qfl[t], rh);
                mma_bf16(sv[2 * bp + 1], qfl[t], rh + 2);
                mma_bf16(sv[2 * bp],     qfh[t], rl);
                mma_bf16(sv[2 * bp + 1], qfh[t], rl + 2);
            }
        }

#pragma unroll
        for (int i = 0; i < 2; i++) {
            float mx = -1e30f;
#pragma unroll
            for (int j = 0; j < 8; j++)
                mx = fmaxf(mx, fmaxf(sv[j][2 * i], sv[j][2 * i + 1]));
            mx = fmaxf(mx, __shfl_xor_sync(0xffffffffu, mx, 1));
            mx = fmaxf(mx, __shfl_xor_sync(0xffffffffu, mx, 2));
            const float mnew = fmaxf(mrun[i], mx);
            const float corr = __expf(mrun[i] - mnew);
            float rs = 0.f;
#pragma unroll
            for (int j = 0; j < 8; j++) {
                const float p0 = __expf(sv[j][2 * i] - mnew);
                const float p1 = __expf(sv[j][2 * i + 1] - mnew);
                sv[j][2 * i] = p0; sv[j][2 * i + 1] = p1;
                rs += p0 + p1;
            }
            rs += __shfl_xor_sync(0xffffffffu, rs, 1);
            rs += __shfl_xor_sync(0xffffffffu, rs, 2);
            lrun[i] = lrun[i] * corr + rs;
#pragma unroll
            for (int j = 0; j < 8; j++) {
                acc[j][2 * i] *= corr;
                acc[j][2 * i + 1] *= corr;
            }
            mrun[i] = mnew;
        }

        uint32_t pfh[4][4], pfl[4][4];
#pragma unroll
        for (int t = 0; t < 4; t++) {
#pragma unroll
            for (int q = 0; q < 4; q++) {
                const int j = 2 * t + (q >> 1);
                const float p0 = sv[j][(q & 1) * 2];
                const float p1 = sv[j][(q & 1) * 2 + 1];
                const __nv_bfloat16 h0 = __float2bfloat16(p0);
                const __nv_bfloat16 h1 = __float2bfloat16(p1);
                pfh[t][q] = ((uint32_t)__bfloat16_as_ushort(h1) << 16) |
                            __bfloat16_as_ushort(h0);
                pfl[t][q] = pack2_bf16(p0 - __bfloat162float(h0),
                                       p1 - __bfloat162float(h1));
            }
        }

#pragma unroll
        for (int t = 0; t < 4; t++) {
            const int lc = ((t * 16 + b_col) >> 3);
#pragma unroll
            for (int bp = 0; bp < 4; bp++) {
                const int roff = (bp * 16 + b_row) * 64 + ((lc ^ bxor8) << 3);
                uint32_t rh[4], rl[4];
                ldm4(rh, uVh + 2 * roff);
                ldm4(rl, uVl + 2 * roff);
                mma_bf16(acc[2 * bp],     pfh[t], rh);
                mma_bf16(acc[2 * bp + 1], pfh[t], rh + 2);
                mma_bf16(acc[2 * bp],     pfl[t], rh);
                mma_bf16(acc[2 * bp + 1], pfl[t], rh + 2);
                mma_bf16(acc[2 * bp],     pfh[t], rl);
                mma_bf16(acc[2 * bp + 1], pfh[t], rl + 2);
            }
        }
    }

    const float il0 = 1.f / lrun[0];
    const float il1 = 1.f / lrun[1];
    const int r0 = q0 + wrow + (l >> 2);
    const int cb = h * 64 + (l & 3) * 2;
#pragma unroll
    for (int j = 0; j < 8; j++) {
        const float a0 = acc[j][0] * il0, a1 = acc[j][1] * il0;
        const float a2 = acc[j][2] * il1, a3 = acc[j][3] * il1;
        const __nv_bfloat16 h0 = __float2bfloat16(a0);
        const __nv_bfloat16 h1 = __float2bfloat16(a1);
        const __nv_bfloat16 h2 = __float2bfloat16(a2);
        const __nv_bfloat16 h3 = __float2bfloat16(a3);
        const size_t o0 = (size_t)(b * N_ + r0) * C_ + cb + j * 8;
        const size_t o1 = (size_t)(b * N_ + r0 + 8) * C_ + cb + j * 8;
        *(uint32_t*)&oh[o0] =
            ((uint32_t)__bfloat16_as_ushort(h1) << 16) | __bfloat16_as_ushort(h0);
        *(uint32_t*)&oh[o1] =
            ((uint32_t)__bfloat16_as_ushort(h3) << 16) | __bfloat16_as_ushort(h2);
        *(uint32_t*)&ol[o0] = pack2_bf16(a0 - __bfloat162float(h0),
                                         a1 - __bfloat162float(h1));
        *(uint32_t*)&ol[o1] = pack2_bf16(a2 - __bfloat162float(h2),
                                         a3 - __bfloat162float(h3));
    }
}

// ---------------------------------------------------------------------------
extern "C" void kernel_launch(void* const* d_in, const int* in_sizes, int n_in,
                              void* d_out, int out_size)
{
    const float* x     = (const float*)d_in[0];
    const float* Wqkv  = (const float*)d_in[1];
    const float* bqkv  = (const float*)d_in[2];
    const float* Wproj = (const float*)d_in[3];
    const float* bproj = (const float*)d_in[4];
    float*       out   = (float*)d_out;

    float* qkv = nullptr;
    __nv_bfloat16 *wqh, *wql, *wph, *wpl, *ah, *al;
    __nv_bfloat16 *aQh, *aQl, *aKh, *aKl, *aVh, *aVl;
    cudaGetSymbolAddress((void**)&qkv, g_qkv);
    cudaGetSymbolAddress((void**)&wqh, g_wqkv_hi);
    cudaGetSymbolAddress((void**)&wql, g_wqkv_lo);
    cudaGetSymbolAddress((void**)&wph, g_wproj_hi);
    cudaGetSymbolAddress((void**)&wpl, g_wproj_lo);
    cudaGetSymbolAddress((void**)&ah,  g_ah);
    cudaGetSymbolAddress((void**)&al,  g_al);
    cudaGetSymbolAddress((void**)&aQh, g_Qh);
    cudaGetSymbolAddress((void**)&aQl, g_Ql);
    cudaGetSymbolAddress((void**)&aKh, g_Kh);
    cudaGetSymbolAddress((void**)&aKl, g_Kl);
    cudaGetSymbolAddress((void**)&aVh, g_Vh);
    cudaGetSymbolAddress((void**)&aVl, g_Vl);

    static bool attr_set = false;
    if (!attr_set) {
        cudaFuncSetAttribute(attn_mma_kernel,
                             cudaFuncAttributeMaxDynamicSharedMemorySize, ATT_SMEM);
        cudaFuncSetAttribute(gemm_mma_kernel<0>,
                             cudaFuncAttributeMaxDynamicSharedMemorySize, GEMM_SMEM);
        cudaFuncSetAttribute(gemm_mma_kernel<1>,
                             cudaFuncAttributeMaxDynamicSharedMemorySize, GEMM_SMEM);
        attr_set = true;
    }

    const int a_total4 = M_TOT * K_DIM / 4;

    // 0) RoPE table + weight splits + x split
    rope_init_kernel<<<1, 512>>>();
    split_w_kernel<<<dim3(QKV_N / 32, K_DIM / 32), dim3(32, 8)>>>(Wqkv, wqh, wql, K_DIM, QKV_N);
    split_w_kernel<<<dim3(C_ / 32, K_DIM / 32), dim3(32, 8)>>>(Wproj, wph, wpl, K_DIM, C_);
    split_a_kernel<<<(a_total4 + 255) / 256, 256>>>(x, ah, al, a_total4);

    // 1) QKV projection + fused RoPE/split epilogue (V -> g_qkv fp32)
    gemm_mma_kernel<1><<<dim3(QKV_N / 128, M_TOT / 128), 256, GEMM_SMEM>>>(
        ah, al, wqh, wql, bqkv, qkv, aQh, aQl, aKh, aKl, M_TOT, QKV_N, K_DIM);

    // 2) V transpose + split
    v_split_kernel<<<dim3(N_ / 64, H_, B_), 256>>>(qkv, aVh, aVl);

    // 3) Flash attention (writes split proj input into g_ah/g_al)
    attn_mma_kernel<<<dim3(N_ / 128, H_, B_), 256, ATT_SMEM>>>(
        aQh, aQl, aKh, aKl, aVh, aVl, ah, al);

    // 4) Output projection
    gemm_mma_kernel<0><<<dim3(C_ / 128, M_TOT / 128), 256, GEMM_SMEM>>>(
        ah, al, wph, wpl, bproj, out, nullptr, nullptr, nullptr, nullptr,
        M_TOT, C_, K_DIM);
}

// round 15
// speedup vs baseline: 2.9440x; 1.0120x over previous
#include <cuda_runtime.h>
#include <cuda_bf16.h>
#include <cstdint>

#define B_    16
#define N_    1024
#define C_    768
#define H_    12
#define M_TOT (B_ * N_)        // 16384
#define QKV_N (3 * C_)         // 2304
#define K_DIM 768
#define BH_   (B_ * H_)        // 192

// ---------------------------------------------------------------------------
// Scratch (__device__ globals only)
// ---------------------------------------------------------------------------
__device__ __align__(16) float2 g_rope[16][32];                 // (cos,sin)[k][pos]
__device__ __align__(16) __nv_bfloat16 g_wqkv_hi[(size_t)QKV_N * K_DIM];
__device__ __align__(16) __nv_bfloat16 g_wqkv_lo[(size_t)QKV_N * K_DIM];
__device__ __align__(16) __nv_bfloat16 g_wproj_hi[(size_t)C_ * K_DIM];
__device__ __align__(16) __nv_bfloat16 g_wproj_lo[(size_t)C_ * K_DIM];
__device__ __align__(16) __nv_bfloat16 g_ah[(size_t)M_TOT * K_DIM];
__device__ __align__(16) __nv_bfloat16 g_al[(size_t)M_TOT * K_DIM];
__device__ __align__(16) __nv_bfloat16 g_Qh[(size_t)BH_ * N_ * 64];
__device__ __align__(16) __nv_bfloat16 g_Ql[(size_t)BH_ * N_ * 64];
__device__ __align__(16) __nv_bfloat16 g_Kh[(size_t)BH_ * N_ * 64];
__device__ __align__(16) __nv_bfloat16 g_Kl[(size_t)BH_ * N_ * 64];
__device__ __align__(16) __nv_bfloat16 g_Vh[(size_t)BH_ * 64 * N_];
__device__ __align__(16) __nv_bfloat16 g_Vl[(size_t)BH_ * 64 * N_];

// ---------------------------------------------------------------------------
// helpers
// ---------------------------------------------------------------------------
__device__ __forceinline__ uint32_t smem_u32(const void* p) {
    uint32_t a;
    asm("{ .reg .u64 t; cvta.to.shared.u64 t, %1; cvt.u32.u64 %0, t; }"
        : "=r"(a) : "l"(p));
    return a;
}
__device__ __forceinline__ void ldm4(uint32_t* r, uint32_t addr) {
    asm volatile("ldmatrix.sync.aligned.m8n8.x4.shared.b16 {%0,%1,%2,%3}, [%4];"
                 : "=r"(r[0]), "=r"(r[1]), "=r"(r[2]), "=r"(r[3]) : "r"(addr));
}
__device__ __forceinline__ void mma_bf16(float* c, const uint32_t* a, const uint32_t* b) {
    asm volatile("mma.sync.aligned.m16n8k16.row.col.f32.bf16.bf16.f32 "
                 "{%0,%1,%2,%3}, {%4,%5,%6,%7}, {%8,%9}, {%0,%1,%2,%3};"
                 : "+f"(c[0]), "+f"(c[1]), "+f"(c[2]), "+f"(c[3])
                 : "r"(a[0]), "r"(a[1]), "r"(a[2]), "r"(a[3]),
                   "r"(b[0]), "r"(b[1]));
}
__device__ __forceinline__ void cp16(uint32_t sa, const void* g) {
    asm volatile("cp.async.cg.shared.global [%0], [%1], 16;" :: "r"(sa), "l"(g));
}
__device__ __forceinline__ void cp_commit() {
    asm volatile("cp.async.commit_group;" ::: "memory");
}
__device__ __forceinline__ void cp_wait1() {
    asm volatile("cp.async.wait_group 1;" ::: "memory");
}
__device__ __forceinline__ void cp_wait0() {
    asm volatile("cp.async.wait_group 0;" ::: "memory");
}
__device__ __forceinline__ uint32_t pack2_bf16(float a, float b) {
    return ((uint32_t)__bfloat16_as_ushort(__float2bfloat16(b)) << 16) |
           (uint32_t)__bfloat16_as_ushort(__float2bfloat16(a));
}

// ---------------------------------------------------------------------------
// RoPE table init (bit-identical expressions to the in-epilogue math)
// ---------------------------------------------------------------------------
__global__ void rope_init_kernel() {
    const int idx = threadIdx.x;           // 0..511
    const int k = idx >> 5, pos = idx & 31;
    const float L = 9.210340371976184f / 16.0f;
    const float ang = (float)pos * expf(-L * (float)k);
    float s, c;
    sincosf(ang, &s, &c);
    g_rope[k][pos] = make_float2(c, s);
}

// ---------------------------------------------------------------------------
// Weight prep: W [K,N] fp32 -> hi/lo bf16 [N,K]
// ---------------------------------------------------------------------------
__global__ void split_w_kernel(const float* __restrict__ W,
                               __nv_bfloat16* __restrict__ hi,
                               __nv_bfloat16* __restrict__ lo,
                               int K, int N) {
    __shared__ float t[32][33];
    const int tx = threadIdx.x, ty = threadIdx.y;
    const int n0 = blockIdx.x * 32, k0 = blockIdx.y * 32;
#pragma unroll
    for (int j = 0; j < 4; j++) {
        const int k = k0 + ty + j * 8;
        t[ty + j * 8][tx] = W[(size_t)k * N + n0 + tx];
    }
    __syncthreads();
#pragma unroll
    for (int j = 0; j < 4; j++) {
        const int n = n0 + ty + j * 8;
        const int k = k0 + tx;
        const float w = t[tx][ty + j * 8];
        const __nv_bfloat16 h = __float2bfloat16(w);
        hi[(size_t)n * K + k] = h;
        lo[(size_t)n * K + k] = __float2bfloat16(w - __bfloat162float(h));
    }
}

// ---------------------------------------------------------------------------
// Activation split
// ---------------------------------------------------------------------------
__global__ void split_a_kernel(const float* __restrict__ A,
                               __nv_bfloat16* __restrict__ hi,
                               __nv_bfloat16* __restrict__ lo,
                               int total4)
{
    const int i = blockIdx.x * blockDim.x + threadIdx.x;
    if (i >= total4) return;
    const float4 v = ((const float4*)A)[i];
    const __nv_bfloat16 h0 = __float2bfloat16(v.x);
    const __nv_bfloat16 h1 = __float2bfloat16(v.y);
    const __nv_bfloat16 h2 = __float2bfloat16(v.z);
    const __nv_bfloat16 h3 = __float2bfloat16(v.w);
    uint2 hp, lp;
    hp.x = ((uint32_t)__bfloat16_as_ushort(h1) << 16) | __bfloat16_as_ushort(h0);
    hp.y = ((uint32_t)__bfloat16_as_ushort(h3) << 16) | __bfloat16_as_ushort(h2);
    lp.x = pack2_bf16(v.x - __bfloat162float(h0), v.y - __bfloat162float(h1));
    lp.y = pack2_bf16(v.z - __bfloat162float(h2), v.w - __bfloat162float(h3));
    ((uint2*)hi)[i] = hp;
    ((uint2*)lo)[i] = lp;
}

// ---------------------------------------------------------------------------
// bf16x3 HMMA GEMM, XOR-swizzled smem, 3-stage cp.async, one sync/iter.
// MODE 0: fp32 out + bias (proj).
// MODE 1: QKV fused epilogue — Q/K bands: RoPE + split (smem-staged);
//         V band: transpose + split (smem-staged) directly to g_V layout.
// Branches are CTA-uniform (1536 is a multiple of 128).
// ---------------------------------------------------------------------------
#define GAS (128 * 32)               // 4096 halfs per array
#define GSTG (4 * GAS)               // 16384 halfs per stage
#define GEMM_SMEM (3 * GSTG * 2)     // 98304 B
#define VST 72                       // V-stage smem stride (halfs)

template <int MODE>
__global__ __launch_bounds__(256, 2) void gemm_mma_kernel(
    const __nv_bfloat16* __restrict__ Ahg, const __nv_bfloat16* __restrict__ Alg,
    const __nv_bfloat16* __restrict__ Bhg, const __nv_bfloat16* __restrict__ Blg,
    const float* __restrict__ bias, float* __restrict__ Cout,
    __nv_bfloat16* __restrict__ Qh, __nv_bfloat16* __restrict__ Ql,
    __nv_bfloat16* __restrict__ Kh, __nv_bfloat16* __restrict__ Kl,
    __nv_bfloat16* __restrict__ Vh, __nv_bfloat16* __restrict__ Vl,
    int M, int N, int K)
{
    extern __shared__ __nv_bfloat16 gsm[];
    const uint32_t sb = smem_u32(gsm);

    const int tid = threadIdx.x;
    const int wid = tid >> 5;
    const int l   = tid & 31;
    const int wm  = wid >> 2;
    const int wn  = wid & 3;
    const int bm  = blockIdx.y * 128;
    const int bn  = blockIdx.x * 128;

    const int a_row = l & 15;
    const int a_col = (l >> 4) * 8;
    const int b_row = (l & 7) + ((l >> 4) & 1) * 8;
    const int b_col = ((l >> 3) & 1) * 8;
    const int axor  = (a_row >> 1) & 3;
    const int bxor  = (b_row >> 1) & 3;

    auto prefetch = [&](int kt, int st) {
#pragma unroll
        for (int i = 0; i < 8; i++) {
            const int c   = i * 256 + tid;
            const int arr = c >> 9;
            const int r   = (c >> 2) & 127;
            const int c16 = c & 3;
            const int off = r * 32 + ((c16 ^ ((r >> 1) & 3)) << 3);
            const uint32_t sa = sb + 2 * (st * GSTG + arr * GAS + off);
            const __nv_bfloat16* g;
            if (arr == 0)      g = Ahg + (size_t)(bm + r) * K + kt + c16 * 8;
            else if (arr == 1) g = Alg + (size_t)(bm + r) * K + kt + c16 * 8;
            else if (arr == 2) g = Bhg + (size_t)(bn + r) * K + kt + c16 * 8;
            else               g = Blg + (size_t)(bn + r) * K + kt + c16 * 8;
            cp16(sa, g);
        }
        cp_commit();
    };

    float acc[4][4][4];
#pragma unroll
    for (int i = 0; i < 4; i++)
#pragma unroll
        for (int j = 0; j < 4; j++)
#pragma unroll
            for (int t = 0; t < 4; t++) acc[i][j][t] = 0.f;

    const int nk = K / 32;                  // 24
    prefetch(0, 0);
    prefetch(32, 1);

    for (int it = 0; it < nk; it++) {
        const int st = it % 3;
        if (it + 1 < nk) cp_wait1();
        else             cp_wait0();
        __syncthreads();
        if (it + 2 < nk) prefetch((it + 2) * 32, (it + 2) % 3);

        const uint32_t uAh = sb + 2 * (st * GSTG + 0 * GAS);
        const uint32_t uAl = sb + 2 * (st * GSTG + 1 * GAS);
        const uint32_t uBh = sb + 2 * (st * GSTG + 2 * GAS);
        const uint32_t uBl = sb + 2 * (st * GSTG + 3 * GAS);

#pragma unroll
        for (int kh = 0; kh < 2; kh++) {
            const int kc = kh * 16;
            const int ac = ((kc + a_col) >> 3) ^ axor;
            const int bc = ((kc + b_col) >> 3) ^ bxor;
            uint32_t af[4][4], bfh[4][2], bfl[4][2];
#pragma unroll
            for (int ti = 0; ti < 4; ti++)
                ldm4(af[ti], uAh + 2 * ((wm * 64 + ti * 16 + a_row) * 32 + ac * 8));
#pragma unroll
            for (int bp = 0; bp < 2; bp++) {
                uint32_t r4[4];
                ldm4(r4, uBh + 2 * ((wn * 32 + bp * 16 + b_row) * 32 + bc * 8));
                bfh[bp * 2 + 0][0] = r4[0]; bfh[bp * 2 + 0][1] = r4[1];
                bfh[bp * 2 + 1][0] = r4[2]; bfh[bp * 2 + 1][1] = r4[3];
            }
#pragma unroll
            for (int bp = 0; bp < 2; bp++) {
                uint32_t r4[4];
                ldm4(r4, uBl + 2 * ((wn * 32 + bp * 16 + b_row) * 32 + bc * 8));
                bfl[bp * 2 + 0][0] = r4[0]; bfl[bp * 2 + 0][1] = r4[1];
                bfl[bp * 2 + 1][0] = r4[2]; bfl[bp * 2 + 1][1] = r4[3];
            }
#pragma unroll
            for (int ti = 0; ti < 4; ti++)
#pragma unroll
                for (int nj = 0; nj < 4; nj++)
                    mma_bf16(acc[ti][nj], af[ti], bfh[nj]);
#pragma unroll
            for (int ti = 0; ti < 4; ti++)
#pragma unroll
                for (int nj = 0; nj < 4; nj++)
                    mma_bf16(acc[ti][nj], af[ti], bfl[nj]);
#pragma unroll
            for (int ti = 0; ti < 4; ti++)
                ldm4(af[ti], uAl + 2 * ((wm * 64 + ti * 16 + a_row) * 32 + ac * 8));
#pragma unroll
            for (int ti = 0; ti < 4; ti++)
#pragma unroll
                for (int nj = 0; nj < 4; nj++)
                    mma_bf16(acc[ti][nj], af[ti], bfh[nj]);
        }
    }

    const int row_in = l >> 2;
    const int col_in = (l & 3) * 2;
    const int col0base = bn + wn * 32;

    if (MODE == 0) {
        // proj: plain fp32 + bias store
#pragma unroll
        for (int ti = 0; ti < 4; ti++) {
#pragma unroll
            for (int nj = 0; nj < 4; nj++) {
                const int col = col0base + nj * 8 + col_in;
                const float b0 = bias[col], b1 = bias[col + 1];
                const int r0 = bm + wm * 64 + ti * 16 + row_in;
                float2 v0 = { acc[ti][nj][0] + b0, acc[ti][nj][1] + b1 };
                float2 v1 = { acc[ti][nj][2] + b0, acc[ti][nj][3] + b1 };
                *(float2*)(Cout + (size_t)r0 * N + col) = v0;
                *(float2*)(Cout + (size_t)(r0 + 8) * N + col) = v1;
            }
        }
    } else if (bn >= 2 * 768) {
        // V band: bias + transpose + hi/lo split, smem-staged, coalesced out.
        __syncthreads();   // retire mainloop smem (CTA-uniform branch)

        const int vcol  = col0base - 1536;        // 0..767
        const int head  = vcol / 64;
        const int dstart = vcol & 63;             // 0 or 32

        __nv_bfloat16* sth = gsm + wid * (32 * VST);
        __nv_bfloat16* stl = gsm + 8 * (32 * VST) + wid * (32 * VST);

#pragma unroll
        for (int nj = 0; nj < 4; nj++) {
            const int jcol = col0base + nj * 8 + col_in;
            const float bV0 = bias[jcol], bV1 = bias[jcol + 1];
#pragma unroll
            for (int ti = 0; ti < 4; ti++) {
#pragma unroll
                for (int kk = 0; kk < 4; kk++) {
                    const int d_in = nj * 8 + col_in + (kk & 1);       // 0..31
                    const int lrow = ti * 16 + row_in + (kk >> 1) * 8; // 0..63
                    const float v = acc[ti][nj][kk] + ((kk & 1) ? bV1 : bV0);
                    const __nv_bfloat16 h = __float2bfloat16(v);
                    sth[d_in * VST + lrow] = h;
                    stl[d_in * VST + lrow] =
                        __float2bfloat16(v - __bfloat162float(h));
                }
            }
        }
        __syncwarp();

        // coalesced copy-out: 32 d-rows x 128B per warp (hi and lo)
        const int r0g   = bm + wm * 64;
        const int bbW   = r0g >> 10;
        const int nbase = r0g & 1023;
        const size_t dbase = (size_t)(bbW * 12 + head) * 64 + dstart;
#pragma unroll
        for (int i = 0; i < 8; i++) {
            const int idx = i * 32 + l;
            const int rr  = idx >> 3;
            const int c   = idx & 7;
            *(uint4*)&Vh[(dbase + rr) * N_ + nbase + c * 8] =
                *(const uint4*)&sth[rr * VST + c * 8];
            *(uint4*)&Vl[(dbase + rr) * N_ + nbase + c * 8] =
                *(const uint4*)&stl[rr * VST + c * 8];
        }
    } else {
        // Q/K band: RoPE via table, stage in smem, coalesced store.
        __syncthreads();   // retire mainloop smem (CTA-uniform branch)

        const int s    = col0base / 768;
        const int head = (col0base % 768) / 64;
        const int half = (col0base % 64) >> 5;
        __nv_bfloat16* dh = s ? Kh : Qh;
        __nv_bfloat16* dl = s ? Kl : Ql;
        const float qs = s ? 1.0f : 0.125f;

        __nv_bfloat16* sth = gsm + wid * 2048;            // 64 rows x 32 halfs
        __nv_bfloat16* stl = gsm + 8 * 2048 + wid * 2048;

#pragma unroll
        for (int nj = 0; nj < 2; nj++) {
            const int jj  = nj * 8 + col_in;
            const int k0  = jj >> 1;
            const int jcol = col0base + jj;
            const float bA0 = bias[jcol],      bA1 = bias[jcol + 1];
            const float bB0 = bias[jcol + 16], bB1 = bias[jcol + 17];
#pragma unroll
            for (int ti = 0; ti < 4; ti++) {
#pragma unroll
                for (int kk = 0; kk < 4; kk++) {
                    const int lrow = ti * 16 + row_in + (kk >> 1) * 8;   // 0..63
                    const int j    = jj + (kk & 1);
                    const float t0 = acc[ti][nj][kk]     + ((kk & 1) ? bA1 : bA0);
                    const float t1 = acc[ti][nj + 2][kk] + ((kk & 1) ? bB1 : bB0);
                    const int n   = (bm + wm * 64 + lrow) & 1023;
                    const int pos = half ? (n & 31) : (n >> 5);
                    const float2 cs0 = g_rope[k0][pos];
                    const float2 cs1 = g_rope[k0 + 8][pos];
                    const float o0 = (t0 * cs0.x - t1 * cs0.y) * qs;
                    const float o1 = (t1 * cs1.x + t0 * cs1.y) * qs;
                    sth[lrow * 32 + j]      = __float2bfloat16(o0);
                    sth[lrow * 32 + j + 16] = __float2bfloat16(o1);
                    stl[lrow * 32 + j]      =
                        __float2bfloat16(o0 - __bfloat162float(__float2bfloat16(o0)));
                    stl[lrow * 32 + j + 16] =
                        __float2bfloat16(o1 - __bfloat162float(__float2bfloat16(o1)));
                }
            }
        }
        __syncwarp();

        const int r0g   = bm + wm * 64;
        const int bbW   = r0g >> 10;
        const int nbase = r0g & 1023;
        const size_t gbase = (((size_t)(bbW * 12 + head) * N_) + nbase) * 64
                             + half * 32;
#pragma unroll
        for (int i = 0; i < 8; i++) {
            const int idx = i * 32 + l;
            const int rr  = idx >> 2;
            const int c4  = idx & 3;
            *(uint4*)&dh[gbase + (size_t)rr * 64 + c4 * 8] =
                *(const uint4*)&sth[rr * 32 + c4 * 8];
            *(uint4*)&dl[gbase + (size_t)rr * 64 + c4 * 8] =
                *(const uint4*)&stl[rr * 32 + c4 * 8];
        }
    }
}

// ---------------------------------------------------------------------------
// Tensor-core flash attention (unchanged from R13/14 — proven)
// ---------------------------------------------------------------------------
#define AAS2 (64 * 64)               // 4096 halfs per array
#define ASTG (4 * AAS2)              // 16384 halfs per stage
#define ATT_SMEM (3 * ASTG * 2)      // 98304 B

__global__ __launch_bounds__(256, 2) void attn_mma_kernel(
    const __nv_bfloat16* __restrict__ Qh, const __nv_bfloat16* __restrict__ Ql,
    const __nv_bfloat16* __restrict__ Kh, const __nv_bfloat16* __restrict__ Kl,
    const __nv_bfloat16* __restrict__ Vh, const __nv_bfloat16* __restrict__ Vl,
    __nv_bfloat16* __restrict__ oh, __nv_bfloat16* __restrict__ ol)
{
    extern __shared__ __nv_bfloat16 smh[];
    const uint32_t sb = smem_u32(smh);

    const int tid = threadIdx.x;
    const int wid = tid >> 5;
    const int l   = tid & 31;
    const int qb  = blockIdx.x;
    const int h   = blockIdx.y;
    const int b   = blockIdx.z;
    const int bh  = b * H_ + h;
    const int q0  = qb * 128;
    const int wrow = wid * 16;

    const int b_row = (l & 7) + ((l >> 4) & 1) * 8;
    const int b_col = ((l >> 3) & 1) * 8;
    const int bxor8 = b_row & 7;

    const uint32_t* q32h = (const uint32_t*)(Qh + ((size_t)bh * N_ + q0) * 64);
    const uint32_t* q32l = (const uint32_t*)(Ql + ((size_t)bh * N_ + q0) * 64);
    uint32_t qfh[4][4], qfl[4][4];
    {
        const int r0 = wrow + (l >> 2);
        const int cb = (l & 3) * 2;
#pragma unroll
        for (int t = 0; t < 4; t++) {
            const int c0 = t * 16 + cb;
            qfh[t][0] = q32h[(r0 * 64 + c0) >> 1];
            qfh[t][1] = q32h[((r0 + 8) * 64 + c0) >> 1];
            qfh[t][2] = q32h[(r0 * 64 + c0 + 8) >> 1];
            qfh[t][3] = q32h[((r0 + 8) * 64 + c0 + 8) >> 1];
            qfl[t][0] = q32l[(r0 * 64 + c0) >> 1];
            qfl[t][1] = q32l[((r0 + 8) * 64 + c0) >> 1];
            qfl[t][2] = q32l[(r0 * 64 + c0 + 8) >> 1];
            qfl[t][3] = q32l[((r0 + 8) * 64 + c0 + 8) >> 1];
        }
    }

    const __nv_bfloat16* gKh = Kh + (size_t)bh * N_ * 64;
    const __nv_bfloat16* gKl = Kl + (size_t)bh * N_ * 64;
    const __nv_bfloat16* gVh = Vh + (size_t)bh * 64 * N_;
    const __nv_bfloat16* gVl = Vl + (size_t)bh * 64 * N_;

    auto prefetch = [&](int kb, int st) {
#pragma unroll
        for (int i = 0; i < 8; i++) {
            const int c   = i * 256 + tid;
            const int arr = c >> 9;
            const int r   = (c >> 3) & 63;
            const int c16 = c & 7;
            const int off = r * 64 + ((c16 ^ (r & 7)) << 3);
            const uint32_t sa = sb + 2 * (st * ASTG + arr * AAS2 + off);
            const __nv_bfloat16* g;
            if (arr == 0)      g = gKh + (size_t)(kb * 64 + r) * 64 + c16 * 8;
            else if (arr == 1) g = gKl + (size_t)(kb * 64 + r) * 64 + c16 * 8;
            else if (arr == 2) g = gVh + (size_t)r * N_ + kb * 64 + c16 * 8;
            else               g = gVl + (size_t)r * N_ + kb * 64 + c16 * 8;
            cp16(sa, g);
        }
        cp_commit();
    };

    float acc[8][4];
    float mrun[2] = { -1e30f, -1e30f }, lrun[2] = { 0.f, 0.f };
#pragma unroll
    for (int j = 0; j < 8; j++)
#pragma unroll
        for (int t = 0; t < 4; t++) acc[j][t] = 0.f;

    prefetch(0, 0);
    prefetch(1, 1);

    for (int kb = 0; kb < 16; kb++) {
        const int st = kb % 3;
        if (kb + 1 < 16) cp_wait1();
        else             cp_wait0();
        __syncthreads();
        if (kb + 2 < 16) prefetch(kb + 2, (kb + 2) % 3);

        const uint32_t uKh = sb + 2 * (st * ASTG + 0 * AAS2);
        const uint32_t uKl = sb + 2 * (st * ASTG + 1 * AAS2);
        const uint32_t uVh = sb + 2 * (st * ASTG + 2 * AAS2);
        const uint32_t uVl = sb + 2 * (st * ASTG + 3 * AAS2);

        float sv[8][4];
#pragma unroll
        for (int j = 0; j < 8; j++)
#pragma unroll
            for (int t = 0; t < 4; t++) sv[j][t] = 0.f;

#pragma unroll
        for (int t = 0; t < 4; t++) {
            const int lc = ((t * 16 + b_col) >> 3);
#pragma unroll
            for (int bp = 0; bp < 4; bp++) {
                const int roff = (bp * 16 + b_row) * 64 + ((lc ^ bxor8) << 3);
                uint32_t rh[4], rl[4];
                ldm4(rh, uKh + 2 * roff);
                ldm4(rl, uKl + 2 * roff);
                mma_bf16(sv[2 * bp],     qfh[t], rh);
                mma_bf16(sv[2 * bp + 1], qfh[t], rh + 2);
                mma_bf16(sv[2 * bp],     qfl[t], rh);
                mma_bf16(sv[2 * bp + 1], qfl[t], rh + 2);
                mma_bf16(sv[2 * bp],     qfh[t], rl);
                mma_bf16(sv[2 * bp + 1], qfh[t], rl + 2);
            }
        }

#pragma unroll
        for (int i = 0; i < 2; i++) {
            float mx = -1e30f;
#pragma unroll
            for (int j = 0; j < 8; j++)
                mx = fmaxf(mx, fmaxf(sv[j][2 * i], sv[j][2 * i + 1]));
            mx = fmaxf(mx, __shfl_xor_sync(0xffffffffu, mx, 1));
            mx = fmaxf(mx, __shfl_xor_sync(0xffffffffu, mx, 2));
            const float mnew = fmaxf(mrun[i], mx);
            const float corr = __expf(mrun[i] - mnew);
            float rs = 0.f;
#pragma unroll
            for (int j = 0; j < 8; j++) {
                const float p0 = __expf(sv[j][2 * i] - mnew);
                const float p1 = __expf(sv[j][2 * i + 1] - mnew);
                sv[j][2 * i] = p0; sv[j][2 * i + 1] = p1;
                rs += p0 + p1;
            }
            rs += __shfl_xor_sync(0xffffffffu, rs, 1);
            rs += __shfl_xor_sync(0xffffffffu, rs, 2);
            lrun[i] = lrun[i] * corr + rs;
#pragma unroll
            for (int j = 0; j < 8; j++) {
                acc[j][2 * i] *= corr;
                acc[j][2 * i + 1] *= corr;
            }
            mrun[i] = mnew;
        }

        uint32_t pfh[4][4], pfl[4][4];
#pragma unroll
        for (int t = 0; t < 4; t++) {
#pragma unroll
            for (int q = 0; q < 4; q++) {
                const int j = 2 * t + (q >> 1);
                const float p0 = sv[j][(q & 1) * 2];
                const float p1 = sv[j][(q & 1) * 2 + 1];
                const __nv_bfloat16 h0 = __float2bfloat16(p0);
                const __nv_bfloat16 h1 = __float2bfloat16(p1);
                pfh[t][q] = ((uint32_t)__bfloat16_as_ushort(h1) << 16) |
                            __bfloat16_as_ushort(h0);
                pfl[t][q] = pack2_bf16(p0 - __bfloat162float(h0),
                                       p1 - __bfloat162float(h1));
            }
        }

#pragma unroll
        for (int t = 0; t < 4; t++) {
            const int lc = ((t * 16 + b_col) >> 3);
#pragma unroll
            for (int bp = 0; bp < 4; bp++) {
                const int roff = (bp * 16 + b_row) * 64 + ((lc ^ bxor8) << 3);
                uint32_t rh[4], rl[4];
                ldm4(rh, uVh + 2 * roff);
                ldm4(rl, uVl + 2 * roff);
                mma_bf16(acc[2 * bp],     pfh[t], rh);
                mma_bf16(acc[2 * bp + 1], pfh[t], rh + 2);
                mma_bf16(acc[2 * bp],     pfl[t], rh);
                mma_bf16(acc[2 * bp + 1], pfl[t], rh + 2);
                mma_bf16(acc[2 * bp],     pfh[t], rl);
                mma_bf16(acc[2 * bp + 1], pfh[t], rl + 2);
            }
        }
    }

    const float il0 = 1.f / lrun[0];
    const float il1 = 1.f / lrun[1];
    const int r0 = q0 + wrow + (l >> 2);
    const int cb = h * 64 + (l & 3) * 2;
#pragma unroll
    for (int j = 0; j < 8; j++) {
        const float a0 = acc[j][0] * il0, a1 = acc[j][1] * il0;
        const float a2 = acc[j][2] * il1, a3 = acc[j][3] * il1;
        const __nv_bfloat16 h0 = __float2bfloat16(a0);
        const __nv_bfloat16 h1 = __float2bfloat16(a1);
        const __nv_bfloat16 h2 = __float2bfloat16(a2);
        const __nv_bfloat16 h3 = __float2bfloat16(a3);
        const size_t o0 = (size_t)(b * N_ + r0) * C_ + cb + j * 8;
        const size_t o1 = (size_t)(b * N_ + r0 + 8) * C_ + cb + j * 8;
        *(uint32_t*)&oh[o0] =
            ((uint32_t)__bfloat16_as_ushort(h1) << 16) | __bfloat16_as_ushort(h0);
        *(uint32_t*)&oh[o1] =
            ((uint32_t)__bfloat16_as_ushort(h3) << 16) | __bfloat16_as_ushort(h2);
        *(uint32_t*)&ol[o0] = pack2_bf16(a0 - __bfloat162float(h0),
                                         a1 - __bfloat162float(h1));
        *(uint32_t*)&ol[o1] = pack2_bf16(a2 - __bfloat162float(h2),
                                         a3 - __bfloat162float(h3));
    }
}

// ---------------------------------------------------------------------------
extern "C" void kernel_launch(void* const* d_in, const int* in_sizes, int n_in,
                              void* d_out, int out_size)
{
    const float* x     = (const float*)d_in[0];
    const float* Wqkv  = (const float*)d_in[1];
    const float* bqkv  = (const float*)d_in[2];
    const float* Wproj = (const float*)d_in[3];
    const float* bproj = (const float*)d_in[4];
    float*       out   = (float*)d_out;

    __nv_bfloat16 *wqh, *wql, *wph, *wpl, *ah, *al;
    __nv_bfloat16 *aQh, *aQl, *aKh, *aKl, *aVh, *aVl;
    cudaGetSymbolAddress((void**)&wqh, g_wqkv_hi);
    cudaGetSymbolAddress((void**)&wql, g_wqkv_lo);
    cudaGetSymbolAddress((void**)&wph, g_wproj_hi);
    cudaGetSymbolAddress((void**)&wpl, g_wproj_lo);
    cudaGetSymbolAddress((void**)&ah,  g_ah);
    cudaGetSymbolAddress((void**)&al,  g_al);
    cudaGetSymbolAddress((void**)&aQh, g_Qh);
    cudaGetSymbolAddress((void**)&aQl, g_Ql);
    cudaGetSymbolAddress((void**)&aKh, g_Kh);
    cudaGetSymbolAddress((void**)&aKl, g_Kl);
    cudaGetSymbolAddress((void**)&aVh, g_Vh);
    cudaGetSymbolAddress((void**)&aVl, g_Vl);

    static bool attr_set = false;
    if (!attr_set) {
        cudaFuncSetAttribute(attn_mma_kernel,
                             cudaFuncAttributeMaxDynamicSharedMemorySize, ATT_SMEM);
        cudaFuncSetAttribute(gemm_mma_kernel<0>,
                             cudaFuncAttributeMaxDynamicSharedMemorySize, GEMM_SMEM);
        cudaFuncSetAttribute(gemm_mma_kernel<1>,
                             cudaFuncAttributeMaxDynamicSharedMemorySize, GEMM_SMEM);
        attr_set = true;
    }

    const int a_total4 = M_TOT * K_DIM / 4;

    // 0) RoPE table + weight splits + x split
    rope_init_kernel<<<1, 512>>>();
    split_w_kernel<<<dim3(QKV_N / 32, K_DIM / 32), dim3(32, 8)>>>(Wqkv, wqh, wql, K_DIM, QKV_N);
    split_w_kernel<<<dim3(C_ / 32, K_DIM / 32), dim3(32, 8)>>>(Wproj, wph, wpl, K_DIM, C_);
    split_a_kernel<<<(a_total4 + 255) / 256, 256>>>(x, ah, al, a_total4);

    // 1) QKV projection + fused RoPE/Q/K/V split epilogues
    gemm_mma_kernel<1><<<dim3(QKV_N / 128, M_TOT / 128), 256, GEMM_SMEM>>>(
        ah, al, wqh, wql, bqkv, nullptr, aQh, aQl, aKh, aKl, aVh, aVl,
        M_TOT, QKV_N, K_DIM);

    // 2) Flash attention (writes split proj input into g_ah/g_al)
    attn_mma_kernel<<<dim3(N_ / 128, H_, B_), 256, ATT_SMEM>>>(
        aQh, aQl, aKh, aKl, aVh, aVl, ah, al);

    // 3) Output projection
    gemm_mma_kernel<0><<<dim3(C_ / 128, M_TOT / 128), 256, GEMM_SMEM>>>(
        ah, al, wph, wpl, bproj, out, nullptr, nullptr, nullptr, nullptr,
        nullptr, nullptr, M_TOT, C_, K_DIM);
}